// round 13
// speedup vs baseline: 3.1291x; 1.0419x over previous
#include <cuda_runtime.h>
#include <cuda_bf16.h>
#include <cuda_fp16.h>
#include <cstdint>
#include <climits>

// ---------------- problem constants ----------------
constexpr int NQ = 40000;        // 200*200
constexpr int ED = 128;
constexpr int NV = 43520;        // sum of level sizes
constexpr int HEADS = 8;
constexpr int NPART = 320;       // bn partial blocks

// ---------------- scratch layout (floats) ----------------
constexpr size_t OFF_Q    = 0;
constexpr size_t SZ_Q     = (size_t)NQ * ED;
constexpr size_t OFF_T1   = OFF_Q + SZ_Q;
constexpr size_t OFF_T2   = OFF_T1 + SZ_Q;
constexpr size_t OFF_H1   = OFF_T2 + SZ_Q;
constexpr size_t SZ_H1    = (size_t)NQ * 128;
constexpr size_t OFF_H2   = OFF_H1 + SZ_H1;
constexpr size_t SZ_H2    = (size_t)NQ * 64;
constexpr size_t OFF_H3   = OFF_H2 + SZ_H2;
constexpr size_t SZ_H3    = (size_t)NQ * 48;
constexpr size_t OFF_H4   = OFF_H3 + SZ_H3;
constexpr size_t OFF_PART = OFF_H4 + SZ_H3;
constexpr size_t SZ_PART  = (size_t)NPART * 2 * 128;
constexpr size_t OFF_SCALE= OFF_PART + SZ_PART;
constexpr size_t OFF_SHIFT= OFF_SCALE + 128;
constexpr size_t OFF_BIAS = OFF_SHIFT + 128;       // 2 layers x 768 packed bias
constexpr size_t SCRATCH_TOTAL = OFF_BIAS + 2 * 768;

__device__ float g_scratch[SCRATCH_TOTAL];
__device__ int   g_maxv;

// ---------------- bf16 / fp16 buffers ----------------
constexpr int W1CHUNKS = 98;                 // conv1: 49 taps * 2 ci-halves
__device__ __align__(16) __nv_bfloat16 g_s1h[(size_t)NQ * 128];
__device__ __align__(16) __nv_bfloat16 g_s1l[(size_t)NQ * 128];
__device__ __align__(16) __nv_bfloat16 g_s2h[(size_t)NQ * 128];
__device__ __align__(16) __nv_bfloat16 g_s2l[(size_t)NQ * 128];
__device__ __align__(16) __half        g_vx[(size_t)NV * 128];    // fp16 V for deform
__device__ __align__(16) __half        g_vin16[(size_t)NV * 128]; // fp16 value input
__device__ __align__(16) __half        g_q16[(size_t)NQ * 128];   // fp16 scratch
__device__ __align__(16) __half        g_qp16[(size_t)NQ * 128];  // fp16 scratch
__device__ __align__(16) __half        g_oa16[(size_t)NQ * 768];  // fp16 offsets+logits
// Wout (bf16x3) per layer 128 x 128
__device__ __align__(16) __nv_bfloat16 g_wph[(size_t)2 * 128 * 128];
__device__ __align__(16) __nv_bfloat16 g_wpl[(size_t)2 * 128 * 128];
// fp16 weights per layer: [OA 768][Wv 128][Wf1 128][Wf2 128] x 128 k
__device__ __align__(16) __half g_wf16[(size_t)2 * 1152 * 128];
// conv1 weights [chunk][co 128][k 64] fp16
__device__ __align__(16) __half g_w16[(size_t)W1CHUNKS * 128 * 64];
// convs 2-4 bf16 split weights
constexpr int WC2_OFF = 0, WC3_OFF = 73728, WC4_OFF = 110592, WC_TOTAL = 147456;
__device__ __align__(16) __nv_bfloat16 g_wch[WC_TOTAL];
__device__ __align__(16) __nv_bfloat16 g_wcl[WC_TOTAL];

// ---------------- small helpers ----------------
__device__ __forceinline__ uint32_t smem_u32(const void* p) {
    return (uint32_t)__cvta_generic_to_shared(p);
}
__device__ __forceinline__ void cpasync16(uint32_t dst, const void* src, bool valid) {
    asm volatile("cp.async.cg.shared.global [%0], [%1], 16, %2;"
                 :: "r"(dst), "l"(src), "r"(valid ? 16u : 0u));
}
__device__ __forceinline__ void cp_commit() { asm volatile("cp.async.commit_group;"); }
__device__ __forceinline__ void cp_wait1()  { asm volatile("cp.async.wait_group 1;"); }
__device__ __forceinline__ void cp_wait0()  { asm volatile("cp.async.wait_group 0;"); }

__device__ __forceinline__ void ldmx4(uint32_t* r, uint32_t addr) {
    asm volatile("ldmatrix.sync.aligned.m8n8.x4.shared.b16 {%0,%1,%2,%3}, [%4];"
                 : "=r"(r[0]), "=r"(r[1]), "=r"(r[2]), "=r"(r[3]) : "r"(addr));
}
__device__ __forceinline__ void ldmx2(uint32_t* r, uint32_t addr) {
    asm volatile("ldmatrix.sync.aligned.m8n8.x2.shared.b16 {%0,%1}, [%2];"
                 : "=r"(r[0]), "=r"(r[1]) : "r"(addr));
}
__device__ __forceinline__ void mma_bf16(float* c, const uint32_t* a, const uint32_t* b) {
    asm volatile("mma.sync.aligned.m16n8k16.row.col.f32.bf16.bf16.f32 "
                 "{%0,%1,%2,%3}, {%4,%5,%6,%7}, {%8,%9}, {%0,%1,%2,%3};"
                 : "+f"(c[0]), "+f"(c[1]), "+f"(c[2]), "+f"(c[3])
                 : "r"(a[0]), "r"(a[1]), "r"(a[2]), "r"(a[3]), "r"(b[0]), "r"(b[1]));
}
__device__ __forceinline__ void mma_f16(float* c, const uint32_t* a, const uint32_t* b) {
    asm volatile("mma.sync.aligned.m16n8k16.row.col.f32.f16.f16.f32 "
                 "{%0,%1,%2,%3}, {%4,%5,%6,%7}, {%8,%9}, {%0,%1,%2,%3};"
                 : "+f"(c[0]), "+f"(c[1]), "+f"(c[2]), "+f"(c[3])
                 : "r"(a[0]), "r"(a[1]), "r"(a[2]), "r"(a[3]), "r"(b[0]), "r"(b[1]));
}
__device__ __forceinline__ void split2(float v, __nv_bfloat16& h, __nv_bfloat16& l) {
    h = __float2bfloat16(v);
    l = __float2bfloat16(v - __bfloat162float(h));
}

// ---------------- elementwise helpers ----------------
__global__ void init_max_kernel(int* gm) { *gm = INT_MIN; }

__global__ void reduce_max_kernel(const int* __restrict__ p, int* gm) {
    int v = INT_MIN;
    for (int k = blockIdx.x * blockDim.x + threadIdx.x; k < NQ; k += gridDim.x * blockDim.x)
        v = max(v, p[k]);
    #pragma unroll
    for (int o = 16; o > 0; o >>= 1) v = max(v, __shfl_xor_sync(0xffffffffu, v, o));
    __shared__ int sm[8];
    int w = threadIdx.x >> 5;
    if ((threadIdx.x & 31) == 0) sm[w] = v;
    __syncthreads();
    if (threadIdx.x == 0) {
        int bv = sm[0];
        for (int i = 1; i < (int)(blockDim.x >> 5); i++) bv = max(bv, sm[i]);
        atomicMax(gm, bv);
    }
}

__global__ void write_mask_kernel(const int* __restrict__ p, const int* __restrict__ gm,
                                  float* __restrict__ out) {
    int i = blockIdx.x * blockDim.x + threadIdx.x;
    if (i < NQ) out[i] = (p[i] < *gm) ? 1.0f : 0.0f;
}

// q+pos -> fp16
__global__ void add_f16_kernel(const float* __restrict__ A, const float* __restrict__ B,
                               __half* __restrict__ o, int n)
{
    int i = blockIdx.x * blockDim.x + threadIdx.x;
    if (i < n) o[i] = __float2half_rn(A[i] + B[i]);
}

// ---------------- fused weight prep + value fp16: one launch ----------------
constexpr int Q0 = 802816;            // conv1 fp16 [chunk][co][k]
constexpr int Q1 = Q0 + 73728;        // conv2 bf16 split
constexpr int Q2 = Q1 + 36864;        // conv3 bf16 split
constexpr int Q3 = Q2 + 36864;        // conv4 bf16 split
constexpr int Q4 = Q3 + 2 * 98304;    // OA fp16 (Woff|Wattn), both layers
constexpr int Q5 = Q4 + 2 * 16384;    // Wv fp16
constexpr int Q6 = Q5 + 2 * 16384;    // Wf1 fp16
constexpr int Q7 = Q6 + 2 * 16384;    // Wf2 fp16
constexpr int Q8 = Q7 + 2 * 16384;    // Wout bf16 split
constexpr int Q9 = Q8 + 2 * 768;      // bias pack
constexpr int Q10 = Q9 + NV * 128;    // value -> fp16

__global__ void prep_kernel(
    const float* __restrict__ cw1, const float* __restrict__ cw2,
    const float* __restrict__ cw3, const float* __restrict__ cw4,
    const float* __restrict__ Woff, const float* __restrict__ Wattn,
    const float* __restrict__ Wv, const float* __restrict__ Wf1,
    const float* __restrict__ Wf2, const float* __restrict__ Wout,
    const float* __restrict__ boff, const float* __restrict__ battn,
    const float* __restrict__ value,
    __half* __restrict__ w16, __nv_bfloat16* __restrict__ wch, __nv_bfloat16* __restrict__ wcl,
    __half* __restrict__ wf16,
    __nv_bfloat16* __restrict__ wph, __nv_bfloat16* __restrict__ wpl,
    float* __restrict__ bias_out, __half* __restrict__ vin16)
{
    int i = blockIdx.x * blockDim.x + threadIdx.x;
    if (i >= Q10) return;
    if (i < Q0) {
        int k = i & 63, co = (i >> 6) & 127, c = i >> 13;
        int e = c >> 1, ci = ((c & 1) << 6) + k;
        w16[i] = __float2half_rn(cw1[(((size_t)co * 128 + ci) * 7 + e / 7) * 7 + e % 7]);
    } else if (i < Q3) {
        const float* W; int CO, CI, CIN_CH, base, j;
        if (i < Q1)      { j = i - Q0; W = cw2; CO = 64; CI = 128; CIN_CH = 2; base = WC2_OFF; }
        else if (i < Q2) { j = i - Q1; W = cw3; CO = 48; CI = 64;  CIN_CH = 1; base = WC3_OFF; }
        else             { j = i - Q2; W = cw4; CO = 48; CI = 48;  CIN_CH = 1; base = WC4_OFF; }
        int k = j & 63, co = (j >> 6) & 63, c = j >> 12;
        int e = c / CIN_CH, ci = (c % CIN_CH) * 64 + k;
        float v = (co < CO && ci < CI) ? W[(((size_t)co * CI + ci) * 3 + e / 3) * 3 + e % 3] : 0.f;
        split2(v, wch[base + j], wcl[base + j]);
    } else if (i < Q4) {
        int j = i - Q3, l = j / 98304, r = j % 98304;
        int n = r >> 7, k = r & 127;
        float v = (n < 512) ? Woff[((size_t)l * 128 + k) * 512 + n]
                            : Wattn[((size_t)l * 128 + k) * 256 + (n - 512)];
        wf16[(size_t)l * 147456 + r] = __float2half_rn(v);
    } else if (i < Q7) {
        const float* W; int off, j;
        if (i < Q5)      { j = i - Q4; W = Wv;  off = 768 * 128; }
        else if (i < Q6) { j = i - Q5; W = Wf1; off = 896 * 128; }
        else             { j = i - Q6; W = Wf2; off = 1024 * 128; }
        int l = j >> 14, r = j & 16383;
        int n = r >> 7, k = r & 127;
        wf16[(size_t)l * 147456 + off + r] = __float2half_rn(W[((size_t)l * 128 + k) * 128 + n]);
    } else if (i < Q8) {
        int j = i - Q7, l = j >> 14, r = j & 16383;
        int n = r >> 7, k = r & 127;
        split2(Wout[((size_t)l * 128 + k) * 128 + n], wph[(size_t)l * 16384 + r], wpl[(size_t)l * 16384 + r]);
    } else if (i < Q9) {
        int j = i - Q8, l = j / 768, n = j % 768;
        bias_out[(size_t)l * 768 + n] = (n < 512) ? boff[(size_t)l * 512 + n] : battn[(size_t)l * 256 + n - 512];
    } else {
        int j = i - Q9;
        vin16[j] = __float2half_rn(value[j]);
    }
}

// ---------------- bf16x3 GEMM (Wout only): residual + fp32 out ----------------
constexpr int GROWB = 272;
constexpr int GTILE = 128 * GROWB;
constexpr int GEMM_SMEM = 4 * GTILE;

__global__ void __launch_bounds__(256, 1) gemm_mma6(
    const __nv_bfloat16* __restrict__ Ah, const __nv_bfloat16* __restrict__ Al,
    const __nv_bfloat16* __restrict__ Bh, const __nv_bfloat16* __restrict__ Bl,
    const float* __restrict__ bias, const float* __restrict__ R,
    float* __restrict__ Cf, int M, int N)
{
    extern __shared__ char smem[];
    const int tid = threadIdx.x;
    const int wid = tid >> 5, lane = tid & 31;
    const int warp_m = wid >> 2, warp_n = wid & 3;
    const uint32_t sb = smem_u32(smem);
    const int bm = blockIdx.x * 128, bn = blockIdx.y * 128;

    {
        const int lrow = tid >> 1, lhalf = tid & 1;
        const bool aval = (bm + lrow) < M;
        const uint32_t sa = sb + (uint32_t)lrow * GROWB + (uint32_t)lhalf * 128;
        const char* agh = (const char*)(Ah + (size_t)(aval ? (bm + lrow) : 0) * 128 + lhalf * 64);
        const char* agl = (const char*)(Al + (size_t)(aval ? (bm + lrow) : 0) * 128 + lhalf * 64);
        const char* bgh = (const char*)(Bh + (size_t)(bn + lrow) * 128 + lhalf * 64);
        const char* bgl = (const char*)(Bl + (size_t)(bn + lrow) * 128 + lhalf * 64);
        #pragma unroll
        for (int i = 0; i < 8; i++) {
            cpasync16(sa + i * 16,             agh + i * 16, aval);
            cpasync16(sa + GTILE + i * 16,     agl + i * 16, aval);
            cpasync16(sa + 2 * GTILE + i * 16, bgh + i * 16, true);
            cpasync16(sa + 3 * GTILE + i * 16, bgl + i * 16, true);
        }
        cp_commit();
        cp_wait0();
        __syncthreads();
    }

    float acc[4][4][4];
    #pragma unroll
    for (int mt = 0; mt < 4; mt++)
        #pragma unroll
        for (int nt = 0; nt < 4; nt++)
            #pragma unroll
            for (int d = 0; d < 4; d++) acc[mt][nt][d] = 0.f;

    const uint32_t a_base = sb + (uint32_t)(warp_m * 64 + (lane & 15)) * GROWB + (uint32_t)(lane >> 4) * 16;
    const uint32_t b_base = sb + 2 * GTILE + (uint32_t)(warp_n * 32 + (lane & 7)) * GROWB
                          + (uint32_t)((lane >> 3) & 1) * 16;

    #pragma unroll
    for (int ks = 0; ks < 8; ks++) {
        const uint32_t kbyte = (uint32_t)ks * 32;
        uint32_t bh[4][2], bl[4][2];
        #pragma unroll
        for (int nt = 0; nt < 4; nt++) {
            ldmx2(bh[nt], b_base + (uint32_t)nt * 8 * GROWB + kbyte);
            ldmx2(bl[nt], b_base + GTILE + (uint32_t)nt * 8 * GROWB + kbyte);
        }
        #pragma unroll
        for (int mt = 0; mt < 4; mt++) {
            uint32_t ah[4], al[4];
            ldmx4(ah, a_base + (uint32_t)mt * 16 * GROWB + kbyte);
            ldmx4(al, a_base + GTILE + (uint32_t)mt * 16 * GROWB + kbyte);
            #pragma unroll
            for (int nt = 0; nt < 4; nt++) {
                mma_bf16(acc[mt][nt], ah, bh[nt]);
                mma_bf16(acc[mt][nt], ah, bl[nt]);
                mma_bf16(acc[mt][nt], al, bh[nt]);
            }
        }
    }

    const int g = lane >> 2, tg = lane & 3;
    #pragma unroll
    for (int mt = 0; mt < 4; mt++) {
        const int r0 = bm + warp_m * 64 + mt * 16 + g;
        #pragma unroll
        for (int nt = 0; nt < 4; nt++) {
            const int col = bn + warp_n * 32 + nt * 8 + tg * 2;
            float2 bb = *(const float2*)&bias[col];
            #pragma unroll
            for (int half = 0; half < 2; half++) {
                const int r = r0 + half * 8;
                if (r >= M) continue;
                float2 rr = *(const float2*)&R[(size_t)r * N + col];
                *(float2*)&Cf[(size_t)r * N + col] =
                    make_float2(acc[mt][nt][half * 2] + bb.x + rr.x,
                                acc[mt][nt][half * 2 + 1] + bb.y + rr.y);
            }
        }
    }
}

// ---------------- fp16 single GEMM ----------------
// FLAGS: 1 relu, 2 residual (fp32 R), 4 fp32 out, 8 fp16 out
constexpr int F16GEMM_SMEM = 2 * GTILE;

template<int FLAGS>
__global__ void __launch_bounds__(256, 2) gemm_f16(
    const __half* __restrict__ A, const __half* __restrict__ B,
    const float* __restrict__ bias, const float* __restrict__ R,
    float* __restrict__ Cf, __half* __restrict__ Cx, int M, int N)
{
    extern __shared__ char smem[];
    const int tid = threadIdx.x;
    const int wid = tid >> 5, lane = tid & 31;
    const int warp_m = wid >> 2, warp_n = wid & 3;
    const uint32_t sb = smem_u32(smem);
    const int bm = blockIdx.x * 128, bn = blockIdx.y * 128;

    {
        const int lrow = tid >> 1, lhalf = tid & 1;
        const bool aval = (bm + lrow) < M;
        const uint32_t sa = sb + (uint32_t)lrow * GROWB + (uint32_t)lhalf * 128;
        const char* ag = (const char*)(A + (size_t)(aval ? (bm + lrow) : 0) * 128 + lhalf * 64);
        const char* bg = (const char*)(B + (size_t)(bn + lrow) * 128 + lhalf * 64);
        #pragma unroll
        for (int i = 0; i < 8; i++) {
            cpasync16(sa + i * 16,         ag + i * 16, aval);
            cpasync16(sa + GTILE + i * 16, bg + i * 16, true);
        }
        cp_commit();
        cp_wait0();
        __syncthreads();
    }

    float acc[4][4][4];
    #pragma unroll
    for (int mt = 0; mt < 4; mt++)
        #pragma unroll
        for (int nt = 0; nt < 4; nt++)
            #pragma unroll
            for (int d = 0; d < 4; d++) acc[mt][nt][d] = 0.f;

    const uint32_t a_base = sb + (uint32_t)(warp_m * 64 + (lane & 15)) * GROWB + (uint32_t)(lane >> 4) * 16;
    const uint32_t b_base = sb + GTILE + (uint32_t)(warp_n * 32 + (lane & 7)) * GROWB
                          + (uint32_t)((lane >> 3) & 1) * 16;

    #pragma unroll
    for (int ks = 0; ks < 8; ks++) {
        const uint32_t kbyte = (uint32_t)ks * 32;
        uint32_t bfr[4][2];
        #pragma unroll
        for (int nt = 0; nt < 4; nt++)
            ldmx2(bfr[nt], b_base + (uint32_t)nt * 8 * GROWB + kbyte);
        #pragma unroll
        for (int mt = 0; mt < 4; mt++) {
            uint32_t afr[4];
            ldmx4(afr, a_base + (uint32_t)mt * 16 * GROWB + kbyte);
            #pragma unroll
            for (int nt = 0; nt < 4; nt++)
                mma_f16(acc[mt][nt], afr, bfr[nt]);
        }
    }

    const int g = lane >> 2, tg = lane & 3;
    #pragma unroll
    for (int mt = 0; mt < 4; mt++) {
        const int r0 = bm + warp_m * 64 + mt * 16 + g;
        #pragma unroll
        for (int nt = 0; nt < 4; nt++) {
            const int col = bn + warp_n * 32 + nt * 8 + tg * 2;
            float2 bb = *(const float2*)&bias[col];
            #pragma unroll
            for (int half = 0; half < 2; half++) {
                const int r = r0 + half * 8;
                if (r >= M) continue;
                float a0 = acc[mt][nt][half * 2] + bb.x;
                float a1 = acc[mt][nt][half * 2 + 1] + bb.y;
                if (FLAGS & 2) {
                    float2 rr = *(const float2*)&R[(size_t)r * N + col];
                    a0 += rr.x; a1 += rr.y;
                }
                if (FLAGS & 1) { a0 = fmaxf(a0, 0.f); a1 = fmaxf(a1, 0.f); }
                if (FLAGS & 4)
                    *(float2*)&Cf[(size_t)r * N + col] = make_float2(a0, a1);
                if (FLAGS & 8)
                    *(__half2*)&Cx[(size_t)r * N + col] = __floats2half2_rn(a0, a1);
            }
        }
    }
}

// ---------------- deformable attention sampling (fp16 V + fp16 OA, fused softmax) ----------------
__global__ void __launch_bounds__(256) deform_kernel(
    const __half* __restrict__ VX, const __half* __restrict__ OA,
    __nv_bfloat16* __restrict__ OH, __nv_bfloat16* __restrict__ OL)
{
    int t = blockIdx.x * 256 + threadIdx.x;
    if (t >= NQ * HEADS) return;
    const int n = t >> 3, h = t & 7;
    const float rx = ((float)(n % 200) + 0.5f) * (1.f / 200.f);
    const float ry = ((float)(n / 200) + 0.5f) * (1.f / 200.f);
    const __half* op = OA + (size_t)n * 768 + h * 64;
    const __half* ap = OA + (size_t)n * 768 + 512 + h * 32;

    float e[32];
    {
        const uint4* apv = (const uint4*)ap;
        #pragma unroll
        for (int q = 0; q < 4; q++) {
            uint4 u = apv[q];
            uint32_t wv[4] = {u.x, u.y, u.z, u.w};
            #pragma unroll
            for (int d = 0; d < 4; d++) {
                float2 f2 = __half22float2(*(const __half2*)&wv[d]);
                e[q * 8 + d * 2 + 0] = f2.x;
                e[q * 8 + d * 2 + 1] = f2.y;
            }
        }
        float m = -1e30f;
        #pragma unroll
        for (int k = 0; k < 32; k++) m = fmaxf(m, e[k]);
        float s = 0.f;
        #pragma unroll
        for (int k = 0; k < 32; k++) { e[k] = expf(e[k] - m); s += e[k]; }
        float inv = 1.f / s;
        #pragma unroll
        for (int k = 0; k < 32; k++) e[k] *= inv;
    }

    float acc[16];
    #pragma unroll
    for (int d = 0; d < 16; d++) acc[d] = 0.f;

    const int stc[4] = {0, 32768, 40960, 43008};
    const int Wc[4]  = {256, 128, 64, 32};
    const int Hc[4]  = {128, 64, 32, 16};

    #pragma unroll
    for (int l = 0; l < 4; l++) {
        const int W = Wc[l], H = Hc[l], st = stc[l];
        const float Wf = (float)W, Hf = (float)H;
        for (int p = 0; p < 8; p++) {
            float2 off2 = __half22float2(*(const __half2*)(op + (l * 8 + p) * 2));
            float aw = e[l * 8 + p];
            float x = (rx + off2.x / Wf) * Wf - 0.5f;
            float y = (ry + off2.y / Hf) * Hf - 0.5f;
            float xf = floorf(x), yf = floorf(y);
            int x0 = (int)xf, y0 = (int)yf;
            float fx = x - xf, fy = y - yf;
            float wx[2] = {1.f - fx, fx};
            float wy[2] = {1.f - fy, fy};
            #pragma unroll
            for (int c = 0; c < 4; c++) {
                int xi = x0 + (c & 1), yi = y0 + (c >> 1);
                float wgt = wx[c & 1] * wy[c >> 1];
                if (xi >= 0 && xi < W && yi >= 0 && yi < H && wgt != 0.f) {
                    const uint4* gp = (const uint4*)(VX + ((size_t)(st + yi * W + xi)) * 128 + h * 16);
                    uint4 u0 = gp[0];
                    uint4 u1 = gp[1];
                    uint32_t wv[8] = {u0.x, u0.y, u0.z, u0.w, u1.x, u1.y, u1.z, u1.w};
                    float cw = aw * wgt;
                    #pragma unroll
                    for (int d = 0; d < 8; d++) {
                        float2 g2 = __half22float2(*(const __half2*)&wv[d]);
                        acc[d * 2 + 0] += cw * g2.x;
                        acc[d * 2 + 1] += cw * g2.y;
                    }
                }
            }
        }
    }
    __nv_bfloat162* oh = (__nv_bfloat162*)(OH + (size_t)n * 128 + h * 16);
    __nv_bfloat162* ol = (__nv_bfloat162*)(OL + (size_t)n * 128 + h * 16);
    #pragma unroll
    for (int d = 0; d < 8; d++) {
        __nv_bfloat16 h0, l0, h1, l1;
        split2(acc[d * 2], h0, l0); split2(acc[d * 2 + 1], h1, l1);
        oh[d] = __nv_bfloat162(h0, h1);
        ol[d] = __nv_bfloat162(l0, l1);
    }
}

// ---------------- layernorm: warp-per-row, 8 rows per block ----------------
// MODE: 3 fp32 + fp16(y), 4 fp32 + fp16(y + pos)
template<int MODE>
__global__ void __launch_bounds__(256) ln_kernel(
    const float* __restrict__ X, const float* __restrict__ g,
    const float* __restrict__ b, float* __restrict__ Y,
    __half* __restrict__ Yx, const float* __restrict__ pos)
{
    const int wid = threadIdx.x >> 5, lane = threadIdx.x & 31;
    const int r = blockIdx.x * 8 + wid;
    if (r >= NQ) return;
    const size_t base = (size_t)r * 128 + lane * 4;
    float4 x4 = *(const float4*)&X[base];
    float s = x4.x + x4.y + x4.z + x4.w;
    #pragma unroll
    for (int o = 16; o > 0; o >>= 1) s += __shfl_xor_sync(0xffffffffu, s, o);
    float m = s * (1.f / 128.f);
    float d0 = x4.x - m, d1 = x4.y - m, d2 = x4.z - m, d3 = x4.w - m;
    float q = d0 * d0 + d1 * d1 + d2 * d2 + d3 * d3;
    #pragma unroll
    for (int o = 16; o > 0; o >>= 1) q += __shfl_xor_sync(0xffffffffu, q, o);
    float inv = rsqrtf(q * (1.f / 128.f) + 1e-5f);
    float4 g4 = *(const float4*)&g[lane * 4];
    float4 b4 = *(const float4*)&b[lane * 4];
    float y0 = d0 * inv * g4.x + b4.x;
    float y1 = d1 * inv * g4.y + b4.y;
    float y2 = d2 * inv * g4.z + b4.z;
    float y3 = d3 * inv * g4.w + b4.w;
    *(float4*)&Y[base] = make_float4(y0, y1, y2, y3);
    if (MODE == 4) {
        float4 p4 = *(const float4*)&pos[base];
        y0 += p4.x; y1 += p4.y; y2 += p4.z; y3 += p4.w;
    }
    __half2 h01 = __floats2half2_rn(y0, y1);
    __half2 h23 = __floats2half2_rn(y2, y3);
    *(uint2*)&Yx[base] = make_uint2(*(uint32_t*)&h01, *(uint32_t*)&h23);
}

// ---------------- conv1 (7x7, 128->128) via mma.sync fp16 single ----------------
constexpr int ROWB = 144;
constexpr int C1TILE = 128 * ROWB;
constexpr int C1BUF  = 2 * C1TILE;
constexpr int CONV1_SMEM = 2 * C1BUF;

__global__ void __launch_bounds__(256, 2) conv1_f16_kernel(
    const __half* __restrict__ q16, const __half* __restrict__ w16,
    float* __restrict__ Out)
{
    extern __shared__ char smem[];
    const int tid = threadIdx.x;
    const int wid = tid >> 5, lane = tid & 31;
    const int warp_m = wid >> 2, warp_n = wid & 3;
    const uint32_t sb = smem_u32(smem);
    const int bm = blockIdx.x * 128;

    const int lrow = tid >> 1, lhalf = tid & 1;
    const int pm = bm + lrow;
    const int py = pm / 200, px = pm % 200;
    const bool prow_ok = pm < NQ;
    const uint32_t s_arow = sb + (uint32_t)lrow * ROWB + (uint32_t)lhalf * 64;
    const uint32_t s_brow = s_arow + C1TILE;

    const uint32_t a_base = sb + (uint32_t)(warp_m * 64 + (lane & 15)) * ROWB + (uint32_t)(lane >> 4) * 16;
    const uint32_t b_base = sb + C1TILE + (uint32_t)(warp_n * 32 + (lane & 7)) * ROWB
                          + (uint32_t)((lane >> 3) & 1) * 16;

    float acc[4][4][4];
    #pragma unroll
    for (int mt = 0; mt < 4; mt++)
        #pragma unroll
        for (int nt = 0; nt < 4; nt++)
            #pragma unroll
            for (int d = 0; d < 4; d++) acc[mt][nt][d] = 0.f;

    auto load_chunk = [&](int c, int buf) {
        const int e = c >> 1, ch = c & 1;
        const int qy = py + e / 7 - 3;
        const int qx = px + e % 7 - 3;
        const bool val = prow_ok && qy >= 0 && qy < 200 && qx >= 0 && qx < 200;
        const size_t aoff = (size_t)(val ? (qy * 200 + qx) : 0) * 128 + (size_t)ch * 64 + (size_t)lhalf * 32;
        const char* ag = (const char*)(q16 + aoff);
        const size_t boff = ((size_t)c * 128 + lrow) * 64 + (size_t)lhalf * 32;
        const char* bg = (const char*)(w16 + boff);
        const uint32_t sa = s_arow + (uint32_t)buf * C1BUF;
        const uint32_t sbr = s_brow + (uint32_t)buf * C1BUF;
        #pragma unroll
        for (int i = 0; i < 4; i++) {
            cpasync16(sa + i * 16,  ag + i * 16, val);
            cpasync16(sbr + i * 16, bg + i * 16, true);
        }
    };

    load_chunk(0, 0); cp_commit();
    load_chunk(1, 1); cp_commit();

    for (int c = 0; c < W1CHUNKS; c++) {
        const int buf = c & 1;
        cp_wait1();
        __syncthreads();

        const uint32_t ab = a_base + (uint32_t)buf * C1BUF;
        const uint32_t bb = b_base + (uint32_t)buf * C1BUF;
        #pragma unroll
        for (int ks = 0; ks < 4; ks++) {
            const uint32_t kbyte = (uint32_t)ks * 32;
            uint32_t bfr[4][2];
            #pragma unroll
            for (int nt = 0; nt < 4; nt++)
                ldmx2(bfr[nt], bb + (uint32_t)nt * 8 * ROWB + kbyte);
            #pragma unroll
            for (int mt = 0; mt < 4; mt++) {
                uint32_t afr[4];
                ldmx4(afr, ab + (uint32_t)mt * 16 * ROWB + kbyte);
                #pragma unroll
                for (int nt = 0; nt < 4; nt++)
                    mma_f16(acc[mt][nt], afr, bfr[nt]);
            }
        }
        __syncthreads();
        if (c + 2 < W1CHUNKS) load_chunk(c + 2, buf);
        cp_commit();
    }

    const int g = lane >> 2, tg = lane & 3;
    #pragma unroll
    for (int mt = 0; mt < 4; mt++) {
        const int r0 = bm + warp_m * 64 + mt * 16 + g;
        #pragma unroll
        for (int nt = 0; nt < 4; nt++) {
            const int col = warp_n * 32 + nt * 8 + tg * 2;
            if (r0 < NQ)
                *(float2*)&Out[(size_t)r0 * 128 + col] = make_float2(acc[mt][nt][0], acc[mt][nt][1]);
            if (r0 + 8 < NQ)
                *(float2*)&Out[(size_t)(r0 + 8) * 128 + col] = make_float2(acc[mt][nt][2], acc[mt][nt][3]);
        }
    }
}

// ---------------- convs 2-4 (3x3) via mma.sync bf16x3, 128x64 tile ----------------
constexpr int CATILE = 128 * ROWB;
constexpr int CBTILE = 64 * ROWB;
constexpr int CBUF = 2 * CATILE + 2 * CBTILE;
constexpr int CONV_SMEM = 2 * CBUF;

template<int CHUNKS, int CIN_CH, int CST>
__global__ void __launch_bounds__(256, 2) conv_mma_kernel(
    const __nv_bfloat16* __restrict__ inh, const __nv_bfloat16* __restrict__ inl,
    const __nv_bfloat16* __restrict__ wh, const __nv_bfloat16* __restrict__ wl,
    float* __restrict__ Out, int COUT)
{
    extern __shared__ char smem[];
    const int tid = threadIdx.x;
    const int wid = tid >> 5, lane = tid & 31;
    const int warp_m = wid >> 1, warp_n = wid & 1;
    const uint32_t sb = smem_u32(smem);
    const int bm = blockIdx.x * 128;

    const int lrow = tid >> 1, lhalf = tid & 1;
    const int pm = bm + lrow;
    const int py = pm / 200, px = pm % 200;
    const bool prow_ok = pm < NQ;
    const uint32_t s_arow = sb + (uint32_t)lrow * ROWB + (uint32_t)lhalf * 64;
    const int brow = tid >> 2, bq = tid & 3;
    const uint32_t s_brow = sb + 2 * CATILE + (uint32_t)brow * ROWB + (uint32_t)bq * 32;

    const uint32_t a_base = sb + (uint32_t)(warp_m * 32 + (lane & 15)) * ROWB + (uint32_t)(lane >> 4) * 16;
    const uint32_t b_base = sb + 2 * CATILE + (uint32_t)(warp_n * 32 + (lane & 7)) * ROWB
                          + (uint32_t)((lane >> 3) & 1) * 16;

    float acc[2][4][4];
    #pragma unroll
    for (int mt = 0; mt < 2; mt++)
        #pragma unroll
        for (int nt = 0; nt < 4; nt++)
            #pragma unroll
            for (int d = 0; d < 4; d++) acc[mt][nt][d] = 0.f;

    auto load_chunk = [&](int c, int buf) {
        const int e = c / CIN_CH, cih = c % CIN_CH;
        const int qy = py + e / 3 - 1;
        const int qx = px + e % 3 - 1;
        const bool val = prow_ok && qy >= 0 && qy < 200 && qx >= 0 && qx < 200;
        const size_t aoff = (size_t)(val ? (qy * 200 + qx) : 0) * CST + (size_t)cih * 64 + (size_t)lhalf * 32;
        const char* agh = (const char*)(inh + aoff);
        const char* agl = (const char*)(inl + aoff);
        const size_t boff = ((size_t)c * 64 + brow) * 64 + (size_t)bq * 16;
        const char* bgh = (const char*)(wh + boff);
        const char* bgl = (const char*)(wl + boff);
        const uint32_t sa = s_arow + (uint32_t)buf * CBUF;
        const uint32_t sbr = s_brow + (uint32_t)buf * CBUF;
        #pragma unroll
        for (int i = 0; i < 4; i++) {
            cpasync16(sa + i * 16,           agh + i * 16, val);
            cpasync16(sa + CATILE + i * 16,  agl + i * 16, val);
        }
        #pragma unroll
        for (int i = 0; i < 2; i++) {
            cpasync16(sbr + i * 16,          bgh + i * 16, true);
            cpasync16(sbr + CBTILE + i * 16, bgl + i * 16, true);
        }
    };

    load_chunk(0, 0); cp_commit();
    load_chunk(1, 1); cp_commit();

    for (int c = 0; c < CHUNKS; c++) {
        const int buf = c & 1;
        cp_wait1();
        __syncthreads();

        const uint32_t ab = a_base + (uint32_t)buf * CBUF;
        const uint32_t bb = b_base + (uint32_t)buf * CBUF;
        #pragma unroll
        for (int ks = 0; ks < 4; ks++) {
            const uint32_t kbyte = (uint32_t)ks * 32;
            uint32_t bh[4][2], bl[4][2];
            #pragma unroll
            for (int nt = 0; nt < 4; nt++) {
                ldmx2(bh[nt], bb + (uint32_t)nt * 8 * ROWB + kbyte);
                ldmx2(bl[nt], bb + CBTILE + (uint32_t)nt * 8 * ROWB + kbyte);
            }
            #pragma unroll
            for (int mt = 0; mt < 2; mt++) {
                uint32_t ah[4], al[4];
                ldmx4(ah, ab + (uint32_t)mt * 16 * ROWB + kbyte);
                ldmx4(al, ab + CATILE + (uint32_t)mt * 16 * ROWB + kbyte);
                #pragma unroll
                for (int nt = 0; nt < 4; nt++) {
                    mma_bf16(acc[mt][nt], ah, bh[nt]);
                    mma_bf16(acc[mt][nt], ah, bl[nt]);
                    mma_bf16(acc[mt][nt], al, bh[nt]);
                }
            }
        }
        __syncthreads();
        if (c + 2 < CHUNKS) load_chunk(c + 2, buf);
        cp_commit();
    }

    const int g = lane >> 2, tg = lane & 3;
    #pragma unroll
    for (int mt = 0; mt < 2; mt++) {
        const int r0 = bm + warp_m * 32 + mt * 16 + g;
        #pragma unroll
        for (int nt = 0; nt < 4; nt++) {
            const int col = warp_n * 32 + nt * 8 + tg * 2;
            if (col >= COUT) continue;
            if (r0 < NQ)
                *(float2*)&Out[(size_t)r0 * COUT + col] = make_float2(acc[mt][nt][0], acc[mt][nt][1]);
            if (r0 + 8 < NQ)
                *(float2*)&Out[(size_t)(r0 + 8) * COUT + col] = make_float2(acc[mt][nt][2], acc[mt][nt][3]);
        }
    }
}

// ---------------- batchnorm (320-way parallel partials, deterministic) ----------------
__global__ void bn_stats_kernel(const float* __restrict__ X, float* __restrict__ part, int C)
{
    int c = threadIdx.x;
    int g = blockIdx.x;
    const int per = (NQ + NPART - 1) / NPART;
    int p0 = g * per;
    int p1 = min(NQ, p0 + per);
    float s = 0.f, q = 0.f;
    for (int p = p0; p < p1; p++) {
        float x = X[(size_t)p * C + c];
        s += x; q += x * x;
    }
    part[(size_t)g * 2 * C + c] = s;
    part[(size_t)g * 2 * C + C + c] = q;
}

__global__ void bn_finalize_kernel(const float* __restrict__ part,
                                   const float* __restrict__ gamma, const float* __restrict__ beta,
                                   float* __restrict__ scale, float* __restrict__ shift, int C)
{
    int c = threadIdx.x;
    float s = 0.f, q = 0.f;
    for (int g = 0; g < NPART; g++) {
        s += part[(size_t)g * 2 * C + c];
        q += part[(size_t)g * 2 * C + C + c];
    }
    const float invP = 1.f / (float)NQ;
    float m = s * invP;
    float v = q * invP - m * m;
    float sc = gamma[c] * rsqrtf(v + 1e-5f);
    scale[c] = sc;
    shift[c] = beta[c] - m * sc;
}

__global__ void bn_apply_split_kernel(const float* __restrict__ X, const float* __restrict__ scale,
                                      const float* __restrict__ shift,
                                      __nv_bfloat16* __restrict__ hi, __nv_bfloat16* __restrict__ lo,
                                      int C, int CST, int total)
{
    int i = blockIdx.x * blockDim.x + threadIdx.x;
    if (i >= total) return;
    int c = i % CST;
    int p = i / CST;
    float v = 0.f;
    if (c < C) v = fmaxf(0.f, fmaf(X[(size_t)p * C + c], scale[c], shift[c]));
    split2(v, hi[i], lo[i]);
}

// ---------------- head: fused BN4+ReLU + 1x1 conv 48 -> 21, output NCHW ----------------
__global__ void head_conv_kernel(const float* __restrict__ H4raw, const float* __restrict__ scale,
                                 const float* __restrict__ shift,
                                 const float* __restrict__ Wo, const float* __restrict__ bo,
                                 float* __restrict__ out)
{
    int p = blockIdx.x * blockDim.x + threadIdx.x;
    if (p >= NQ) return;
    float x[48];
    const float4* hp = (const float4*)(H4raw + (size_t)p * 48);
    #pragma unroll
    for (int i = 0; i < 12; i++) {
        float4 v = hp[i];
        x[i * 4 + 0] = v.x; x[i * 4 + 1] = v.y; x[i * 4 + 2] = v.z; x[i * 4 + 3] = v.w;
    }
    #pragma unroll
    for (int ci = 0; ci < 48; ci++)
        x[ci] = fmaxf(0.f, fmaf(x[ci], scale[ci], shift[ci]));
    for (int co = 0; co < 21; co++) {
        float s = bo[co];
        const float* w = Wo + co * 48;
        #pragma unroll
        for (int ci = 0; ci < 48; ci++) s = fmaf(x[ci], w[ci], s);
        out[(size_t)co * NQ + p] = s;
    }
}

// ---------------- launch ----------------
extern "C" void kernel_launch(void* const* d_in, const int* in_sizes, int n_in,
                              void* d_out, int out_size)
{
    const float* value = (const float*)d_in[0];
    const float* bq    = (const float*)d_in[1];
    const float* bpos  = (const float*)d_in[2];
    const int*   proj  = (const int*)d_in[3];
    const float* Wv    = (const float*)d_in[4];
    const float* bv    = (const float*)d_in[5];
    const float* Woff  = (const float*)d_in[6];
    const float* boff  = (const float*)d_in[7];
    const float* Wattn = (const float*)d_in[8];
    const float* battn = (const float*)d_in[9];
    const float* Wout  = (const float*)d_in[10];
    const float* bout  = (const float*)d_in[11];
    const float* Wf1   = (const float*)d_in[12];
    const float* bf1   = (const float*)d_in[13];
    const float* Wf2   = (const float*)d_in[14];
    const float* bf2   = (const float*)d_in[15];
    const float* lng   = (const float*)d_in[16];
    const float* lnb   = (const float*)d_in[17];
    const float* cw1   = (const float*)d_in[18];
    const float* g1    = (const float*)d_in[19];
    const float* b1    = (const float*)d_in[20];
    const float* cw2   = (const float*)d_in[21];
    const float* g2    = (const float*)d_in[22];
    const float* b2    = (const float*)d_in[23];
    const float* cw3   = (const float*)d_in[24];
    const float* g3    = (const float*)d_in[25];
    const float* b3    = (const float*)d_in[26];
    const float* cw4   = (const float*)d_in[27];
    const float* g4    = (const float*)d_in[28];
    const float* b4    = (const float*)d_in[29];
    const float* objw  = (const float*)d_in[30];
    const float* objb  = (const float*)d_in[31];
    float* out = (float*)d_out;

    float* S = nullptr;
    cudaGetSymbolAddress((void**)&S, g_scratch);
    int* gm = nullptr;
    cudaGetSymbolAddress((void**)&gm, g_maxv);
    __nv_bfloat16 *s1h, *s1l, *s2h, *s2l, *wph, *wpl, *wch, *wcl;
    __half *vx, *vin16, *q16, *qp16, *w16, *wf16, *oa16;
    cudaGetSymbolAddress((void**)&s1h, g_s1h);
    cudaGetSymbolAddress((void**)&s1l, g_s1l);
    cudaGetSymbolAddress((void**)&s2h, g_s2h);
    cudaGetSymbolAddress((void**)&s2l, g_s2l);
    cudaGetSymbolAddress((void**)&vx,  g_vx);
    cudaGetSymbolAddress((void**)&vin16, g_vin16);
    cudaGetSymbolAddress((void**)&q16, g_q16);
    cudaGetSymbolAddress((void**)&qp16, g_qp16);
    cudaGetSymbolAddress((void**)&w16, g_w16);
    cudaGetSymbolAddress((void**)&wf16, g_wf16);
    cudaGetSymbolAddress((void**)&oa16, g_oa16);
    cudaGetSymbolAddress((void**)&wph, g_wph);
    cudaGetSymbolAddress((void**)&wpl, g_wpl);
    cudaGetSymbolAddress((void**)&wch, g_wch);
    cudaGetSymbolAddress((void**)&wcl, g_wcl);

    float* PQ    = S + OFF_Q;
    float* PT1   = S + OFF_T1;
    float* PT2   = S + OFF_T2;
    float* PH1   = S + OFF_H1;
    float* PH2   = S + OFF_H2;
    float* PH3   = S + OFF_H3;
    float* PH4   = S + OFF_H4;
    float* PPART = S + OFF_PART;
    float* PSCALE= S + OFF_SCALE;
    float* PSHIFT= S + OFF_SHIFT;
    float* PBIAS = S + OFF_BIAS;

    cudaFuncSetAttribute(conv1_f16_kernel, cudaFuncAttributeMaxDynamicSharedMemorySize, CONV1_SMEM);
    cudaFuncSetAttribute(gemm_f16<8>,    cudaFuncAttributeMaxDynamicSharedMemorySize, F16GEMM_SMEM);
    cudaFuncSetAttribute(gemm_f16<9>,    cudaFuncAttributeMaxDynamicSharedMemorySize, F16GEMM_SMEM);
    cudaFuncSetAttribute(gemm_f16<6>,    cudaFuncAttributeMaxDynamicSharedMemorySize, F16GEMM_SMEM);
    cudaFuncSetAttribute(gemm_mma6,      cudaFuncAttributeMaxDynamicSharedMemorySize, GEMM_SMEM);
    cudaFuncSetAttribute((conv_mma_kernel<18, 2, 128>), cudaFuncAttributeMaxDynamicSharedMemorySize, CONV_SMEM);
    cudaFuncSetAttribute((conv_mma_kernel<9, 1, 64>),   cudaFuncAttributeMaxDynamicSharedMemorySize, CONV_SMEM);

    // --- observed_masks ---
    init_max_kernel<<<1, 1>>>(gm);
    reduce_max_kernel<<<40, 256>>>(proj, gm);
    write_mask_kernel<<<(NQ + 255) / 256, 256>>>(proj, gm, out + 21 * NQ);

    // --- fused weight prep + value fp16 (single launch) ---
    prep_kernel<<<(Q10 + 255) / 256, 256>>>(cw1, cw2, cw3, cw4, Woff, Wattn, Wv, Wf1, Wf2, Wout,
                                            boff, battn, value,
                                            w16, wch, wcl, wf16, wph, wpl, PBIAS, vin16);

    // --- q init ---
    cudaMemcpyAsync(PQ, bq, (size_t)NQ * ED * sizeof(float), cudaMemcpyDeviceToDevice);

    // --- 2 encoder layers ---
    add_f16_kernel<<<(NQ * ED + 255) / 256, 256>>>(PQ, bpos, qp16, NQ * ED);
    for (int i = 0; i < 2; i++) {
        size_t LW = (size_t)i * 1152 * 128;
        gemm_f16<8><<<dim3(340, 1), 256, F16GEMM_SMEM>>>(vin16, wf16 + LW + 768 * 128,
                                                         bv + i * 128, nullptr, nullptr, vx, NV, 128);
        gemm_f16<8><<<dim3(313, 6), 256, F16GEMM_SMEM>>>(qp16, wf16 + LW,
                                                         PBIAS + i * 768, nullptr, nullptr, oa16, NQ, 768);
        deform_kernel<<<(NQ * HEADS + 255) / 256, 256>>>(vx, oa16, s2h, s2l);
        gemm_mma6<<<dim3(313, 1), 256, GEMM_SMEM>>>(s2h, s2l, wph + (size_t)i * 128 * 128, wpl + (size_t)i * 128 * 128,
                                                    bout + i * 128, PQ, PT1, NQ, 128);
        ln_kernel<3><<<(NQ + 7) / 8, 256>>>(PT1, lng + (i * 2 + 0) * 128, lnb + (i * 2 + 0) * 128, PQ, q16, nullptr);
        gemm_f16<9><<<dim3(313, 1), 256, F16GEMM_SMEM>>>(q16, wf16 + LW + 896 * 128,
                                                         bf1 + i * 128, nullptr, nullptr, qp16, NQ, 128);
        gemm_f16<6><<<dim3(313, 1), 256, F16GEMM_SMEM>>>(qp16, wf16 + LW + 1024 * 128,
                                                         bf2 + i * 128, PQ, PT2, nullptr, NQ, 128);
        if (i == 0)
            ln_kernel<4><<<(NQ + 7) / 8, 256>>>(PT2, lng + 1 * 128, lnb + 1 * 128, PQ, qp16, bpos);   // fp16(q+pos)
        else
            ln_kernel<3><<<(NQ + 7) / 8, 256>>>(PT2, lng + 3 * 128, lnb + 3 * 128, PQ, q16, nullptr); // fp16(q)
    }

    // --- conv head ---
    conv1_f16_kernel<<<313, 256, CONV1_SMEM>>>(q16, w16, PH1);
    bn_stats_kernel<<<NPART, 128>>>(PH1, PPART, 128);
    bn_finalize_kernel<<<1, 128>>>(PPART, g1, b1, PSCALE, PSHIFT, 128);
    bn_apply_split_kernel<<<(NQ * 128 + 255) / 256, 256>>>(PH1, PSCALE, PSHIFT, s1h, s1l, 128, 128, NQ * 128);

    conv_mma_kernel<18, 2, 128><<<313, 256, CONV_SMEM>>>(s1h, s1l, wch + WC2_OFF, wcl + WC2_OFF, PH2, 64);
    bn_stats_kernel<<<NPART, 64>>>(PH2, PPART, 64);
    bn_finalize_kernel<<<1, 64>>>(PPART, g2, b2, PSCALE, PSHIFT, 64);
    bn_apply_split_kernel<<<(NQ * 64 + 255) / 256, 256>>>(PH2, PSCALE, PSHIFT, s2h, s2l, 64, 64, NQ * 64);

    conv_mma_kernel<9, 1, 64><<<313, 256, CONV_SMEM>>>(s2h, s2l, wch + WC3_OFF, wcl + WC3_OFF, PH3, 48);
    bn_stats_kernel<<<NPART, 48>>>(PH3, PPART, 48);
    bn_finalize_kernel<<<1, 48>>>(PPART, g3, b3, PSCALE, PSHIFT, 48);
    bn_apply_split_kernel<<<(NQ * 64 + 255) / 256, 256>>>(PH3, PSCALE, PSHIFT, s1h, s1l, 48, 64, NQ * 64);

    conv_mma_kernel<9, 1, 64><<<313, 256, CONV_SMEM>>>(s1h, s1l, wch + WC4_OFF, wcl + WC4_OFF, PH4, 48);
    bn_stats_kernel<<<NPART, 48>>>(PH4, PPART, 48);
    bn_finalize_kernel<<<1, 48>>>(PPART, g4, b4, PSCALE, PSHIFT, 48);
    head_conv_kernel<<<(NQ + 255) / 256, 256>>>(PH4, PSCALE, PSHIFT, objw, objb, out);
}

// round 14
// speedup vs baseline: 3.3232x; 1.0620x over previous
#include <cuda_runtime.h>
#include <cuda_bf16.h>
#include <cuda_fp16.h>
#include <cstdint>
#include <climits>

// ---------------- problem constants ----------------
constexpr int NQ = 40000;        // 200*200
constexpr int ED = 128;
constexpr int NV = 43520;        // sum of level sizes
constexpr int HEADS = 8;
constexpr int NBLK = 313;        // conv blocks = bn partials

// ---------------- scratch layout (floats) ----------------
constexpr size_t OFF_Q    = 0;
constexpr size_t SZ_Q     = (size_t)NQ * ED;
constexpr size_t OFF_T1   = OFF_Q + SZ_Q;
constexpr size_t OFF_T2   = OFF_T1 + SZ_Q;
constexpr size_t OFF_H1   = OFF_T2 + SZ_Q;
constexpr size_t SZ_H1    = (size_t)NQ * 128;
constexpr size_t OFF_H2   = OFF_H1 + SZ_H1;
constexpr size_t SZ_H2    = (size_t)NQ * 64;
constexpr size_t OFF_H3   = OFF_H2 + SZ_H2;
constexpr size_t SZ_H3    = (size_t)NQ * 48;
constexpr size_t OFF_H4   = OFF_H3 + SZ_H3;
constexpr size_t OFF_PART = OFF_H4 + SZ_H3;
constexpr size_t SZ_PART  = (size_t)NBLK * 2 * 128 + 256;
constexpr size_t OFF_SCALE= OFF_PART + SZ_PART;
constexpr size_t OFF_SHIFT= OFF_SCALE + 128;
constexpr size_t OFF_BIAS = OFF_SHIFT + 128;       // 2 layers x 768 packed bias
constexpr size_t SCRATCH_TOTAL = OFF_BIAS + 2 * 768;

__device__ float g_scratch[SCRATCH_TOTAL];
__device__ int   g_maxv;

// ---------------- bf16 / fp16 buffers ----------------
constexpr int W1CHUNKS = 98;                 // conv1: 49 taps * 2 ci-halves
__device__ __align__(16) __nv_bfloat16 g_s1h[(size_t)NQ * 128];
__device__ __align__(16) __nv_bfloat16 g_s1l[(size_t)NQ * 128];
__device__ __align__(16) __nv_bfloat16 g_s2h[(size_t)NQ * 128];
__device__ __align__(16) __nv_bfloat16 g_s2l[(size_t)NQ * 128];
__device__ __align__(16) __half        g_vx[(size_t)NV * 128];    // fp16 V for deform
__device__ __align__(16) __half        g_vin16[(size_t)NV * 128]; // fp16 value input
__device__ __align__(16) __half        g_q16[(size_t)NQ * 128];   // fp16 scratch
__device__ __align__(16) __half        g_qp16[(size_t)NQ * 128];  // fp16 scratch
__device__ __align__(16) __half        g_oa16[(size_t)NQ * 768];  // fp16 offsets+logits
// Wout (bf16x3) per layer 128 x 128
__device__ __align__(16) __nv_bfloat16 g_wph[(size_t)2 * 128 * 128];
__device__ __align__(16) __nv_bfloat16 g_wpl[(size_t)2 * 128 * 128];
// fp16 weights per layer: [OA 768][Wv 128][Wf1 128][Wf2 128] x 128 k
__device__ __align__(16) __half g_wf16[(size_t)2 * 1152 * 128];
// conv1 weights [chunk][co 128][k 64] fp16
__device__ __align__(16) __half g_w16[(size_t)W1CHUNKS * 128 * 64];
// convs 2-4 bf16 split weights
constexpr int WC2_OFF = 0, WC3_OFF = 73728, WC4_OFF = 110592, WC_TOTAL = 147456;
__device__ __align__(16) __nv_bfloat16 g_wch[WC_TOTAL];
__device__ __align__(16) __nv_bfloat16 g_wcl[WC_TOTAL];

// ---------------- small helpers ----------------
__device__ __forceinline__ uint32_t smem_u32(const void* p) {
    return (uint32_t)__cvta_generic_to_shared(p);
}
__device__ __forceinline__ void cpasync16(uint32_t dst, const void* src, bool valid) {
    asm volatile("cp.async.cg.shared.global [%0], [%1], 16, %2;"
                 :: "r"(dst), "l"(src), "r"(valid ? 16u : 0u));
}
__device__ __forceinline__ void cp_commit() { asm volatile("cp.async.commit_group;"); }
__device__ __forceinline__ void cp_wait1()  { asm volatile("cp.async.wait_group 1;"); }
__device__ __forceinline__ void cp_wait0()  { asm volatile("cp.async.wait_group 0;"); }

__device__ __forceinline__ void ldmx4(uint32_t* r, uint32_t addr) {
    asm volatile("ldmatrix.sync.aligned.m8n8.x4.shared.b16 {%0,%1,%2,%3}, [%4];"
                 : "=r"(r[0]), "=r"(r[1]), "=r"(r[2]), "=r"(r[3]) : "r"(addr));
}
__device__ __forceinline__ void ldmx2(uint32_t* r, uint32_t addr) {
    asm volatile("ldmatrix.sync.aligned.m8n8.x2.shared.b16 {%0,%1}, [%2];"
                 : "=r"(r[0]), "=r"(r[1]) : "r"(addr));
}
__device__ __forceinline__ void mma_bf16(float* c, const uint32_t* a, const uint32_t* b) {
    asm volatile("mma.sync.aligned.m16n8k16.row.col.f32.bf16.bf16.f32 "
                 "{%0,%1,%2,%3}, {%4,%5,%6,%7}, {%8,%9}, {%0,%1,%2,%3};"
                 : "+f"(c[0]), "+f"(c[1]), "+f"(c[2]), "+f"(c[3])
                 : "r"(a[0]), "r"(a[1]), "r"(a[2]), "r"(a[3]), "r"(b[0]), "r"(b[1]));
}
__device__ __forceinline__ void mma_f16(float* c, const uint32_t* a, const uint32_t* b) {
    asm volatile("mma.sync.aligned.m16n8k16.row.col.f32.f16.f16.f32 "
                 "{%0,%1,%2,%3}, {%4,%5,%6,%7}, {%8,%9}, {%0,%1,%2,%3};"
                 : "+f"(c[0]), "+f"(c[1]), "+f"(c[2]), "+f"(c[3])
                 : "r"(a[0]), "r"(a[1]), "r"(a[2]), "r"(a[3]), "r"(b[0]), "r"(b[1]));
}
__device__ __forceinline__ void split2(float v, __nv_bfloat16& h, __nv_bfloat16& l) {
    h = __float2bfloat16(v);
    l = __float2bfloat16(v - __bfloat162float(h));
}

// ---------------- elementwise helpers ----------------
__global__ void init_max_kernel(int* gm) { *gm = INT_MIN; }

__global__ void reduce_max_kernel(const int* __restrict__ p, int* gm) {
    int v = INT_MIN;
    for (int k = blockIdx.x * blockDim.x + threadIdx.x; k < NQ; k += gridDim.x * blockDim.x)
        v = max(v, p[k]);
    #pragma unroll
    for (int o = 16; o > 0; o >>= 1) v = max(v, __shfl_xor_sync(0xffffffffu, v, o));
    __shared__ int sm[8];
    int w = threadIdx.x >> 5;
    if ((threadIdx.x & 31) == 0) sm[w] = v;
    __syncthreads();
    if (threadIdx.x == 0) {
        int bv = sm[0];
        for (int i = 1; i < (int)(blockDim.x >> 5); i++) bv = max(bv, sm[i]);
        atomicMax(gm, bv);
    }
}

__global__ void write_mask_kernel(const int* __restrict__ p, const int* __restrict__ gm,
                                  float* __restrict__ out) {
    int i = blockIdx.x * blockDim.x + threadIdx.x;
    if (i < NQ) out[i] = (p[i] < *gm) ? 1.0f : 0.0f;
}

// q+pos -> fp16
__global__ void add_f16_kernel(const float* __restrict__ A, const float* __restrict__ B,
                               __half* __restrict__ o, int n)
{
    int i = blockIdx.x * blockDim.x + threadIdx.x;
    if (i < n) o[i] = __float2half_rn(A[i] + B[i]);
}

// ---------------- fused weight prep + value fp16: one launch ----------------
constexpr int Q0 = 802816;            // conv1 fp16 [chunk][co][k]
constexpr int Q1 = Q0 + 73728;        // conv2 bf16 split
constexpr int Q2 = Q1 + 36864;        // conv3 bf16 split
constexpr int Q3 = Q2 + 36864;        // conv4 bf16 split
constexpr int Q4 = Q3 + 2 * 98304;    // OA fp16 (Woff|Wattn), both layers
constexpr int Q5 = Q4 + 2 * 16384;    // Wv fp16
constexpr int Q6 = Q5 + 2 * 16384;    // Wf1 fp16
constexpr int Q7 = Q6 + 2 * 16384;    // Wf2 fp16
constexpr int Q8 = Q7 + 2 * 16384;    // Wout bf16 split
constexpr int Q9 = Q8 + 2 * 768;      // bias pack
constexpr int Q10 = Q9 + NV * 128;    // value -> fp16

__global__ void prep_kernel(
    const float* __restrict__ cw1, const float* __restrict__ cw2,
    const float* __restrict__ cw3, const float* __restrict__ cw4,
    const float* __restrict__ Woff, const float* __restrict__ Wattn,
    const float* __restrict__ Wv, const float* __restrict__ Wf1,
    const float* __restrict__ Wf2, const float* __restrict__ Wout,
    const float* __restrict__ boff, const float* __restrict__ battn,
    const float* __restrict__ value,
    __half* __restrict__ w16, __nv_bfloat16* __restrict__ wch, __nv_bfloat16* __restrict__ wcl,
    __half* __restrict__ wf16,
    __nv_bfloat16* __restrict__ wph, __nv_bfloat16* __restrict__ wpl,
    float* __restrict__ bias_out, __half* __restrict__ vin16)
{
    int i = blockIdx.x * blockDim.x + threadIdx.x;
    if (i >= Q10) return;
    if (i < Q0) {
        int k = i & 63, co = (i >> 6) & 127, c = i >> 13;
        int e = c >> 1, ci = ((c & 1) << 6) + k;
        w16[i] = __float2half_rn(cw1[(((size_t)co * 128 + ci) * 7 + e / 7) * 7 + e % 7]);
    } else if (i < Q3) {
        const float* W; int CO, CI, CIN_CH, base, j;
        if (i < Q1)      { j = i - Q0; W = cw2; CO = 64; CI = 128; CIN_CH = 2; base = WC2_OFF; }
        else if (i < Q2) { j = i - Q1; W = cw3; CO = 48; CI = 64;  CIN_CH = 1; base = WC3_OFF; }
        else             { j = i - Q2; W = cw4; CO = 48; CI = 48;  CIN_CH = 1; base = WC4_OFF; }
        int k = j & 63, co = (j >> 6) & 63, c = j >> 12;
        int e = c / CIN_CH, ci = (c % CIN_CH) * 64 + k;
        float v = (co < CO && ci < CI) ? W[(((size_t)co * CI + ci) * 3 + e / 3) * 3 + e % 3] : 0.f;
        split2(v, wch[base + j], wcl[base + j]);
    } else if (i < Q4) {
        int j = i - Q3, l = j / 98304, r = j % 98304;
        int n = r >> 7, k = r & 127;
        float v = (n < 512) ? Woff[((size_t)l * 128 + k) * 512 + n]
                            : Wattn[((size_t)l * 128 + k) * 256 + (n - 512)];
        wf16[(size_t)l * 147456 + r] = __float2half_rn(v);
    } else if (i < Q7) {
        const float* W; int off, j;
        if (i < Q5)      { j = i - Q4; W = Wv;  off = 768 * 128; }
        else if (i < Q6) { j = i - Q5; W = Wf1; off = 896 * 128; }
        else             { j = i - Q6; W = Wf2; off = 1024 * 128; }
        int l = j >> 14, r = j & 16383;
        int n = r >> 7, k = r & 127;
        wf16[(size_t)l * 147456 + off + r] = __float2half_rn(W[((size_t)l * 128 + k) * 128 + n]);
    } else if (i < Q8) {
        int j = i - Q7, l = j >> 14, r = j & 16383;
        int n = r >> 7, k = r & 127;
        split2(Wout[((size_t)l * 128 + k) * 128 + n], wph[(size_t)l * 16384 + r], wpl[(size_t)l * 16384 + r]);
    } else if (i < Q9) {
        int j = i - Q8, l = j / 768, n = j % 768;
        bias_out[(size_t)l * 768 + n] = (n < 512) ? boff[(size_t)l * 512 + n] : battn[(size_t)l * 256 + n - 512];
    } else {
        int j = i - Q9;
        vin16[j] = __float2half_rn(value[j]);
    }
}

// ---------------- bf16x3 GEMM (Wout only): residual + fp32 out ----------------
constexpr int GROWB = 272;
constexpr int GTILE = 128 * GROWB;
constexpr int GEMM_SMEM = 4 * GTILE;

__global__ void __launch_bounds__(256, 1) gemm_mma6(
    const __nv_bfloat16* __restrict__ Ah, const __nv_bfloat16* __restrict__ Al,
    const __nv_bfloat16* __restrict__ Bh, const __nv_bfloat16* __restrict__ Bl,
    const float* __restrict__ bias, const float* __restrict__ R,
    float* __restrict__ Cf, int M, int N)
{
    extern __shared__ char smem[];
    const int tid = threadIdx.x;
    const int wid = tid >> 5, lane = tid & 31;
    const int warp_m = wid >> 2, warp_n = wid & 3;
    const uint32_t sb = smem_u32(smem);
    const int bm = blockIdx.x * 128, bn = blockIdx.y * 128;

    {
        const int lrow = tid >> 1, lhalf = tid & 1;
        const bool aval = (bm + lrow) < M;
        const uint32_t sa = sb + (uint32_t)lrow * GROWB + (uint32_t)lhalf * 128;
        const char* agh = (const char*)(Ah + (size_t)(aval ? (bm + lrow) : 0) * 128 + lhalf * 64);
        const char* agl = (const char*)(Al + (size_t)(aval ? (bm + lrow) : 0) * 128 + lhalf * 64);
        const char* bgh = (const char*)(Bh + (size_t)(bn + lrow) * 128 + lhalf * 64);
        const char* bgl = (const char*)(Bl + (size_t)(bn + lrow) * 128 + lhalf * 64);
        #pragma unroll
        for (int i = 0; i < 8; i++) {
            cpasync16(sa + i * 16,             agh + i * 16, aval);
            cpasync16(sa + GTILE + i * 16,     agl + i * 16, aval);
            cpasync16(sa + 2 * GTILE + i * 16, bgh + i * 16, true);
            cpasync16(sa + 3 * GTILE + i * 16, bgl + i * 16, true);
        }
        cp_commit();
        cp_wait0();
        __syncthreads();
    }

    float acc[4][4][4];
    #pragma unroll
    for (int mt = 0; mt < 4; mt++)
        #pragma unroll
        for (int nt = 0; nt < 4; nt++)
            #pragma unroll
            for (int d = 0; d < 4; d++) acc[mt][nt][d] = 0.f;

    const uint32_t a_base = sb + (uint32_t)(warp_m * 64 + (lane & 15)) * GROWB + (uint32_t)(lane >> 4) * 16;
    const uint32_t b_base = sb + 2 * GTILE + (uint32_t)(warp_n * 32 + (lane & 7)) * GROWB
                          + (uint32_t)((lane >> 3) & 1) * 16;

    #pragma unroll
    for (int ks = 0; ks < 8; ks++) {
        const uint32_t kbyte = (uint32_t)ks * 32;
        uint32_t bh[4][2], bl[4][2];
        #pragma unroll
        for (int nt = 0; nt < 4; nt++) {
            ldmx2(bh[nt], b_base + (uint32_t)nt * 8 * GROWB + kbyte);
            ldmx2(bl[nt], b_base + GTILE + (uint32_t)nt * 8 * GROWB + kbyte);
        }
        #pragma unroll
        for (int mt = 0; mt < 4; mt++) {
            uint32_t ah[4], al[4];
            ldmx4(ah, a_base + (uint32_t)mt * 16 * GROWB + kbyte);
            ldmx4(al, a_base + GTILE + (uint32_t)mt * 16 * GROWB + kbyte);
            #pragma unroll
            for (int nt = 0; nt < 4; nt++) {
                mma_bf16(acc[mt][nt], ah, bh[nt]);
                mma_bf16(acc[mt][nt], ah, bl[nt]);
                mma_bf16(acc[mt][nt], al, bh[nt]);
            }
        }
    }

    const int g = lane >> 2, tg = lane & 3;
    #pragma unroll
    for (int mt = 0; mt < 4; mt++) {
        const int r0 = bm + warp_m * 64 + mt * 16 + g;
        #pragma unroll
        for (int nt = 0; nt < 4; nt++) {
            const int col = bn + warp_n * 32 + nt * 8 + tg * 2;
            float2 bb = *(const float2*)&bias[col];
            #pragma unroll
            for (int half = 0; half < 2; half++) {
                const int r = r0 + half * 8;
                if (r >= M) continue;
                float2 rr = *(const float2*)&R[(size_t)r * N + col];
                *(float2*)&Cf[(size_t)r * N + col] =
                    make_float2(acc[mt][nt][half * 2] + bb.x + rr.x,
                                acc[mt][nt][half * 2 + 1] + bb.y + rr.y);
            }
        }
    }
}

// ---------------- fp16 single GEMM ----------------
// FLAGS: 1 relu, 2 residual (fp32 R), 4 fp32 out, 8 fp16 out
constexpr int F16GEMM_SMEM = 2 * GTILE;

template<int FLAGS>
__global__ void __launch_bounds__(256, 2) gemm_f16(
    const __half* __restrict__ A, const __half* __restrict__ B,
    const float* __restrict__ bias, const float* __restrict__ R,
    float* __restrict__ Cf, __half* __restrict__ Cx, int M, int N)
{
    extern __shared__ char smem[];
    const int tid = threadIdx.x;
    const int wid = tid >> 5, lane = tid & 31;
    const int warp_m = wid >> 2, warp_n = wid & 3;
    const uint32_t sb = smem_u32(smem);
    const int bm = blockIdx.x * 128, bn = blockIdx.y * 128;

    {
        const int lrow = tid >> 1, lhalf = tid & 1;
        const bool aval = (bm + lrow) < M;
        const uint32_t sa = sb + (uint32_t)lrow * GROWB + (uint32_t)lhalf * 128;
        const char* ag = (const char*)(A + (size_t)(aval ? (bm + lrow) : 0) * 128 + lhalf * 64);
        const char* bg = (const char*)(B + (size_t)(bn + lrow) * 128 + lhalf * 64);
        #pragma unroll
        for (int i = 0; i < 8; i++) {
            cpasync16(sa + i * 16,         ag + i * 16, aval);
            cpasync16(sa + GTILE + i * 16, bg + i * 16, true);
        }
        cp_commit();
        cp_wait0();
        __syncthreads();
    }

    float acc[4][4][4];
    #pragma unroll
    for (int mt = 0; mt < 4; mt++)
        #pragma unroll
        for (int nt = 0; nt < 4; nt++)
            #pragma unroll
            for (int d = 0; d < 4; d++) acc[mt][nt][d] = 0.f;

    const uint32_t a_base = sb + (uint32_t)(warp_m * 64 + (lane & 15)) * GROWB + (uint32_t)(lane >> 4) * 16;
    const uint32_t b_base = sb + GTILE + (uint32_t)(warp_n * 32 + (lane & 7)) * GROWB
                          + (uint32_t)((lane >> 3) & 1) * 16;

    #pragma unroll
    for (int ks = 0; ks < 8; ks++) {
        const uint32_t kbyte = (uint32_t)ks * 32;
        uint32_t bfr[4][2];
        #pragma unroll
        for (int nt = 0; nt < 4; nt++)
            ldmx2(bfr[nt], b_base + (uint32_t)nt * 8 * GROWB + kbyte);
        #pragma unroll
        for (int mt = 0; mt < 4; mt++) {
            uint32_t afr[4];
            ldmx4(afr, a_base + (uint32_t)mt * 16 * GROWB + kbyte);
            #pragma unroll
            for (int nt = 0; nt < 4; nt++)
                mma_f16(acc[mt][nt], afr, bfr[nt]);
        }
    }

    const int g = lane >> 2, tg = lane & 3;
    #pragma unroll
    for (int mt = 0; mt < 4; mt++) {
        const int r0 = bm + warp_m * 64 + mt * 16 + g;
        #pragma unroll
        for (int nt = 0; nt < 4; nt++) {
            const int col = bn + warp_n * 32 + nt * 8 + tg * 2;
            float2 bb = *(const float2*)&bias[col];
            #pragma unroll
            for (int half = 0; half < 2; half++) {
                const int r = r0 + half * 8;
                if (r >= M) continue;
                float a0 = acc[mt][nt][half * 2] + bb.x;
                float a1 = acc[mt][nt][half * 2 + 1] + bb.y;
                if (FLAGS & 2) {
                    float2 rr = *(const float2*)&R[(size_t)r * N + col];
                    a0 += rr.x; a1 += rr.y;
                }
                if (FLAGS & 1) { a0 = fmaxf(a0, 0.f); a1 = fmaxf(a1, 0.f); }
                if (FLAGS & 4)
                    *(float2*)&Cf[(size_t)r * N + col] = make_float2(a0, a1);
                if (FLAGS & 8)
                    *(__half2*)&Cx[(size_t)r * N + col] = __floats2half2_rn(a0, a1);
            }
        }
    }
}

// ---------------- deformable attention sampling (fp16 V + fp16 OA, fused softmax) ----------------
__global__ void __launch_bounds__(256) deform_kernel(
    const __half* __restrict__ VX, const __half* __restrict__ OA,
    __nv_bfloat16* __restrict__ OH, __nv_bfloat16* __restrict__ OL)
{
    int t = blockIdx.x * 256 + threadIdx.x;
    if (t >= NQ * HEADS) return;
    const int n = t >> 3, h = t & 7;
    const float rx = ((float)(n % 200) + 0.5f) * (1.f / 200.f);
    const float ry = ((float)(n / 200) + 0.5f) * (1.f / 200.f);
    const __half* op = OA + (size_t)n * 768 + h * 64;
    const __half* ap = OA + (size_t)n * 768 + 512 + h * 32;

    float e[32];
    {
        const uint4* apv = (const uint4*)ap;
        #pragma unroll
        for (int q = 0; q < 4; q++) {
            uint4 u = apv[q];
            uint32_t wv[4] = {u.x, u.y, u.z, u.w};
            #pragma unroll
            for (int d = 0; d < 4; d++) {
                float2 f2 = __half22float2(*(const __half2*)&wv[d]);
                e[q * 8 + d * 2 + 0] = f2.x;
                e[q * 8 + d * 2 + 1] = f2.y;
            }
        }
        float m = -1e30f;
        #pragma unroll
        for (int k = 0; k < 32; k++) m = fmaxf(m, e[k]);
        float s = 0.f;
        #pragma unroll
        for (int k = 0; k < 32; k++) { e[k] = expf(e[k] - m); s += e[k]; }
        float inv = 1.f / s;
        #pragma unroll
        for (int k = 0; k < 32; k++) e[k] *= inv;
    }

    float acc[16];
    #pragma unroll
    for (int d = 0; d < 16; d++) acc[d] = 0.f;

    const int stc[4] = {0, 32768, 40960, 43008};
    const int Wc[4]  = {256, 128, 64, 32};
    const int Hc[4]  = {128, 64, 32, 16};
    const uint4* opv = (const uint4*)op;

    #pragma unroll
    for (int l = 0; l < 4; l++) {
        const int W = Wc[l], H = Hc[l], st = stc[l];
        const float Wf = (float)W, Hf = (float)H;
        // vectorized offset loads: 8 points = 16 halves = 2 x uint4
        uint4 o0 = opv[l * 2], o1 = opv[l * 2 + 1];
        uint32_t ow[8] = {o0.x, o0.y, o0.z, o0.w, o1.x, o1.y, o1.z, o1.w};
        #pragma unroll
        for (int p = 0; p < 8; p++) {
            float2 off2 = __half22float2(*(const __half2*)&ow[p]);
            float aw = e[l * 8 + p];
            float x = (rx + off2.x / Wf) * Wf - 0.5f;
            float y = (ry + off2.y / Hf) * Hf - 0.5f;
            float xf = floorf(x), yf = floorf(y);
            int x0 = (int)xf, y0 = (int)yf;
            float fx = x - xf, fy = y - yf;
            float wx[2] = {1.f - fx, fx};
            float wy[2] = {1.f - fy, fy};
            #pragma unroll
            for (int c = 0; c < 4; c++) {
                int xi = x0 + (c & 1), yi = y0 + (c >> 1);
                float wgt = wx[c & 1] * wy[c >> 1];
                if (xi >= 0 && xi < W && yi >= 0 && yi < H && wgt != 0.f) {
                    const uint4* gp = (const uint4*)(VX + ((size_t)(st + yi * W + xi)) * 128 + h * 16);
                    uint4 u0 = gp[0];
                    uint4 u1 = gp[1];
                    uint32_t wv[8] = {u0.x, u0.y, u0.z, u0.w, u1.x, u1.y, u1.z, u1.w};
                    float cw = aw * wgt;
                    #pragma unroll
                    for (int d = 0; d < 8; d++) {
                        float2 g2 = __half22float2(*(const __half2*)&wv[d]);
                        acc[d * 2 + 0] += cw * g2.x;
                        acc[d * 2 + 1] += cw * g2.y;
                    }
                }
            }
        }
    }
    __nv_bfloat162* oh = (__nv_bfloat162*)(OH + (size_t)n * 128 + h * 16);
    __nv_bfloat162* ol = (__nv_bfloat162*)(OL + (size_t)n * 128 + h * 16);
    #pragma unroll
    for (int d = 0; d < 8; d++) {
        __nv_bfloat16 h0, l0, h1, l1;
        split2(acc[d * 2], h0, l0); split2(acc[d * 2 + 1], h1, l1);
        oh[d] = __nv_bfloat162(h0, h1);
        ol[d] = __nv_bfloat162(l0, l1);
    }
}

// ---------------- layernorm: warp-per-row, 8 rows per block ----------------
// MODE: 3 fp32 + fp16(y), 4 fp32 + fp16(y + pos)
template<int MODE>
__global__ void __launch_bounds__(256) ln_kernel(
    const float* __restrict__ X, const float* __restrict__ g,
    const float* __restrict__ b, float* __restrict__ Y,
    __half* __restrict__ Yx, const float* __restrict__ pos)
{
    const int wid = threadIdx.x >> 5, lane = threadIdx.x & 31;
    const int r = blockIdx.x * 8 + wid;
    if (r >= NQ) return;
    const size_t base = (size_t)r * 128 + lane * 4;
    float4 x4 = *(const float4*)&X[base];
    float s = x4.x + x4.y + x4.z + x4.w;
    #pragma unroll
    for (int o = 16; o > 0; o >>= 1) s += __shfl_xor_sync(0xffffffffu, s, o);
    float m = s * (1.f / 128.f);
    float d0 = x4.x - m, d1 = x4.y - m, d2 = x4.z - m, d3 = x4.w - m;
    float q = d0 * d0 + d1 * d1 + d2 * d2 + d3 * d3;
    #pragma unroll
    for (int o = 16; o > 0; o >>= 1) q += __shfl_xor_sync(0xffffffffu, q, o);
    float inv = rsqrtf(q * (1.f / 128.f) + 1e-5f);
    float4 g4 = *(const float4*)&g[lane * 4];
    float4 b4 = *(const float4*)&b[lane * 4];
    float y0 = d0 * inv * g4.x + b4.x;
    float y1 = d1 * inv * g4.y + b4.y;
    float y2 = d2 * inv * g4.z + b4.z;
    float y3 = d3 * inv * g4.w + b4.w;
    *(float4*)&Y[base] = make_float4(y0, y1, y2, y3);
    if (MODE == 4) {
        float4 p4 = *(const float4*)&pos[base];
        y0 += p4.x; y1 += p4.y; y2 += p4.z; y3 += p4.w;
    }
    __half2 h01 = __floats2half2_rn(y0, y1);
    __half2 h23 = __floats2half2_rn(y2, y3);
    *(uint2*)&Yx[base] = make_uint2(*(uint32_t*)&h01, *(uint32_t*)&h23);
}

// ---------------- conv1 (7x7, 128->128) via mma.sync fp16, fused BN stats ----------------
constexpr int ROWB = 144;
constexpr int C1TILE = 128 * ROWB;
constexpr int C1BUF  = 2 * C1TILE;
constexpr int CONV1_SMEM = 2 * C1BUF;

__global__ void __launch_bounds__(256, 2) conv1_f16_kernel(
    const __half* __restrict__ q16, const __half* __restrict__ w16,
    float* __restrict__ Out, float* __restrict__ part)
{
    extern __shared__ char smem[];
    __shared__ float red_s[8][128], red_q[8][128];
    const int tid = threadIdx.x;
    const int wid = tid >> 5, lane = tid & 31;
    const int warp_m = wid >> 2, warp_n = wid & 3;
    const uint32_t sb = smem_u32(smem);
    const int bm = blockIdx.x * 128;

    const int lrow = tid >> 1, lhalf = tid & 1;
    const int pm = bm + lrow;
    const int py = pm / 200, px = pm % 200;
    const bool prow_ok = pm < NQ;
    const uint32_t s_arow = sb + (uint32_t)lrow * ROWB + (uint32_t)lhalf * 64;
    const uint32_t s_brow = s_arow + C1TILE;

    const uint32_t a_base = sb + (uint32_t)(warp_m * 64 + (lane & 15)) * ROWB + (uint32_t)(lane >> 4) * 16;
    const uint32_t b_base = sb + C1TILE + (uint32_t)(warp_n * 32 + (lane & 7)) * ROWB
                          + (uint32_t)((lane >> 3) & 1) * 16;

    float acc[4][4][4];
    #pragma unroll
    for (int mt = 0; mt < 4; mt++)
        #pragma unroll
        for (int nt = 0; nt < 4; nt++)
            #pragma unroll
            for (int d = 0; d < 4; d++) acc[mt][nt][d] = 0.f;

    auto load_chunk = [&](int c, int buf) {
        const int e = c >> 1, ch = c & 1;
        const int qy = py + e / 7 - 3;
        const int qx = px + e % 7 - 3;
        const bool val = prow_ok && qy >= 0 && qy < 200 && qx >= 0 && qx < 200;
        const size_t aoff = (size_t)(val ? (qy * 200 + qx) : 0) * 128 + (size_t)ch * 64 + (size_t)lhalf * 32;
        const char* ag = (const char*)(q16 + aoff);
        const size_t boff = ((size_t)c * 128 + lrow) * 64 + (size_t)lhalf * 32;
        const char* bg = (const char*)(w16 + boff);
        const uint32_t sa = s_arow + (uint32_t)buf * C1BUF;
        const uint32_t sbr = s_brow + (uint32_t)buf * C1BUF;
        #pragma unroll
        for (int i = 0; i < 4; i++) {
            cpasync16(sa + i * 16,  ag + i * 16, val);
            cpasync16(sbr + i * 16, bg + i * 16, true);
        }
    };

    load_chunk(0, 0); cp_commit();
    load_chunk(1, 1); cp_commit();

    for (int c = 0; c < W1CHUNKS; c++) {
        const int buf = c & 1;
        cp_wait1();
        __syncthreads();

        const uint32_t ab = a_base + (uint32_t)buf * C1BUF;
        const uint32_t bb = b_base + (uint32_t)buf * C1BUF;
        #pragma unroll
        for (int ks = 0; ks < 4; ks++) {
            const uint32_t kbyte = (uint32_t)ks * 32;
            uint32_t bfr[4][2];
            #pragma unroll
            for (int nt = 0; nt < 4; nt++)
                ldmx2(bfr[nt], bb + (uint32_t)nt * 8 * ROWB + kbyte);
            #pragma unroll
            for (int mt = 0; mt < 4; mt++) {
                uint32_t afr[4];
                ldmx4(afr, ab + (uint32_t)mt * 16 * ROWB + kbyte);
                #pragma unroll
                for (int nt = 0; nt < 4; nt++)
                    mma_f16(acc[mt][nt], afr, bfr[nt]);
            }
        }
        __syncthreads();
        if (c + 2 < W1CHUNKS) load_chunk(c + 2, buf);
        cp_commit();
    }

    const int g = lane >> 2, tg = lane & 3;
    #pragma unroll
    for (int mt = 0; mt < 4; mt++) {
        const int r0 = bm + warp_m * 64 + mt * 16 + g;
        #pragma unroll
        for (int nt = 0; nt < 4; nt++) {
            const int col = warp_n * 32 + nt * 8 + tg * 2;
            if (r0 < NQ)
                *(float2*)&Out[(size_t)r0 * 128 + col] = make_float2(acc[mt][nt][0], acc[mt][nt][1]);
            if (r0 + 8 < NQ)
                *(float2*)&Out[(size_t)(r0 + 8) * 128 + col] = make_float2(acc[mt][nt][2], acc[mt][nt][3]);
        }
    }

    // fused BN stats (rows >= NQ contribute exact zeros since A tiles are zero-filled)
    float cs[8], cq[8];
    #pragma unroll
    for (int nt = 0; nt < 4; nt++)
        #pragma unroll
        for (int j = 0; j < 2; j++) {
            float s = 0.f, q = 0.f;
            #pragma unroll
            for (int mt = 0; mt < 4; mt++) {
                float v0 = acc[mt][nt][j], v1 = acc[mt][nt][2 + j];
                s += v0 + v1; q += v0 * v0 + v1 * v1;
            }
            cs[nt * 2 + j] = s; cq[nt * 2 + j] = q;
        }
    #pragma unroll
    for (int k = 0; k < 8; k++) {
        #pragma unroll
        for (int o = 4; o <= 16; o <<= 1) {
            cs[k] += __shfl_xor_sync(0xffffffffu, cs[k], o);
            cq[k] += __shfl_xor_sync(0xffffffffu, cq[k], o);
        }
    }
    if (lane < 4) {
        #pragma unroll
        for (int nt = 0; nt < 4; nt++)
            #pragma unroll
            for (int j = 0; j < 2; j++) {
                int col = warp_n * 32 + nt * 8 + lane * 2 + j;
                red_s[wid][col] = cs[nt * 2 + j];
                red_q[wid][col] = cq[nt * 2 + j];
            }
    }
    __syncthreads();
    if (tid < 128) {
        int wn = tid >> 5;
        float s = red_s[wn][tid] + red_s[4 + wn][tid];
        float q = red_q[wn][tid] + red_q[4 + wn][tid];
        part[(size_t)blockIdx.x * 256 + tid] = s;
        part[(size_t)blockIdx.x * 256 + 128 + tid] = q;
    }
}

// ---------------- convs 2-4 (3x3) via mma.sync bf16x3, fused BN stats ----------------
constexpr int CATILE = 128 * ROWB;
constexpr int CBTILE = 64 * ROWB;
constexpr int CBUF = 2 * CATILE + 2 * CBTILE;
constexpr int CONV_SMEM = 2 * CBUF;

template<int CHUNKS, int CIN_CH, int CST>
__global__ void __launch_bounds__(256, 2) conv_mma_kernel(
    const __nv_bfloat16* __restrict__ inh, const __nv_bfloat16* __restrict__ inl,
    const __nv_bfloat16* __restrict__ wh, const __nv_bfloat16* __restrict__ wl,
    float* __restrict__ Out, int COUT, float* __restrict__ part)
{
    extern __shared__ char smem[];
    __shared__ float red_s[8][64], red_q[8][64];
    const int tid = threadIdx.x;
    const int wid = tid >> 5, lane = tid & 31;
    const int warp_m = wid >> 1, warp_n = wid & 1;
    const uint32_t sb = smem_u32(smem);
    const int bm = blockIdx.x * 128;

    const int lrow = tid >> 1, lhalf = tid & 1;
    const int pm = bm + lrow;
    const int py = pm / 200, px = pm % 200;
    const bool prow_ok = pm < NQ;
    const uint32_t s_arow = sb + (uint32_t)lrow * ROWB + (uint32_t)lhalf * 64;
    const int brow = tid >> 2, bq = tid & 3;
    const uint32_t s_brow = sb + 2 * CATILE + (uint32_t)brow * ROWB + (uint32_t)bq * 32;

    const uint32_t a_base = sb + (uint32_t)(warp_m * 32 + (lane & 15)) * ROWB + (uint32_t)(lane >> 4) * 16;
    const uint32_t b_base = sb + 2 * CATILE + (uint32_t)(warp_n * 32 + (lane & 7)) * ROWB
                          + (uint32_t)((lane >> 3) & 1) * 16;

    float acc[2][4][4];
    #pragma unroll
    for (int mt = 0; mt < 2; mt++)
        #pragma unroll
        for (int nt = 0; nt < 4; nt++)
            #pragma unroll
            for (int d = 0; d < 4; d++) acc[mt][nt][d] = 0.f;

    auto load_chunk = [&](int c, int buf) {
        const int e = c / CIN_CH, cih = c % CIN_CH;
        const int qy = py + e / 3 - 1;
        const int qx = px + e % 3 - 1;
        const bool val = prow_ok && qy >= 0 && qy < 200 && qx >= 0 && qx < 200;
        const size_t aoff = (size_t)(val ? (qy * 200 + qx) : 0) * CST + (size_t)cih * 64 + (size_t)lhalf * 32;
        const char* agh = (const char*)(inh + aoff);
        const char* agl = (const char*)(inl + aoff);
        const size_t boff = ((size_t)c * 64 + brow) * 64 + (size_t)bq * 16;
        const char* bgh = (const char*)(wh + boff);
        const char* bgl = (const char*)(wl + boff);
        const uint32_t sa = s_arow + (uint32_t)buf * CBUF;
        const uint32_t sbr = s_brow + (uint32_t)buf * CBUF;
        #pragma unroll
        for (int i = 0; i < 4; i++) {
            cpasync16(sa + i * 16,           agh + i * 16, val);
            cpasync16(sa + CATILE + i * 16,  agl + i * 16, val);
        }
        #pragma unroll
        for (int i = 0; i < 2; i++) {
            cpasync16(sbr + i * 16,          bgh + i * 16, true);
            cpasync16(sbr + CBTILE + i * 16, bgl + i * 16, true);
        }
    };

    load_chunk(0, 0); cp_commit();
    load_chunk(1, 1); cp_commit();

    for (int c = 0; c < CHUNKS; c++) {
        const int buf = c & 1;
        cp_wait1();
        __syncthreads();

        const uint32_t ab = a_base + (uint32_t)buf * CBUF;
        const uint32_t bb = b_base + (uint32_t)buf * CBUF;
        #pragma unroll
        for (int ks = 0; ks < 4; ks++) {
            const uint32_t kbyte = (uint32_t)ks * 32;
            uint32_t bh[4][2], bl[4][2];
            #pragma unroll
            for (int nt = 0; nt < 4; nt++) {
                ldmx2(bh[nt], bb + (uint32_t)nt * 8 * ROWB + kbyte);
                ldmx2(bl[nt], bb + CBTILE + (uint32_t)nt * 8 * ROWB + kbyte);
            }
            #pragma unroll
            for (int mt = 0; mt < 2; mt++) {
                uint32_t ah[4], al[4];
                ldmx4(ah, ab + (uint32_t)mt * 16 * ROWB + kbyte);
                ldmx4(al, ab + CATILE + (uint32_t)mt * 16 * ROWB + kbyte);
                #pragma unroll
                for (int nt = 0; nt < 4; nt++) {
                    mma_bf16(acc[mt][nt], ah, bh[nt]);
                    mma_bf16(acc[mt][nt], ah, bl[nt]);
                    mma_bf16(acc[mt][nt], al, bh[nt]);
                }
            }
        }
        __syncthreads();
        if (c + 2 < CHUNKS) load_chunk(c + 2, buf);
        cp_commit();
    }

    const int g = lane >> 2, tg = lane & 3;
    #pragma unroll
    for (int mt = 0; mt < 2; mt++) {
        const int r0 = bm + warp_m * 32 + mt * 16 + g;
        #pragma unroll
        for (int nt = 0; nt < 4; nt++) {
            const int col = warp_n * 32 + nt * 8 + tg * 2;
            if (col >= COUT) continue;
            if (r0 < NQ)
                *(float2*)&Out[(size_t)r0 * COUT + col] = make_float2(acc[mt][nt][0], acc[mt][nt][1]);
            if (r0 + 8 < NQ)
                *(float2*)&Out[(size_t)(r0 + 8) * COUT + col] = make_float2(acc[mt][nt][2], acc[mt][nt][3]);
        }
    }

    // fused BN stats
    float cs[8], cq[8];
    #pragma unroll
    for (int nt = 0; nt < 4; nt++)
        #pragma unroll
        for (int j = 0; j < 2; j++) {
            float s = 0.f, q = 0.f;
            #pragma unroll
            for (int mt = 0; mt < 2; mt++) {
                float v0 = acc[mt][nt][j], v1 = acc[mt][nt][2 + j];
                s += v0 + v1; q += v0 * v0 + v1 * v1;
            }
            cs[nt * 2 + j] = s; cq[nt * 2 + j] = q;
        }
    #pragma unroll
    for (int k = 0; k < 8; k++) {
        #pragma unroll
        for (int o = 4; o <= 16; o <<= 1) {
            cs[k] += __shfl_xor_sync(0xffffffffu, cs[k], o);
            cq[k] += __shfl_xor_sync(0xffffffffu, cq[k], o);
        }
    }
    if (lane < 4) {
        #pragma unroll
        for (int nt = 0; nt < 4; nt++)
            #pragma unroll
            for (int j = 0; j < 2; j++) {
                int col = warp_n * 32 + nt * 8 + lane * 2 + j;
                red_s[wid][col] = cs[nt * 2 + j];
                red_q[wid][col] = cq[nt * 2 + j];
            }
    }
    __syncthreads();
    if (tid < COUT) {
        int wn = tid >> 5;
        float s = 0.f, q = 0.f;
        #pragma unroll
        for (int wm = 0; wm < 4; wm++) {
            s += red_s[wm * 2 + wn][tid];
            q += red_q[wm * 2 + wn][tid];
        }
        part[(size_t)blockIdx.x * 2 * COUT + tid] = s;
        part[(size_t)blockIdx.x * 2 * COUT + COUT + tid] = q;
    }
}

// ---------------- batchnorm finalize (sums NBLK per-block partials) ----------------
__global__ void bn_finalize_kernel(const float* __restrict__ part,
                                   const float* __restrict__ gamma, const float* __restrict__ beta,
                                   float* __restrict__ scale, float* __restrict__ shift, int C)
{
    int c = threadIdx.x;
    float s = 0.f, q = 0.f;
    for (int g = 0; g < NBLK; g++) {
        s += part[(size_t)g * 2 * C + c];
        q += part[(size_t)g * 2 * C + C + c];
    }
    const float invP = 1.f / (float)NQ;
    float m = s * invP;
    float v = q * invP - m * m;
    float sc = gamma[c] * rsqrtf(v + 1e-5f);
    scale[c] = sc;
    shift[c] = beta[c] - m * sc;
}

__global__ void bn_apply_split_kernel(const float* __restrict__ X, const float* __restrict__ scale,
                                      const float* __restrict__ shift,
                                      __nv_bfloat16* __restrict__ hi, __nv_bfloat16* __restrict__ lo,
                                      int C, int CST, int total)
{
    int i = blockIdx.x * blockDim.x + threadIdx.x;
    if (i >= total) return;
    int c = i % CST;
    int p = i / CST;
    float v = 0.f;
    if (c < C) v = fmaxf(0.f, fmaf(X[(size_t)p * C + c], scale[c], shift[c]));
    split2(v, hi[i], lo[i]);
}

// ---------------- head: fused BN4+ReLU + 1x1 conv 48 -> 21, output NCHW ----------------
__global__ void head_conv_kernel(const float* __restrict__ H4raw, const float* __restrict__ scale,
                                 const float* __restrict__ shift,
                                 const float* __restrict__ Wo, const float* __restrict__ bo,
                                 float* __restrict__ out)
{
    int p = blockIdx.x * blockDim.x + threadIdx.x;
    if (p >= NQ) return;
    float x[48];
    const float4* hp = (const float4*)(H4raw + (size_t)p * 48);
    #pragma unroll
    for (int i = 0; i < 12; i++) {
        float4 v = hp[i];
        x[i * 4 + 0] = v.x; x[i * 4 + 1] = v.y; x[i * 4 + 2] = v.z; x[i * 4 + 3] = v.w;
    }
    #pragma unroll
    for (int ci = 0; ci < 48; ci++)
        x[ci] = fmaxf(0.f, fmaf(x[ci], scale[ci], shift[ci]));
    for (int co = 0; co < 21; co++) {
        float s = bo[co];
        const float* w = Wo + co * 48;
        #pragma unroll
        for (int ci = 0; ci < 48; ci++) s = fmaf(x[ci], w[ci], s);
        out[(size_t)co * NQ + p] = s;
    }
}

// ---------------- launch ----------------
extern "C" void kernel_launch(void* const* d_in, const int* in_sizes, int n_in,
                              void* d_out, int out_size)
{
    const float* value = (const float*)d_in[0];
    const float* bq    = (const float*)d_in[1];
    const float* bpos  = (const float*)d_in[2];
    const int*   proj  = (const int*)d_in[3];
    const float* Wv    = (const float*)d_in[4];
    const float* bv    = (const float*)d_in[5];
    const float* Woff  = (const float*)d_in[6];
    const float* boff  = (const float*)d_in[7];
    const float* Wattn = (const float*)d_in[8];
    const float* battn = (const float*)d_in[9];
    const float* Wout  = (const float*)d_in[10];
    const float* bout  = (const float*)d_in[11];
    const float* Wf1   = (const float*)d_in[12];
    const float* bf1   = (const float*)d_in[13];
    const float* Wf2   = (const float*)d_in[14];
    const float* bf2   = (const float*)d_in[15];
    const float* lng   = (const float*)d_in[16];
    const float* lnb   = (const float*)d_in[17];
    const float* cw1   = (const float*)d_in[18];
    const float* g1    = (const float*)d_in[19];
    const float* b1    = (const float*)d_in[20];
    const float* cw2   = (const float*)d_in[21];
    const float* g2    = (const float*)d_in[22];
    const float* b2    = (const float*)d_in[23];
    const float* cw3   = (const float*)d_in[24];
    const float* g3    = (const float*)d_in[25];
    const float* b3    = (const float*)d_in[26];
    const float* cw4   = (const float*)d_in[27];
    const float* g4    = (const float*)d_in[28];
    const float* b4    = (const float*)d_in[29];
    const float* objw  = (const float*)d_in[30];
    const float* objb  = (const float*)d_in[31];
    float* out = (float*)d_out;

    float* S = nullptr;
    cudaGetSymbolAddress((void**)&S, g_scratch);
    int* gm = nullptr;
    cudaGetSymbolAddress((void**)&gm, g_maxv);
    __nv_bfloat16 *s1h, *s1l, *s2h, *s2l, *wph, *wpl, *wch, *wcl;
    __half *vx, *vin16, *q16, *qp16, *w16, *wf16, *oa16;
    cudaGetSymbolAddress((void**)&s1h, g_s1h);
    cudaGetSymbolAddress((void**)&s1l, g_s1l);
    cudaGetSymbolAddress((void**)&s2h, g_s2h);
    cudaGetSymbolAddress((void**)&s2l, g_s2l);
    cudaGetSymbolAddress((void**)&vx,  g_vx);
    cudaGetSymbolAddress((void**)&vin16, g_vin16);
    cudaGetSymbolAddress((void**)&q16, g_q16);
    cudaGetSymbolAddress((void**)&qp16, g_qp16);
    cudaGetSymbolAddress((void**)&w16, g_w16);
    cudaGetSymbolAddress((void**)&wf16, g_wf16);
    cudaGetSymbolAddress((void**)&oa16, g_oa16);
    cudaGetSymbolAddress((void**)&wph, g_wph);
    cudaGetSymbolAddress((void**)&wpl, g_wpl);
    cudaGetSymbolAddress((void**)&wch, g_wch);
    cudaGetSymbolAddress((void**)&wcl, g_wcl);

    float* PQ    = S + OFF_Q;
    float* PT1   = S + OFF_T1;
    float* PT2   = S + OFF_T2;
    float* PH1   = S + OFF_H1;
    float* PH2   = S + OFF_H2;
    float* PH3   = S + OFF_H3;
    float* PH4   = S + OFF_H4;
    float* PPART = S + OFF_PART;
    float* PSCALE= S + OFF_SCALE;
    float* PSHIFT= S + OFF_SHIFT;
    float* PBIAS = S + OFF_BIAS;

    cudaFuncSetAttribute(conv1_f16_kernel, cudaFuncAttributeMaxDynamicSharedMemorySize, CONV1_SMEM);
    cudaFuncSetAttribute(gemm_f16<8>,    cudaFuncAttributeMaxDynamicSharedMemorySize, F16GEMM_SMEM);
    cudaFuncSetAttribute(gemm_f16<9>,    cudaFuncAttributeMaxDynamicSharedMemorySize, F16GEMM_SMEM);
    cudaFuncSetAttribute(gemm_f16<6>,    cudaFuncAttributeMaxDynamicSharedMemorySize, F16GEMM_SMEM);
    cudaFuncSetAttribute(gemm_mma6,      cudaFuncAttributeMaxDynamicSharedMemorySize, GEMM_SMEM);
    cudaFuncSetAttribute((conv_mma_kernel<18, 2, 128>), cudaFuncAttributeMaxDynamicSharedMemorySize, CONV_SMEM);
    cudaFuncSetAttribute((conv_mma_kernel<9, 1, 64>),   cudaFuncAttributeMaxDynamicSharedMemorySize, CONV_SMEM);

    // --- observed_masks ---
    init_max_kernel<<<1, 1>>>(gm);
    reduce_max_kernel<<<40, 256>>>(proj, gm);
    write_mask_kernel<<<(NQ + 255) / 256, 256>>>(proj, gm, out + 21 * NQ);

    // --- fused weight prep + value fp16 (single launch) ---
    prep_kernel<<<(Q10 + 255) / 256, 256>>>(cw1, cw2, cw3, cw4, Woff, Wattn, Wv, Wf1, Wf2, Wout,
                                            boff, battn, value,
                                            w16, wch, wcl, wf16, wph, wpl, PBIAS, vin16);

    // --- q init ---
    cudaMemcpyAsync(PQ, bq, (size_t)NQ * ED * sizeof(float), cudaMemcpyDeviceToDevice);

    // --- 2 encoder layers ---
    add_f16_kernel<<<(NQ * ED + 255) / 256, 256>>>(PQ, bpos, qp16, NQ * ED);
    for (int i = 0; i < 2; i++) {
        size_t LW = (size_t)i * 1152 * 128;
        gemm_f16<8><<<dim3(340, 1), 256, F16GEMM_SMEM>>>(vin16, wf16 + LW + 768 * 128,
                                                         bv + i * 128, nullptr, nullptr, vx, NV, 128);
        gemm_f16<8><<<dim3(313, 6), 256, F16GEMM_SMEM>>>(qp16, wf16 + LW,
                                                         PBIAS + i * 768, nullptr, nullptr, oa16, NQ, 768);
        deform_kernel<<<(NQ * HEADS + 255) / 256, 256>>>(vx, oa16, s2h, s2l);
        gemm_mma6<<<dim3(313, 1), 256, GEMM_SMEM>>>(s2h, s2l, wph + (size_t)i * 128 * 128, wpl + (size_t)i * 128 * 128,
                                                    bout + i * 128, PQ, PT1, NQ, 128);
        ln_kernel<3><<<(NQ + 7) / 8, 256>>>(PT1, lng + (i * 2 + 0) * 128, lnb + (i * 2 + 0) * 128, PQ, q16, nullptr);
        gemm_f16<9><<<dim3(313, 1), 256, F16GEMM_SMEM>>>(q16, wf16 + LW + 896 * 128,
                                                         bf1 + i * 128, nullptr, nullptr, qp16, NQ, 128);
        gemm_f16<6><<<dim3(313, 1), 256, F16GEMM_SMEM>>>(qp16, wf16 + LW + 1024 * 128,
                                                         bf2 + i * 128, PQ, PT2, nullptr, NQ, 128);
        if (i == 0)
            ln_kernel<4><<<(NQ + 7) / 8, 256>>>(PT2, lng + 1 * 128, lnb + 1 * 128, PQ, qp16, bpos);   // fp16(q+pos)
        else
            ln_kernel<3><<<(NQ + 7) / 8, 256>>>(PT2, lng + 3 * 128, lnb + 3 * 128, PQ, q16, nullptr); // fp16(q)
    }

    // --- conv head (BN stats fused into conv epilogues) ---
    conv1_f16_kernel<<<NBLK, 256, CONV1_SMEM>>>(q16, w16, PH1, PPART);
    bn_finalize_kernel<<<1, 128>>>(PPART, g1, b1, PSCALE, PSHIFT, 128);
    bn_apply_split_kernel<<<(NQ * 128 + 255) / 256, 256>>>(PH1, PSCALE, PSHIFT, s1h, s1l, 128, 128, NQ * 128);

    conv_mma_kernel<18, 2, 128><<<NBLK, 256, CONV_SMEM>>>(s1h, s1l, wch + WC2_OFF, wcl + WC2_OFF, PH2, 64, PPART);
    bn_finalize_kernel<<<1, 64>>>(PPART, g2, b2, PSCALE, PSHIFT, 64);
    bn_apply_split_kernel<<<(NQ * 64 + 255) / 256, 256>>>(PH2, PSCALE, PSHIFT, s2h, s2l, 64, 64, NQ * 64);

    conv_mma_kernel<9, 1, 64><<<NBLK, 256, CONV_SMEM>>>(s2h, s2l, wch + WC3_OFF, wcl + WC3_OFF, PH3, 48, PPART);
    bn_finalize_kernel<<<1, 48>>>(PPART, g3, b3, PSCALE, PSHIFT, 48);
    bn_apply_split_kernel<<<(NQ * 64 + 255) / 256, 256>>>(PH3, PSCALE, PSHIFT, s1h, s1l, 48, 64, NQ * 64);

    conv_mma_kernel<9, 1, 64><<<NBLK, 256, CONV_SMEM>>>(s1h, s1l, wch + WC4_OFF, wcl + WC4_OFF, PH4, 48, PPART);
    bn_finalize_kernel<<<1, 48>>>(PPART, g4, b4, PSCALE, PSHIFT, 48);
    head_conv_kernel<<<(NQ + 255) / 256, 256>>>(PH4, PSCALE, PSHIFT, objw, objb, out);
}

// round 15
// speedup vs baseline: 3.4676x; 1.0434x over previous
#include <cuda_runtime.h>
#include <cuda_bf16.h>
#include <cuda_fp16.h>
#include <cstdint>
#include <climits>

// ---------------- problem constants ----------------
constexpr int NQ = 40000;        // 200*200
constexpr int ED = 128;
constexpr int NV = 43520;        // sum of level sizes
constexpr int HEADS = 8;
constexpr int NBLK = 313;        // conv blocks = bn partials

// ---------------- scratch layout (floats) ----------------
constexpr size_t OFF_Q    = 0;
constexpr size_t SZ_Q     = (size_t)NQ * ED;
constexpr size_t OFF_T1   = OFF_Q + SZ_Q;
constexpr size_t OFF_T2   = OFF_T1 + SZ_Q;
constexpr size_t OFF_H1   = OFF_T2 + SZ_Q;
constexpr size_t SZ_H1    = (size_t)NQ * 128;
constexpr size_t OFF_H2   = OFF_H1 + SZ_H1;
constexpr size_t SZ_H2    = (size_t)NQ * 64;
constexpr size_t OFF_H3   = OFF_H2 + SZ_H2;
constexpr size_t SZ_H3    = (size_t)NQ * 48;
constexpr size_t OFF_H4   = OFF_H3 + SZ_H3;
constexpr size_t OFF_PART = OFF_H4 + SZ_H3;
constexpr size_t SZ_PART  = (size_t)NBLK * 2 * 128 + 256;
constexpr size_t OFF_SCALE= OFF_PART + SZ_PART;
constexpr size_t OFF_SHIFT= OFF_SCALE + 128;
constexpr size_t OFF_BIAS = OFF_SHIFT + 128;       // 2 layers x 768 packed bias
constexpr size_t SCRATCH_TOTAL = OFF_BIAS + 2 * 768;

__device__ float g_scratch[SCRATCH_TOTAL];
__device__ int   g_maxv;

// ---------------- bf16 / fp16 buffers ----------------
constexpr int W1CHUNKS = 98;                 // conv1: 49 taps * 2 ci-halves
__device__ __align__(16) __nv_bfloat16 g_s1h[(size_t)NQ * 128];
__device__ __align__(16) __nv_bfloat16 g_s1l[(size_t)NQ * 128];
__device__ __align__(16) __nv_bfloat16 g_s2h[(size_t)NQ * 128];
__device__ __align__(16) __nv_bfloat16 g_s2l[(size_t)NQ * 128];
__device__ __align__(16) __half        g_vx[(size_t)NV * 128];    // fp16 V for deform
__device__ __align__(16) __half        g_vin16[(size_t)NV * 128]; // fp16 value input
__device__ __align__(16) __half        g_q16[(size_t)NQ * 128];   // fp16 scratch (deform out / LN out)
__device__ __align__(16) __half        g_qp16[(size_t)NQ * 128];  // fp16 scratch
__device__ __align__(16) __half        g_oa16[(size_t)NQ * 768];  // fp16 offsets+logits
// fp16 weights per layer: [OA 768][Wv 128][Wf1 128][Wf2 128][Wout 128] x 128 k
constexpr int WFL = 1280 * 128;              // per-layer stride
__device__ __align__(16) __half g_wf16[(size_t)2 * WFL];
// conv1 weights [chunk][co 128][k 64] fp16
__device__ __align__(16) __half g_w16[(size_t)W1CHUNKS * 128 * 64];
// convs 2-4 bf16 split weights
constexpr int WC2_OFF = 0, WC3_OFF = 73728, WC4_OFF = 110592, WC_TOTAL = 147456;
__device__ __align__(16) __nv_bfloat16 g_wch[WC_TOTAL];
__device__ __align__(16) __nv_bfloat16 g_wcl[WC_TOTAL];

// ---------------- small helpers ----------------
__device__ __forceinline__ uint32_t smem_u32(const void* p) {
    return (uint32_t)__cvta_generic_to_shared(p);
}
__device__ __forceinline__ void cpasync16(uint32_t dst, const void* src, bool valid) {
    asm volatile("cp.async.cg.shared.global [%0], [%1], 16, %2;"
                 :: "r"(dst), "l"(src), "r"(valid ? 16u : 0u));
}
__device__ __forceinline__ void cp_commit() { asm volatile("cp.async.commit_group;"); }
__device__ __forceinline__ void cp_wait1()  { asm volatile("cp.async.wait_group 1;"); }
__device__ __forceinline__ void cp_wait0()  { asm volatile("cp.async.wait_group 0;"); }

__device__ __forceinline__ void ldmx4(uint32_t* r, uint32_t addr) {
    asm volatile("ldmatrix.sync.aligned.m8n8.x4.shared.b16 {%0,%1,%2,%3}, [%4];"
                 : "=r"(r[0]), "=r"(r[1]), "=r"(r[2]), "=r"(r[3]) : "r"(addr));
}
__device__ __forceinline__ void ldmx2(uint32_t* r, uint32_t addr) {
    asm volatile("ldmatrix.sync.aligned.m8n8.x2.shared.b16 {%0,%1}, [%2];"
                 : "=r"(r[0]), "=r"(r[1]) : "r"(addr));
}
__device__ __forceinline__ void mma_bf16(float* c, const uint32_t* a, const uint32_t* b) {
    asm volatile("mma.sync.aligned.m16n8k16.row.col.f32.bf16.bf16.f32 "
                 "{%0,%1,%2,%3}, {%4,%5,%6,%7}, {%8,%9}, {%0,%1,%2,%3};"
                 : "+f"(c[0]), "+f"(c[1]), "+f"(c[2]), "+f"(c[3])
                 : "r"(a[0]), "r"(a[1]), "r"(a[2]), "r"(a[3]), "r"(b[0]), "r"(b[1]));
}
__device__ __forceinline__ void mma_f16(float* c, const uint32_t* a, const uint32_t* b) {
    asm volatile("mma.sync.aligned.m16n8k16.row.col.f32.f16.f16.f32 "
                 "{%0,%1,%2,%3}, {%4,%5,%6,%7}, {%8,%9}, {%0,%1,%2,%3};"
                 : "+f"(c[0]), "+f"(c[1]), "+f"(c[2]), "+f"(c[3])
                 : "r"(a[0]), "r"(a[1]), "r"(a[2]), "r"(a[3]), "r"(b[0]), "r"(b[1]));
}
__device__ __forceinline__ void split2(float v, __nv_bfloat16& h, __nv_bfloat16& l) {
    h = __float2bfloat16(v);
    l = __float2bfloat16(v - __bfloat162float(h));
}

// ---------------- elementwise helpers ----------------
__global__ void init_max_kernel(int* gm) { *gm = INT_MIN; }

__global__ void reduce_max_kernel(const int* __restrict__ p, int* gm) {
    int v = INT_MIN;
    for (int k = blockIdx.x * blockDim.x + threadIdx.x; k < NQ; k += gridDim.x * blockDim.x)
        v = max(v, p[k]);
    #pragma unroll
    for (int o = 16; o > 0; o >>= 1) v = max(v, __shfl_xor_sync(0xffffffffu, v, o));
    __shared__ int sm[8];
    int w = threadIdx.x >> 5;
    if ((threadIdx.x & 31) == 0) sm[w] = v;
    __syncthreads();
    if (threadIdx.x == 0) {
        int bv = sm[0];
        for (int i = 1; i < (int)(blockDim.x >> 5); i++) bv = max(bv, sm[i]);
        atomicMax(gm, bv);
    }
}

__global__ void write_mask_kernel(const int* __restrict__ p, const int* __restrict__ gm,
                                  float* __restrict__ out) {
    int i = blockIdx.x * blockDim.x + threadIdx.x;
    if (i < NQ) out[i] = (p[i] < *gm) ? 1.0f : 0.0f;
}

// q+pos -> fp16
__global__ void add_f16_kernel(const float* __restrict__ A, const float* __restrict__ B,
                               __half* __restrict__ o, int n)
{
    int i = blockIdx.x * blockDim.x + threadIdx.x;
    if (i < n) o[i] = __float2half_rn(A[i] + B[i]);
}

// ---------------- fused weight prep + value fp16: one launch ----------------
constexpr int Q0 = 802816;            // conv1 fp16 [chunk][co][k]
constexpr int Q1 = Q0 + 73728;        // conv2 bf16 split
constexpr int Q2 = Q1 + 36864;        // conv3 bf16 split
constexpr int Q3 = Q2 + 36864;        // conv4 bf16 split
constexpr int Q4 = Q3 + 2 * 98304;    // OA fp16 (Woff|Wattn), both layers
constexpr int Q5 = Q4 + 2 * 16384;    // Wv fp16
constexpr int Q6 = Q5 + 2 * 16384;    // Wf1 fp16
constexpr int Q7 = Q6 + 2 * 16384;    // Wf2 fp16
constexpr int Q8 = Q7 + 2 * 16384;    // Wout fp16
constexpr int Q9 = Q8 + 2 * 768;      // bias pack
constexpr int Q10 = Q9 + NV * 128;    // value -> fp16

__global__ void prep_kernel(
    const float* __restrict__ cw1, const float* __restrict__ cw2,
    const float* __restrict__ cw3, const float* __restrict__ cw4,
    const float* __restrict__ Woff, const float* __restrict__ Wattn,
    const float* __restrict__ Wv, const float* __restrict__ Wf1,
    const float* __restrict__ Wf2, const float* __restrict__ Wout,
    const float* __restrict__ boff, const float* __restrict__ battn,
    const float* __restrict__ value,
    __half* __restrict__ w16, __nv_bfloat16* __restrict__ wch, __nv_bfloat16* __restrict__ wcl,
    __half* __restrict__ wf16,
    float* __restrict__ bias_out, __half* __restrict__ vin16)
{
    int i = blockIdx.x * blockDim.x + threadIdx.x;
    if (i >= Q10) return;
    if (i < Q0) {
        int k = i & 63, co = (i >> 6) & 127, c = i >> 13;
        int e = c >> 1, ci = ((c & 1) << 6) + k;
        w16[i] = __float2half_rn(cw1[(((size_t)co * 128 + ci) * 7 + e / 7) * 7 + e % 7]);
    } else if (i < Q3) {
        const float* W; int CO, CI, CIN_CH, base, j;
        if (i < Q1)      { j = i - Q0; W = cw2; CO = 64; CI = 128; CIN_CH = 2; base = WC2_OFF; }
        else if (i < Q2) { j = i - Q1; W = cw3; CO = 48; CI = 64;  CIN_CH = 1; base = WC3_OFF; }
        else             { j = i - Q2; W = cw4; CO = 48; CI = 48;  CIN_CH = 1; base = WC4_OFF; }
        int k = j & 63, co = (j >> 6) & 63, c = j >> 12;
        int e = c / CIN_CH, ci = (c % CIN_CH) * 64 + k;
        float v = (co < CO && ci < CI) ? W[(((size_t)co * CI + ci) * 3 + e / 3) * 3 + e % 3] : 0.f;
        split2(v, wch[base + j], wcl[base + j]);
    } else if (i < Q4) {
        int j = i - Q3, l = j / 98304, r = j % 98304;
        int n = r >> 7, k = r & 127;
        float v = (n < 512) ? Woff[((size_t)l * 128 + k) * 512 + n]
                            : Wattn[((size_t)l * 128 + k) * 256 + (n - 512)];
        wf16[(size_t)l * WFL + r] = __float2half_rn(v);
    } else if (i < Q8) {
        const float* W; int off, j;
        if (i < Q5)      { j = i - Q4; W = Wv;   off = 768 * 128; }
        else if (i < Q6) { j = i - Q5; W = Wf1;  off = 896 * 128; }
        else if (i < Q7) { j = i - Q6; W = Wf2;  off = 1024 * 128; }
        else             { j = i - Q7; W = Wout; off = 1152 * 128; }
        int l = j >> 14, r = j & 16383;
        int n = r >> 7, k = r & 127;
        wf16[(size_t)l * WFL + off + r] = __float2half_rn(W[((size_t)l * 128 + k) * 128 + n]);
    } else if (i < Q9) {
        int j = i - Q8, l = j / 768, n = j % 768;
        bias_out[(size_t)l * 768 + n] = (n < 512) ? boff[(size_t)l * 512 + n] : battn[(size_t)l * 256 + n - 512];
    } else {
        int j = i - Q9;
        vin16[j] = __float2half_rn(value[j]);
    }
}

// ---------------- fp16 single GEMM ----------------
// FLAGS: 1 relu, 2 residual (fp32 R), 4 fp32 out, 8 fp16 out
constexpr int GROWB = 272;
constexpr int GTILE = 128 * GROWB;
constexpr int F16GEMM_SMEM = 2 * GTILE;

template<int FLAGS>
__global__ void __launch_bounds__(256, 2) gemm_f16(
    const __half* __restrict__ A, const __half* __restrict__ B,
    const float* __restrict__ bias, const float* __restrict__ R,
    float* __restrict__ Cf, __half* __restrict__ Cx, int M, int N)
{
    extern __shared__ char smem[];
    const int tid = threadIdx.x;
    const int wid = tid >> 5, lane = tid & 31;
    const int warp_m = wid >> 2, warp_n = wid & 3;
    const uint32_t sb = smem_u32(smem);
    const int bm = blockIdx.x * 128, bn = blockIdx.y * 128;

    {
        const int lrow = tid >> 1, lhalf = tid & 1;
        const bool aval = (bm + lrow) < M;
        const uint32_t sa = sb + (uint32_t)lrow * GROWB + (uint32_t)lhalf * 128;
        const char* ag = (const char*)(A + (size_t)(aval ? (bm + lrow) : 0) * 128 + lhalf * 64);
        const char* bg = (const char*)(B + (size_t)(bn + lrow) * 128 + lhalf * 64);
        #pragma unroll
        for (int i = 0; i < 8; i++) {
            cpasync16(sa + i * 16,         ag + i * 16, aval);
            cpasync16(sa + GTILE + i * 16, bg + i * 16, true);
        }
        cp_commit();
        cp_wait0();
        __syncthreads();
    }

    float acc[4][4][4];
    #pragma unroll
    for (int mt = 0; mt < 4; mt++)
        #pragma unroll
        for (int nt = 0; nt < 4; nt++)
            #pragma unroll
            for (int d = 0; d < 4; d++) acc[mt][nt][d] = 0.f;

    const uint32_t a_base = sb + (uint32_t)(warp_m * 64 + (lane & 15)) * GROWB + (uint32_t)(lane >> 4) * 16;
    const uint32_t b_base = sb + GTILE + (uint32_t)(warp_n * 32 + (lane & 7)) * GROWB
                          + (uint32_t)((lane >> 3) & 1) * 16;

    #pragma unroll
    for (int ks = 0; ks < 8; ks++) {
        const uint32_t kbyte = (uint32_t)ks * 32;
        uint32_t bfr[4][2];
        #pragma unroll
        for (int nt = 0; nt < 4; nt++)
            ldmx2(bfr[nt], b_base + (uint32_t)nt * 8 * GROWB + kbyte);
        #pragma unroll
        for (int mt = 0; mt < 4; mt++) {
            uint32_t afr[4];
            ldmx4(afr, a_base + (uint32_t)mt * 16 * GROWB + kbyte);
            #pragma unroll
            for (int nt = 0; nt < 4; nt++)
                mma_f16(acc[mt][nt], afr, bfr[nt]);
        }
    }

    const int g = lane >> 2, tg = lane & 3;
    #pragma unroll
    for (int mt = 0; mt < 4; mt++) {
        const int r0 = bm + warp_m * 64 + mt * 16 + g;
        #pragma unroll
        for (int nt = 0; nt < 4; nt++) {
            const int col = bn + warp_n * 32 + nt * 8 + tg * 2;
            float2 bb = *(const float2*)&bias[col];
            #pragma unroll
            for (int half = 0; half < 2; half++) {
                const int r = r0 + half * 8;
                if (r >= M) continue;
                float a0 = acc[mt][nt][half * 2] + bb.x;
                float a1 = acc[mt][nt][half * 2 + 1] + bb.y;
                if (FLAGS & 2) {
                    float2 rr = *(const float2*)&R[(size_t)r * N + col];
                    a0 += rr.x; a1 += rr.y;
                }
                if (FLAGS & 1) { a0 = fmaxf(a0, 0.f); a1 = fmaxf(a1, 0.f); }
                if (FLAGS & 4)
                    *(float2*)&Cf[(size_t)r * N + col] = make_float2(a0, a1);
                if (FLAGS & 8)
                    *(__half2*)&Cx[(size_t)r * N + col] = __floats2half2_rn(a0, a1);
            }
        }
    }
}

// ---------------- deformable attention sampling (fp16 V + fp16 OA, fp16 out) ----------------
__global__ void __launch_bounds__(256) deform_kernel(
    const __half* __restrict__ VX, const __half* __restrict__ OA,
    __half* __restrict__ OX)
{
    int t = blockIdx.x * 256 + threadIdx.x;
    if (t >= NQ * HEADS) return;
    const int n = t >> 3, h = t & 7;
    const float rx = ((float)(n % 200) + 0.5f) * (1.f / 200.f);
    const float ry = ((float)(n / 200) + 0.5f) * (1.f / 200.f);
    const __half* op = OA + (size_t)n * 768 + h * 64;
    const __half* ap = OA + (size_t)n * 768 + 512 + h * 32;

    float e[32];
    {
        const uint4* apv = (const uint4*)ap;
        #pragma unroll
        for (int q = 0; q < 4; q++) {
            uint4 u = apv[q];
            uint32_t wv[4] = {u.x, u.y, u.z, u.w};
            #pragma unroll
            for (int d = 0; d < 4; d++) {
                float2 f2 = __half22float2(*(const __half2*)&wv[d]);
                e[q * 8 + d * 2 + 0] = f2.x;
                e[q * 8 + d * 2 + 1] = f2.y;
            }
        }
        float m = -1e30f;
        #pragma unroll
        for (int k = 0; k < 32; k++) m = fmaxf(m, e[k]);
        float s = 0.f;
        #pragma unroll
        for (int k = 0; k < 32; k++) { e[k] = expf(e[k] - m); s += e[k]; }
        float inv = 1.f / s;
        #pragma unroll
        for (int k = 0; k < 32; k++) e[k] *= inv;
    }

    float acc[16];
    #pragma unroll
    for (int d = 0; d < 16; d++) acc[d] = 0.f;

    const int stc[4] = {0, 32768, 40960, 43008};
    const int Wc[4]  = {256, 128, 64, 32};
    const int Hc[4]  = {128, 64, 32, 16};
    const uint4* opv = (const uint4*)op;

    #pragma unroll
    for (int l = 0; l < 4; l++) {
        const int W = Wc[l], H = Hc[l], st = stc[l];
        const float Wf = (float)W, Hf = (float)H;
        uint4 o0 = opv[l * 2], o1 = opv[l * 2 + 1];
        uint32_t ow[8] = {o0.x, o0.y, o0.z, o0.w, o1.x, o1.y, o1.z, o1.w};
        #pragma unroll
        for (int p = 0; p < 8; p++) {
            float2 off2 = __half22float2(*(const __half2*)&ow[p]);
            float aw = e[l * 8 + p];
            float x = (rx + off2.x / Wf) * Wf - 0.5f;
            float y = (ry + off2.y / Hf) * Hf - 0.5f;
            float xf = floorf(x), yf = floorf(y);
            int x0 = (int)xf, y0 = (int)yf;
            float fx = x - xf, fy = y - yf;
            float wx[2] = {1.f - fx, fx};
            float wy[2] = {1.f - fy, fy};
            #pragma unroll
            for (int c = 0; c < 4; c++) {
                int xi = x0 + (c & 1), yi = y0 + (c >> 1);
                float wgt = wx[c & 1] * wy[c >> 1];
                if (xi >= 0 && xi < W && yi >= 0 && yi < H && wgt != 0.f) {
                    const uint4* gp = (const uint4*)(VX + ((size_t)(st + yi * W + xi)) * 128 + h * 16);
                    uint4 u0 = gp[0];
                    uint4 u1 = gp[1];
                    uint32_t wv[8] = {u0.x, u0.y, u0.z, u0.w, u1.x, u1.y, u1.z, u1.w};
                    float cw = aw * wgt;
                    #pragma unroll
                    for (int d = 0; d < 8; d++) {
                        float2 g2 = __half22float2(*(const __half2*)&wv[d]);
                        acc[d * 2 + 0] += cw * g2.x;
                        acc[d * 2 + 1] += cw * g2.y;
                    }
                }
            }
        }
    }
    uint32_t ov[8];
    #pragma unroll
    for (int d = 0; d < 8; d++) {
        __half2 h2 = __floats2half2_rn(acc[d * 2], acc[d * 2 + 1]);
        ov[d] = *(uint32_t*)&h2;
    }
    uint4* o = (uint4*)(OX + (size_t)n * 128 + h * 16);
    o[0] = make_uint4(ov[0], ov[1], ov[2], ov[3]);
    o[1] = make_uint4(ov[4], ov[5], ov[6], ov[7]);
}

// ---------------- layernorm: warp-per-row, 8 rows per block ----------------
// MODE: 3 fp32 + fp16(y), 4 fp32 + fp16(y + pos)
template<int MODE>
__global__ void __launch_bounds__(256) ln_kernel(
    const float* __restrict__ X, const float* __restrict__ g,
    const float* __restrict__ b, float* __restrict__ Y,
    __half* __restrict__ Yx, const float* __restrict__ pos)
{
    const int wid = threadIdx.x >> 5, lane = threadIdx.x & 31;
    const int r = blockIdx.x * 8 + wid;
    if (r >= NQ) return;
    const size_t base = (size_t)r * 128 + lane * 4;
    float4 x4 = *(const float4*)&X[base];
    float s = x4.x + x4.y + x4.z + x4.w;
    #pragma unroll
    for (int o = 16; o > 0; o >>= 1) s += __shfl_xor_sync(0xffffffffu, s, o);
    float m = s * (1.f / 128.f);
    float d0 = x4.x - m, d1 = x4.y - m, d2 = x4.z - m, d3 = x4.w - m;
    float q = d0 * d0 + d1 * d1 + d2 * d2 + d3 * d3;
    #pragma unroll
    for (int o = 16; o > 0; o >>= 1) q += __shfl_xor_sync(0xffffffffu, q, o);
    float inv = rsqrtf(q * (1.f / 128.f) + 1e-5f);
    float4 g4 = *(const float4*)&g[lane * 4];
    float4 b4 = *(const float4*)&b[lane * 4];
    float y0 = d0 * inv * g4.x + b4.x;
    float y1 = d1 * inv * g4.y + b4.y;
    float y2 = d2 * inv * g4.z + b4.z;
    float y3 = d3 * inv * g4.w + b4.w;
    *(float4*)&Y[base] = make_float4(y0, y1, y2, y3);
    if (MODE == 4) {
        float4 p4 = *(const float4*)&pos[base];
        y0 += p4.x; y1 += p4.y; y2 += p4.z; y3 += p4.w;
    }
    __half2 h01 = __floats2half2_rn(y0, y1);
    __half2 h23 = __floats2half2_rn(y2, y3);
    *(uint2*)&Yx[base] = make_uint2(*(uint32_t*)&h01, *(uint32_t*)&h23);
}

// ---------------- conv1 (7x7, 128->128) via mma.sync fp16, fused BN stats ----------------
constexpr int ROWB = 144;
constexpr int C1TILE = 128 * ROWB;
constexpr int C1BUF  = 2 * C1TILE;
constexpr int CONV1_SMEM = 2 * C1BUF;

__global__ void __launch_bounds__(256, 2) conv1_f16_kernel(
    const __half* __restrict__ q16, const __half* __restrict__ w16,
    float* __restrict__ Out, float* __restrict__ part)
{
    extern __shared__ char smem[];
    __shared__ float red_s[8][128], red_q[8][128];
    const int tid = threadIdx.x;
    const int wid = tid >> 5, lane = tid & 31;
    const int warp_m = wid >> 2, warp_n = wid & 3;
    const uint32_t sb = smem_u32(smem);
    const int bm = blockIdx.x * 128;

    const int lrow = tid >> 1, lhalf = tid & 1;
    const int pm = bm + lrow;
    const int py = pm / 200, px = pm % 200;
    const bool prow_ok = pm < NQ;
    const uint32_t s_arow = sb + (uint32_t)lrow * ROWB + (uint32_t)lhalf * 64;
    const uint32_t s_brow = s_arow + C1TILE;

    const uint32_t a_base = sb + (uint32_t)(warp_m * 64 + (lane & 15)) * ROWB + (uint32_t)(lane >> 4) * 16;
    const uint32_t b_base = sb + C1TILE + (uint32_t)(warp_n * 32 + (lane & 7)) * ROWB
                          + (uint32_t)((lane >> 3) & 1) * 16;

    float acc[4][4][4];
    #pragma unroll
    for (int mt = 0; mt < 4; mt++)
        #pragma unroll
        for (int nt = 0; nt < 4; nt++)
            #pragma unroll
            for (int d = 0; d < 4; d++) acc[mt][nt][d] = 0.f;

    auto load_chunk = [&](int c, int buf) {
        const int e = c >> 1, ch = c & 1;
        const int qy = py + e / 7 - 3;
        const int qx = px + e % 7 - 3;
        const bool val = prow_ok && qy >= 0 && qy < 200 && qx >= 0 && qx < 200;
        const size_t aoff = (size_t)(val ? (qy * 200 + qx) : 0) * 128 + (size_t)ch * 64 + (size_t)lhalf * 32;
        const char* ag = (const char*)(q16 + aoff);
        const size_t boff = ((size_t)c * 128 + lrow) * 64 + (size_t)lhalf * 32;
        const char* bg = (const char*)(w16 + boff);
        const uint32_t sa = s_arow + (uint32_t)buf * C1BUF;
        const uint32_t sbr = s_brow + (uint32_t)buf * C1BUF;
        #pragma unroll
        for (int i = 0; i < 4; i++) {
            cpasync16(sa + i * 16,  ag + i * 16, val);
            cpasync16(sbr + i * 16, bg + i * 16, true);
        }
    };

    load_chunk(0, 0); cp_commit();
    load_chunk(1, 1); cp_commit();

    for (int c = 0; c < W1CHUNKS; c++) {
        const int buf = c & 1;
        cp_wait1();
        __syncthreads();

        const uint32_t ab = a_base + (uint32_t)buf * C1BUF;
        const uint32_t bb = b_base + (uint32_t)buf * C1BUF;
        #pragma unroll
        for (int ks = 0; ks < 4; ks++) {
            const uint32_t kbyte = (uint32_t)ks * 32;
            uint32_t bfr[4][2];
            #pragma unroll
            for (int nt = 0; nt < 4; nt++)
                ldmx2(bfr[nt], bb + (uint32_t)nt * 8 * ROWB + kbyte);
            #pragma unroll
            for (int mt = 0; mt < 4; mt++) {
                uint32_t afr[4];
                ldmx4(afr, ab + (uint32_t)mt * 16 * ROWB + kbyte);
                #pragma unroll
                for (int nt = 0; nt < 4; nt++)
                    mma_f16(acc[mt][nt], afr, bfr[nt]);
            }
        }
        __syncthreads();
        if (c + 2 < W1CHUNKS) load_chunk(c + 2, buf);
        cp_commit();
    }

    const int g = lane >> 2, tg = lane & 3;
    #pragma unroll
    for (int mt = 0; mt < 4; mt++) {
        const int r0 = bm + warp_m * 64 + mt * 16 + g;
        #pragma unroll
        for (int nt = 0; nt < 4; nt++) {
            const int col = warp_n * 32 + nt * 8 + tg * 2;
            if (r0 < NQ)
                *(float2*)&Out[(size_t)r0 * 128 + col] = make_float2(acc[mt][nt][0], acc[mt][nt][1]);
            if (r0 + 8 < NQ)
                *(float2*)&Out[(size_t)(r0 + 8) * 128 + col] = make_float2(acc[mt][nt][2], acc[mt][nt][3]);
        }
    }

    // fused BN stats
    float cs[8], cq[8];
    #pragma unroll
    for (int nt = 0; nt < 4; nt++)
        #pragma unroll
        for (int j = 0; j < 2; j++) {
            float s = 0.f, q = 0.f;
            #pragma unroll
            for (int mt = 0; mt < 4; mt++) {
                float v0 = acc[mt][nt][j], v1 = acc[mt][nt][2 + j];
                s += v0 + v1; q += v0 * v0 + v1 * v1;
            }
            cs[nt * 2 + j] = s; cq[nt * 2 + j] = q;
        }
    #pragma unroll
    for (int k = 0; k < 8; k++) {
        #pragma unroll
        for (int o = 4; o <= 16; o <<= 1) {
            cs[k] += __shfl_xor_sync(0xffffffffu, cs[k], o);
            cq[k] += __shfl_xor_sync(0xffffffffu, cq[k], o);
        }
    }
    if (lane < 4) {
        #pragma unroll
        for (int nt = 0; nt < 4; nt++)
            #pragma unroll
            for (int j = 0; j < 2; j++) {
                int col = warp_n * 32 + nt * 8 + lane * 2 + j;
                red_s[wid][col] = cs[nt * 2 + j];
                red_q[wid][col] = cq[nt * 2 + j];
            }
    }
    __syncthreads();
    if (tid < 128) {
        int wn = tid >> 5;
        float s = red_s[wn][tid] + red_s[4 + wn][tid];
        float q = red_q[wn][tid] + red_q[4 + wn][tid];
        part[(size_t)blockIdx.x * 256 + tid] = s;
        part[(size_t)blockIdx.x * 256 + 128 + tid] = q;
    }
}

// ---------------- convs 2-4 (3x3) via mma.sync bf16x3, fused BN stats ----------------
constexpr int CATILE = 128 * ROWB;
constexpr int CBTILE = 64 * ROWB;
constexpr int CBUF = 2 * CATILE + 2 * CBTILE;
constexpr int CONV_SMEM = 2 * CBUF;

template<int CHUNKS, int CIN_CH, int CST>
__global__ void __launch_bounds__(256, 2) conv_mma_kernel(
    const __nv_bfloat16* __restrict__ inh, const __nv_bfloat16* __restrict__ inl,
    const __nv_bfloat16* __restrict__ wh, const __nv_bfloat16* __restrict__ wl,
    float* __restrict__ Out, int COUT, float* __restrict__ part)
{
    extern __shared__ char smem[];
    __shared__ float red_s[8][64], red_q[8][64];
    const int tid = threadIdx.x;
    const int wid = tid >> 5, lane = tid & 31;
    const int warp_m = wid >> 1, warp_n = wid & 1;
    const uint32_t sb = smem_u32(smem);
    const int bm = blockIdx.x * 128;

    const int lrow = tid >> 1, lhalf = tid & 1;
    const int pm = bm + lrow;
    const int py = pm / 200, px = pm % 200;
    const bool prow_ok = pm < NQ;
    const uint32_t s_arow = sb + (uint32_t)lrow * ROWB + (uint32_t)lhalf * 64;
    const int brow = tid >> 2, bq = tid & 3;
    const uint32_t s_brow = sb + 2 * CATILE + (uint32_t)brow * ROWB + (uint32_t)bq * 32;

    const uint32_t a_base = sb + (uint32_t)(warp_m * 32 + (lane & 15)) * ROWB + (uint32_t)(lane >> 4) * 16;
    const uint32_t b_base = sb + 2 * CATILE + (uint32_t)(warp_n * 32 + (lane & 7)) * ROWB
                          + (uint32_t)((lane >> 3) & 1) * 16;

    float acc[2][4][4];
    #pragma unroll
    for (int mt = 0; mt < 2; mt++)
        #pragma unroll
        for (int nt = 0; nt < 4; nt++)
            #pragma unroll
            for (int d = 0; d < 4; d++) acc[mt][nt][d] = 0.f;

    auto load_chunk = [&](int c, int buf) {
        const int e = c / CIN_CH, cih = c % CIN_CH;
        const int qy = py + e / 3 - 1;
        const int qx = px + e % 3 - 1;
        const bool val = prow_ok && qy >= 0 && qy < 200 && qx >= 0 && qx < 200;
        const size_t aoff = (size_t)(val ? (qy * 200 + qx) : 0) * CST + (size_t)cih * 64 + (size_t)lhalf * 32;
        const char* agh = (const char*)(inh + aoff);
        const char* agl = (const char*)(inl + aoff);
        const size_t boff = ((size_t)c * 64 + brow) * 64 + (size_t)bq * 16;
        const char* bgh = (const char*)(wh + boff);
        const char* bgl = (const char*)(wl + boff);
        const uint32_t sa = s_arow + (uint32_t)buf * CBUF;
        const uint32_t sbr = s_brow + (uint32_t)buf * CBUF;
        #pragma unroll
        for (int i = 0; i < 4; i++) {
            cpasync16(sa + i * 16,           agh + i * 16, val);
            cpasync16(sa + CATILE + i * 16,  agl + i * 16, val);
        }
        #pragma unroll
        for (int i = 0; i < 2; i++) {
            cpasync16(sbr + i * 16,          bgh + i * 16, true);
            cpasync16(sbr + CBTILE + i * 16, bgl + i * 16, true);
        }
    };

    load_chunk(0, 0); cp_commit();
    load_chunk(1, 1); cp_commit();

    for (int c = 0; c < CHUNKS; c++) {
        const int buf = c & 1;
        cp_wait1();
        __syncthreads();

        const uint32_t ab = a_base + (uint32_t)buf * CBUF;
        const uint32_t bb = b_base + (uint32_t)buf * CBUF;
        #pragma unroll
        for (int ks = 0; ks < 4; ks++) {
            const uint32_t kbyte = (uint32_t)ks * 32;
            uint32_t bh[4][2], bl[4][2];
            #pragma unroll
            for (int nt = 0; nt < 4; nt++) {
                ldmx2(bh[nt], bb + (uint32_t)nt * 8 * ROWB + kbyte);
                ldmx2(bl[nt], bb + CBTILE + (uint32_t)nt * 8 * ROWB + kbyte);
            }
            #pragma unroll
            for (int mt = 0; mt < 2; mt++) {
                uint32_t ah[4], al[4];
                ldmx4(ah, ab + (uint32_t)mt * 16 * ROWB + kbyte);
                ldmx4(al, ab + CATILE + (uint32_t)mt * 16 * ROWB + kbyte);
                #pragma unroll
                for (int nt = 0; nt < 4; nt++) {
                    mma_bf16(acc[mt][nt], ah, bh[nt]);
                    mma_bf16(acc[mt][nt], ah, bl[nt]);
                    mma_bf16(acc[mt][nt], al, bh[nt]);
                }
            }
        }
        __syncthreads();
        if (c + 2 < CHUNKS) load_chunk(c + 2, buf);
        cp_commit();
    }

    const int g = lane >> 2, tg = lane & 3;
    #pragma unroll
    for (int mt = 0; mt < 2; mt++) {
        const int r0 = bm + warp_m * 32 + mt * 16 + g;
        #pragma unroll
        for (int nt = 0; nt < 4; nt++) {
            const int col = warp_n * 32 + nt * 8 + tg * 2;
            if (col >= COUT) continue;
            if (r0 < NQ)
                *(float2*)&Out[(size_t)r0 * COUT + col] = make_float2(acc[mt][nt][0], acc[mt][nt][1]);
            if (r0 + 8 < NQ)
                *(float2*)&Out[(size_t)(r0 + 8) * COUT + col] = make_float2(acc[mt][nt][2], acc[mt][nt][3]);
        }
    }

    // fused BN stats
    float cs[8], cq[8];
    #pragma unroll
    for (int nt = 0; nt < 4; nt++)
        #pragma unroll
        for (int j = 0; j < 2; j++) {
            float s = 0.f, q = 0.f;
            #pragma unroll
            for (int mt = 0; mt < 2; mt++) {
                float v0 = acc[mt][nt][j], v1 = acc[mt][nt][2 + j];
                s += v0 + v1; q += v0 * v0 + v1 * v1;
            }
            cs[nt * 2 + j] = s; cq[nt * 2 + j] = q;
        }
    #pragma unroll
    for (int k = 0; k < 8; k++) {
        #pragma unroll
        for (int o = 4; o <= 16; o <<= 1) {
            cs[k] += __shfl_xor_sync(0xffffffffu, cs[k], o);
            cq[k] += __shfl_xor_sync(0xffffffffu, cq[k], o);
        }
    }
    if (lane < 4) {
        #pragma unroll
        for (int nt = 0; nt < 4; nt++)
            #pragma unroll
            for (int j = 0; j < 2; j++) {
                int col = warp_n * 32 + nt * 8 + lane * 2 + j;
                red_s[wid][col] = cs[nt * 2 + j];
                red_q[wid][col] = cq[nt * 2 + j];
            }
    }
    __syncthreads();
    if (tid < COUT) {
        int wn = tid >> 5;
        float s = 0.f, q = 0.f;
        #pragma unroll
        for (int wm = 0; wm < 4; wm++) {
            s += red_s[wm * 2 + wn][tid];
            q += red_q[wm * 2 + wn][tid];
        }
        part[(size_t)blockIdx.x * 2 * COUT + tid] = s;
        part[(size_t)blockIdx.x * 2 * COUT + COUT + tid] = q;
    }
}

// ---------------- batchnorm finalize (sums NBLK per-block partials) ----------------
__global__ void bn_finalize_kernel(const float* __restrict__ part,
                                   const float* __restrict__ gamma, const float* __restrict__ beta,
                                   float* __restrict__ scale, float* __restrict__ shift, int C)
{
    int c = threadIdx.x;
    float s = 0.f, q = 0.f;
    for (int g = 0; g < NBLK; g++) {
        s += part[(size_t)g * 2 * C + c];
        q += part[(size_t)g * 2 * C + C + c];
    }
    const float invP = 1.f / (float)NQ;
    float m = s * invP;
    float v = q * invP - m * m;
    float sc = gamma[c] * rsqrtf(v + 1e-5f);
    scale[c] = sc;
    shift[c] = beta[c] - m * sc;
}

__global__ void bn_apply_split_kernel(const float* __restrict__ X, const float* __restrict__ scale,
                                      const float* __restrict__ shift,
                                      __nv_bfloat16* __restrict__ hi, __nv_bfloat16* __restrict__ lo,
                                      int C, int CST, int total)
{
    int i = blockIdx.x * blockDim.x + threadIdx.x;
    if (i >= total) return;
    int c = i % CST;
    int p = i / CST;
    float v = 0.f;
    if (c < C) v = fmaxf(0.f, fmaf(X[(size_t)p * C + c], scale[c], shift[c]));
    split2(v, hi[i], lo[i]);
}

// ---------------- head: fused BN4+ReLU + 1x1 conv 48 -> 21, output NCHW ----------------
__global__ void head_conv_kernel(const float* __restrict__ H4raw, const float* __restrict__ scale,
                                 const float* __restrict__ shift,
                                 const float* __restrict__ Wo, const float* __restrict__ bo,
                                 float* __restrict__ out)
{
    int p = blockIdx.x * blockDim.x + threadIdx.x;
    if (p >= NQ) return;
    float x[48];
    const float4* hp = (const float4*)(H4raw + (size_t)p * 48);
    #pragma unroll
    for (int i = 0; i < 12; i++) {
        float4 v = hp[i];
        x[i * 4 + 0] = v.x; x[i * 4 + 1] = v.y; x[i * 4 + 2] = v.z; x[i * 4 + 3] = v.w;
    }
    #pragma unroll
    for (int ci = 0; ci < 48; ci++)
        x[ci] = fmaxf(0.f, fmaf(x[ci], scale[ci], shift[ci]));
    for (int co = 0; co < 21; co++) {
        float s = bo[co];
        const float* w = Wo + co * 48;
        #pragma unroll
        for (int ci = 0; ci < 48; ci++) s = fmaf(x[ci], w[ci], s);
        out[(size_t)co * NQ + p] = s;
    }
}

// ---------------- launch ----------------
extern "C" void kernel_launch(void* const* d_in, const int* in_sizes, int n_in,
                              void* d_out, int out_size)
{
    const float* value = (const float*)d_in[0];
    const float* bq    = (const float*)d_in[1];
    const float* bpos  = (const float*)d_in[2];
    const int*   proj  = (const int*)d_in[3];
    const float* Wv    = (const float*)d_in[4];
    const float* bv    = (const float*)d_in[5];
    const float* Woff  = (const float*)d_in[6];
    const float* boff  = (const float*)d_in[7];
    const float* Wattn = (const float*)d_in[8];
    const float* battn = (const float*)d_in[9];
    const float* Wout  = (const float*)d_in[10];
    const float* bout  = (const float*)d_in[11];
    const float* Wf1   = (const float*)d_in[12];
    const float* bf1   = (const float*)d_in[13];
    const float* Wf2   = (const float*)d_in[14];
    const float* bf2   = (const float*)d_in[15];
    const float* lng   = (const float*)d_in[16];
    const float* lnb   = (const float*)d_in[17];
    const float* cw1   = (const float*)d_in[18];
    const float* g1    = (const float*)d_in[19];
    const float* b1    = (const float*)d_in[20];
    const float* cw2   = (const float*)d_in[21];
    const float* g2    = (const float*)d_in[22];
    const float* b2    = (const float*)d_in[23];
    const float* cw3   = (const float*)d_in[24];
    const float* g3    = (const float*)d_in[25];
    const float* b3    = (const float*)d_in[26];
    const float* cw4   = (const float*)d_in[27];
    const float* g4    = (const float*)d_in[28];
    const float* b4    = (const float*)d_in[29];
    const float* objw  = (const float*)d_in[30];
    const float* objb  = (const float*)d_in[31];
    float* out = (float*)d_out;

    float* S = nullptr;
    cudaGetSymbolAddress((void**)&S, g_scratch);
    int* gm = nullptr;
    cudaGetSymbolAddress((void**)&gm, g_maxv);
    __nv_bfloat16 *s1h, *s1l, *s2h, *s2l, *wch, *wcl;
    __half *vx, *vin16, *q16, *qp16, *w16, *wf16, *oa16;
    cudaGetSymbolAddress((void**)&s1h, g_s1h);
    cudaGetSymbolAddress((void**)&s1l, g_s1l);
    cudaGetSymbolAddress((void**)&s2h, g_s2h);
    cudaGetSymbolAddress((void**)&s2l, g_s2l);
    cudaGetSymbolAddress((void**)&vx,  g_vx);
    cudaGetSymbolAddress((void**)&vin16, g_vin16);
    cudaGetSymbolAddress((void**)&q16, g_q16);
    cudaGetSymbolAddress((void**)&qp16, g_qp16);
    cudaGetSymbolAddress((void**)&w16, g_w16);
    cudaGetSymbolAddress((void**)&wf16, g_wf16);
    cudaGetSymbolAddress((void**)&oa16, g_oa16);
    cudaGetSymbolAddress((void**)&wch, g_wch);
    cudaGetSymbolAddress((void**)&wcl, g_wcl);

    float* PQ    = S + OFF_Q;
    float* PT1   = S + OFF_T1;
    float* PT2   = S + OFF_T2;
    float* PH1   = S + OFF_H1;
    float* PH2   = S + OFF_H2;
    float* PH3   = S + OFF_H3;
    float* PH4   = S + OFF_H4;
    float* PPART = S + OFF_PART;
    float* PSCALE= S + OFF_SCALE;
    float* PSHIFT= S + OFF_SHIFT;
    float* PBIAS = S + OFF_BIAS;

    cudaFuncSetAttribute(conv1_f16_kernel, cudaFuncAttributeMaxDynamicSharedMemorySize, CONV1_SMEM);
    cudaFuncSetAttribute(gemm_f16<8>,    cudaFuncAttributeMaxDynamicSharedMemorySize, F16GEMM_SMEM);
    cudaFuncSetAttribute(gemm_f16<9>,    cudaFuncAttributeMaxDynamicSharedMemorySize, F16GEMM_SMEM);
    cudaFuncSetAttribute(gemm_f16<6>,    cudaFuncAttributeMaxDynamicSharedMemorySize, F16GEMM_SMEM);
    cudaFuncSetAttribute((conv_mma_kernel<18, 2, 128>), cudaFuncAttributeMaxDynamicSharedMemorySize, CONV_SMEM);
    cudaFuncSetAttribute((conv_mma_kernel<9, 1, 64>),   cudaFuncAttributeMaxDynamicSharedMemorySize, CONV_SMEM);

    // --- observed_masks ---
    init_max_kernel<<<1, 1>>>(gm);
    reduce_max_kernel<<<40, 256>>>(proj, gm);
    write_mask_kernel<<<(NQ + 255) / 256, 256>>>(proj, gm, out + 21 * NQ);

    // --- fused weight prep + value fp16 (single launch) ---
    prep_kernel<<<(Q10 + 255) / 256, 256>>>(cw1, cw2, cw3, cw4, Woff, Wattn, Wv, Wf1, Wf2, Wout,
                                            boff, battn, value,
                                            w16, wch, wcl, wf16, PBIAS, vin16);

    // --- q init ---
    cudaMemcpyAsync(PQ, bq, (size_t)NQ * ED * sizeof(float), cudaMemcpyDeviceToDevice);

    // --- 2 encoder layers ---
    add_f16_kernel<<<(NQ * ED + 255) / 256, 256>>>(PQ, bpos, qp16, NQ * ED);
    for (int i = 0; i < 2; i++) {
        size_t LW = (size_t)i * WFL;
        gemm_f16<8><<<dim3(340, 1), 256, F16GEMM_SMEM>>>(vin16, wf16 + LW + 768 * 128,
                                                         bv + i * 128, nullptr, nullptr, vx, NV, 128);
        gemm_f16<8><<<dim3(313, 6), 256, F16GEMM_SMEM>>>(qp16, wf16 + LW,
                                                         PBIAS + i * 768, nullptr, nullptr, oa16, NQ, 768);
        deform_kernel<<<(NQ * HEADS + 255) / 256, 256>>>(vx, oa16, q16);
        // Wout fp16 + residual -> PT1
        gemm_f16<6><<<dim3(313, 1), 256, F16GEMM_SMEM>>>(q16, wf16 + LW + 1152 * 128,
                                                         bout + i * 128, PQ, PT1, nullptr, NQ, 128);
        ln_kernel<3><<<(NQ + 7) / 8, 256>>>(PT1, lng + (i * 2 + 0) * 128, lnb + (i * 2 + 0) * 128, PQ, q16, nullptr);
        gemm_f16<9><<<dim3(313, 1), 256, F16GEMM_SMEM>>>(q16, wf16 + LW + 896 * 128,
                                                         bf1 + i * 128, nullptr, nullptr, qp16, NQ, 128);
        gemm_f16<6><<<dim3(313, 1), 256, F16GEMM_SMEM>>>(qp16, wf16 + LW + 1024 * 128,
                                                         bf2 + i * 128, PQ, PT2, nullptr, NQ, 128);
        if (i == 0)
            ln_kernel<4><<<(NQ + 7) / 8, 256>>>(PT2, lng + 1 * 128, lnb + 1 * 128, PQ, qp16, bpos);   // fp16(q+pos)
        else
            ln_kernel<3><<<(NQ + 7) / 8, 256>>>(PT2, lng + 3 * 128, lnb + 3 * 128, PQ, q16, nullptr); // fp16(q)
    }

    // --- conv head (BN stats fused into conv epilogues) ---
    conv1_f16_kernel<<<NBLK, 256, CONV1_SMEM>>>(q16, w16, PH1, PPART);
    bn_finalize_kernel<<<1, 128>>>(PPART, g1, b1, PSCALE, PSHIFT, 128);
    bn_apply_split_kernel<<<(NQ * 128 + 255) / 256, 256>>>(PH1, PSCALE, PSHIFT, s1h, s1l, 128, 128, NQ * 128);

    conv_mma_kernel<18, 2, 128><<<NBLK, 256, CONV_SMEM>>>(s1h, s1l, wch + WC2_OFF, wcl + WC2_OFF, PH2, 64, PPART);
    bn_finalize_kernel<<<1, 64>>>(PPART, g2, b2, PSCALE, PSHIFT, 64);
    bn_apply_split_kernel<<<(NQ * 64 + 255) / 256, 256>>>(PH2, PSCALE, PSHIFT, s2h, s2l, 64, 64, NQ * 64);

    conv_mma_kernel<9, 1, 64><<<NBLK, 256, CONV_SMEM>>>(s2h, s2l, wch + WC3_OFF, wcl + WC3_OFF, PH3, 48, PPART);
    bn_finalize_kernel<<<1, 48>>>(PPART, g3, b3, PSCALE, PSHIFT, 48);
    bn_apply_split_kernel<<<(NQ * 64 + 255) / 256, 256>>>(PH3, PSCALE, PSHIFT, s1h, s1l, 48, 64, NQ * 64);

    conv_mma_kernel<9, 1, 64><<<NBLK, 256, CONV_SMEM>>>(s1h, s1l, wch + WC4_OFF, wcl + WC4_OFF, PH4, 48, PPART);
    bn_finalize_kernel<<<1, 48>>>(PPART, g4, b4, PSCALE, PSHIFT, 48);
    head_conv_kernel<<<(NQ + 255) / 256, 256>>>(PH4, PSCALE, PSHIFT, objw, objb, out);
}

// round 16
// speedup vs baseline: 3.5366x; 1.0199x over previous
#include <cuda_runtime.h>
#include <cuda_bf16.h>
#include <cuda_fp16.h>
#include <cstdint>
#include <climits>

// ---------------- problem constants ----------------
constexpr int NQ = 40000;        // 200*200
constexpr int ED = 128;
constexpr int NV = 43520;        // sum of level sizes
constexpr int HEADS = 8;
constexpr int NBLK = 313;        // conv blocks = bn partials
constexpr int NMAXB = 40;        // max-reduction partial blocks

// ---------------- scratch layout (floats) ----------------
constexpr size_t OFF_Q    = 0;
constexpr size_t SZ_Q     = (size_t)NQ * ED;
constexpr size_t OFF_T1   = OFF_Q + SZ_Q;
constexpr size_t OFF_T2   = OFF_T1 + SZ_Q;
constexpr size_t OFF_H1   = OFF_T2 + SZ_Q;
constexpr size_t SZ_H1    = (size_t)NQ * 128;
constexpr size_t OFF_H2   = OFF_H1 + SZ_H1;
constexpr size_t SZ_H2    = (size_t)NQ * 64;
constexpr size_t OFF_H3   = OFF_H2 + SZ_H2;
constexpr size_t SZ_H3    = (size_t)NQ * 48;
constexpr size_t OFF_H4   = OFF_H3 + SZ_H3;
constexpr size_t OFF_PART = OFF_H4 + SZ_H3;
constexpr size_t SZ_PART  = (size_t)NBLK * 2 * 128 + 256;
constexpr size_t OFF_SCALE= OFF_PART + SZ_PART;
constexpr size_t OFF_SHIFT= OFF_SCALE + 128;
constexpr size_t OFF_BIAS = OFF_SHIFT + 128;       // 2 layers x 768 packed bias
constexpr size_t SCRATCH_TOTAL = OFF_BIAS + 2 * 768;

__device__ float g_scratch[SCRATCH_TOTAL];
__device__ int   g_pmax[NMAXB];

// ---------------- bf16 / fp16 buffers ----------------
constexpr int W1CHUNKS = 98;                 // conv1: 49 taps * 2 ci-halves
__device__ __align__(16) __nv_bfloat16 g_s1h[(size_t)NQ * 128];
__device__ __align__(16) __nv_bfloat16 g_s1l[(size_t)NQ * 128];
__device__ __align__(16) __nv_bfloat16 g_s2h[(size_t)NQ * 128];
__device__ __align__(16) __nv_bfloat16 g_s2l[(size_t)NQ * 128];
__device__ __align__(16) __half        g_vx[(size_t)NV * 128];    // fp16 V for deform
__device__ __align__(16) __half        g_vin16[(size_t)NV * 128]; // fp16 value input
__device__ __align__(16) __half        g_q16[(size_t)NQ * 128];   // fp16 scratch (deform out / LN out)
__device__ __align__(16) __half        g_qp16[(size_t)NQ * 128];  // fp16 scratch
__device__ __align__(16) __half        g_oa16[(size_t)NQ * 768];  // fp16 offsets+logits
// fp16 weights per layer: [OA 768][Wv 128][Wf1 128][Wf2 128][Wout 128] x 128 k
constexpr int WFL = 1280 * 128;              // per-layer stride
__device__ __align__(16) __half g_wf16[(size_t)2 * WFL];
// conv1 weights [chunk][co 128][k 64] fp16
__device__ __align__(16) __half g_w16[(size_t)W1CHUNKS * 128 * 64];
// convs 2-4 bf16 split weights
constexpr int WC2_OFF = 0, WC3_OFF = 73728, WC4_OFF = 110592, WC_TOTAL = 147456;
__device__ __align__(16) __nv_bfloat16 g_wch[WC_TOTAL];
__device__ __align__(16) __nv_bfloat16 g_wcl[WC_TOTAL];

// ---------------- small helpers ----------------
__device__ __forceinline__ uint32_t smem_u32(const void* p) {
    return (uint32_t)__cvta_generic_to_shared(p);
}
__device__ __forceinline__ void cpasync16(uint32_t dst, const void* src, bool valid) {
    asm volatile("cp.async.cg.shared.global [%0], [%1], 16, %2;"
                 :: "r"(dst), "l"(src), "r"(valid ? 16u : 0u));
}
__device__ __forceinline__ void cp_commit() { asm volatile("cp.async.commit_group;"); }
__device__ __forceinline__ void cp_wait1()  { asm volatile("cp.async.wait_group 1;"); }
__device__ __forceinline__ void cp_wait0()  { asm volatile("cp.async.wait_group 0;"); }

__device__ __forceinline__ void ldmx4(uint32_t* r, uint32_t addr) {
    asm volatile("ldmatrix.sync.aligned.m8n8.x4.shared.b16 {%0,%1,%2,%3}, [%4];"
                 : "=r"(r[0]), "=r"(r[1]), "=r"(r[2]), "=r"(r[3]) : "r"(addr));
}
__device__ __forceinline__ void ldmx2(uint32_t* r, uint32_t addr) {
    asm volatile("ldmatrix.sync.aligned.m8n8.x2.shared.b16 {%0,%1}, [%2];"
                 : "=r"(r[0]), "=r"(r[1]) : "r"(addr));
}
__device__ __forceinline__ void mma_bf16(float* c, const uint32_t* a, const uint32_t* b) {
    asm volatile("mma.sync.aligned.m16n8k16.row.col.f32.bf16.bf16.f32 "
                 "{%0,%1,%2,%3}, {%4,%5,%6,%7}, {%8,%9}, {%0,%1,%2,%3};"
                 : "+f"(c[0]), "+f"(c[1]), "+f"(c[2]), "+f"(c[3])
                 : "r"(a[0]), "r"(a[1]), "r"(a[2]), "r"(a[3]), "r"(b[0]), "r"(b[1]));
}
__device__ __forceinline__ void mma_f16(float* c, const uint32_t* a, const uint32_t* b) {
    asm volatile("mma.sync.aligned.m16n8k16.row.col.f32.f16.f16.f32 "
                 "{%0,%1,%2,%3}, {%4,%5,%6,%7}, {%8,%9}, {%0,%1,%2,%3};"
                 : "+f"(c[0]), "+f"(c[1]), "+f"(c[2]), "+f"(c[3])
                 : "r"(a[0]), "r"(a[1]), "r"(a[2]), "r"(a[3]), "r"(b[0]), "r"(b[1]));
}
__device__ __forceinline__ void split2(float v, __nv_bfloat16& h, __nv_bfloat16& l) {
    h = __float2bfloat16(v);
    l = __float2bfloat16(v - __bfloat162float(h));
}

// ---------------- observed_masks: 2-launch deterministic max + mask ----------------
__global__ void reduce_max_part_kernel(const int* __restrict__ p, int* __restrict__ pm) {
    int v = INT_MIN;
    for (int k = blockIdx.x * blockDim.x + threadIdx.x; k < NQ; k += gridDim.x * blockDim.x)
        v = max(v, p[k]);
    #pragma unroll
    for (int o = 16; o > 0; o >>= 1) v = max(v, __shfl_xor_sync(0xffffffffu, v, o));
    __shared__ int sm[8];
    int w = threadIdx.x >> 5;
    if ((threadIdx.x & 31) == 0) sm[w] = v;
    __syncthreads();
    if (threadIdx.x == 0) {
        int bv = sm[0];
        for (int i = 1; i < (int)(blockDim.x >> 5); i++) bv = max(bv, sm[i]);
        pm[blockIdx.x] = bv;
    }
}

__global__ void write_mask_kernel(const int* __restrict__ p, const int* __restrict__ pm,
                                  float* __restrict__ out) {
    __shared__ int sm;
    if (threadIdx.x == 0) {
        int v = INT_MIN;
        #pragma unroll
        for (int g = 0; g < NMAXB; g++) v = max(v, pm[g]);
        sm = v;
    }
    __syncthreads();
    int i = blockIdx.x * blockDim.x + threadIdx.x;
    if (i < NQ) out[i] = (p[i] < sm) ? 1.0f : 0.0f;
}

// q+pos -> fp16, 4-wide
__global__ void add_f16_kernel(const float* __restrict__ A, const float* __restrict__ B,
                               __half* __restrict__ o, int n4)
{
    int i = blockIdx.x * blockDim.x + threadIdx.x;
    if (i >= n4) return;
    int idx = i * 4;
    float4 a = *(const float4*)&A[idx];
    float4 b = *(const float4*)&B[idx];
    __half2 h01 = __floats2half2_rn(a.x + b.x, a.y + b.y);
    __half2 h23 = __floats2half2_rn(a.z + b.z, a.w + b.w);
    *(uint2*)&o[idx] = make_uint2(*(uint32_t*)&h01, *(uint32_t*)&h23);
}

// ---------------- fused weight prep + value fp16: one launch ----------------
constexpr int Q0 = 802816;            // conv1 fp16 [chunk][co][k]
constexpr int Q1 = Q0 + 73728;        // conv2 bf16 split
constexpr int Q2 = Q1 + 36864;        // conv3 bf16 split
constexpr int Q3 = Q2 + 36864;        // conv4 bf16 split
constexpr int Q4 = Q3 + 2 * 98304;    // OA fp16 (Woff|Wattn), both layers
constexpr int Q5 = Q4 + 2 * 16384;    // Wv fp16
constexpr int Q6 = Q5 + 2 * 16384;    // Wf1 fp16
constexpr int Q7 = Q6 + 2 * 16384;    // Wf2 fp16
constexpr int Q8 = Q7 + 2 * 16384;    // Wout fp16
constexpr int Q9 = Q8 + 2 * 768;      // bias pack
constexpr int Q10 = Q9 + NV * 128;    // value -> fp16

__global__ void prep_kernel(
    const float* __restrict__ cw1, const float* __restrict__ cw2,
    const float* __restrict__ cw3, const float* __restrict__ cw4,
    const float* __restrict__ Woff, const float* __restrict__ Wattn,
    const float* __restrict__ Wv, const float* __restrict__ Wf1,
    const float* __restrict__ Wf2, const float* __restrict__ Wout,
    const float* __restrict__ boff, const float* __restrict__ battn,
    const float* __restrict__ value,
    __half* __restrict__ w16, __nv_bfloat16* __restrict__ wch, __nv_bfloat16* __restrict__ wcl,
    __half* __restrict__ wf16,
    float* __restrict__ bias_out, __half* __restrict__ vin16)
{
    int i = blockIdx.x * blockDim.x + threadIdx.x;
    if (i >= Q10) return;
    if (i < Q0) {
        int k = i & 63, co = (i >> 6) & 127, c = i >> 13;
        int e = c >> 1, ci = ((c & 1) << 6) + k;
        w16[i] = __float2half_rn(cw1[(((size_t)co * 128 + ci) * 7 + e / 7) * 7 + e % 7]);
    } else if (i < Q3) {
        const float* W; int CO, CI, CIN_CH, base, j;
        if (i < Q1)      { j = i - Q0; W = cw2; CO = 64; CI = 128; CIN_CH = 2; base = WC2_OFF; }
        else if (i < Q2) { j = i - Q1; W = cw3; CO = 48; CI = 64;  CIN_CH = 1; base = WC3_OFF; }
        else             { j = i - Q2; W = cw4; CO = 48; CI = 48;  CIN_CH = 1; base = WC4_OFF; }
        int k = j & 63, co = (j >> 6) & 63, c = j >> 12;
        int e = c / CIN_CH, ci = (c % CIN_CH) * 64 + k;
        float v = (co < CO && ci < CI) ? W[(((size_t)co * CI + ci) * 3 + e / 3) * 3 + e % 3] : 0.f;
        split2(v, wch[base + j], wcl[base + j]);
    } else if (i < Q4) {
        int j = i - Q3, l = j / 98304, r = j % 98304;
        int n = r >> 7, k = r & 127;
        float v = (n < 512) ? Woff[((size_t)l * 128 + k) * 512 + n]
                            : Wattn[((size_t)l * 128 + k) * 256 + (n - 512)];
        wf16[(size_t)l * WFL + r] = __float2half_rn(v);
    } else if (i < Q8) {
        const float* W; int off, j;
        if (i < Q5)      { j = i - Q4; W = Wv;   off = 768 * 128; }
        else if (i < Q6) { j = i - Q5; W = Wf1;  off = 896 * 128; }
        else if (i < Q7) { j = i - Q6; W = Wf2;  off = 1024 * 128; }
        else             { j = i - Q7; W = Wout; off = 1152 * 128; }
        int l = j >> 14, r = j & 16383;
        int n = r >> 7, k = r & 127;
        wf16[(size_t)l * WFL + off + r] = __float2half_rn(W[((size_t)l * 128 + k) * 128 + n]);
    } else if (i < Q9) {
        int j = i - Q8, l = j / 768, n = j % 768;
        bias_out[(size_t)l * 768 + n] = (n < 512) ? boff[(size_t)l * 512 + n] : battn[(size_t)l * 256 + n - 512];
    } else {
        int j = i - Q9;
        vin16[j] = __float2half_rn(value[j]);
    }
}

// ---------------- fp16 single GEMM ----------------
// FLAGS: 1 relu, 2 residual (fp32 R), 4 fp32 out, 8 fp16 out
constexpr int GROWB = 272;
constexpr int GTILE = 128 * GROWB;
constexpr int F16GEMM_SMEM = 2 * GTILE;

template<int FLAGS>
__global__ void __launch_bounds__(256, 2) gemm_f16(
    const __half* __restrict__ A, const __half* __restrict__ B,
    const float* __restrict__ bias, const float* __restrict__ R,
    float* __restrict__ Cf, __half* __restrict__ Cx, int M, int N)
{
    extern __shared__ char smem[];
    const int tid = threadIdx.x;
    const int wid = tid >> 5, lane = tid & 31;
    const int warp_m = wid >> 2, warp_n = wid & 3;
    const uint32_t sb = smem_u32(smem);
    const int bm = blockIdx.x * 128, bn = blockIdx.y * 128;

    {
        const int lrow = tid >> 1, lhalf = tid & 1;
        const bool aval = (bm + lrow) < M;
        const uint32_t sa = sb + (uint32_t)lrow * GROWB + (uint32_t)lhalf * 128;
        const char* ag = (const char*)(A + (size_t)(aval ? (bm + lrow) : 0) * 128 + lhalf * 64);
        const char* bg = (const char*)(B + (size_t)(bn + lrow) * 128 + lhalf * 64);
        #pragma unroll
        for (int i = 0; i < 8; i++) {
            cpasync16(sa + i * 16,         ag + i * 16, aval);
            cpasync16(sa + GTILE + i * 16, bg + i * 16, true);
        }
        cp_commit();
        cp_wait0();
        __syncthreads();
    }

    float acc[4][4][4];
    #pragma unroll
    for (int mt = 0; mt < 4; mt++)
        #pragma unroll
        for (int nt = 0; nt < 4; nt++)
            #pragma unroll
            for (int d = 0; d < 4; d++) acc[mt][nt][d] = 0.f;

    const uint32_t a_base = sb + (uint32_t)(warp_m * 64 + (lane & 15)) * GROWB + (uint32_t)(lane >> 4) * 16;
    const uint32_t b_base = sb + GTILE + (uint32_t)(warp_n * 32 + (lane & 7)) * GROWB
                          + (uint32_t)((lane >> 3) & 1) * 16;

    #pragma unroll
    for (int ks = 0; ks < 8; ks++) {
        const uint32_t kbyte = (uint32_t)ks * 32;
        uint32_t bfr[4][2];
        #pragma unroll
        for (int nt = 0; nt < 4; nt++)
            ldmx2(bfr[nt], b_base + (uint32_t)nt * 8 * GROWB + kbyte);
        #pragma unroll
        for (int mt = 0; mt < 4; mt++) {
            uint32_t afr[4];
            ldmx4(afr, a_base + (uint32_t)mt * 16 * GROWB + kbyte);
            #pragma unroll
            for (int nt = 0; nt < 4; nt++)
                mma_f16(acc[mt][nt], afr, bfr[nt]);
        }
    }

    const int g = lane >> 2, tg = lane & 3;
    #pragma unroll
    for (int mt = 0; mt < 4; mt++) {
        const int r0 = bm + warp_m * 64 + mt * 16 + g;
        #pragma unroll
        for (int nt = 0; nt < 4; nt++) {
            const int col = bn + warp_n * 32 + nt * 8 + tg * 2;
            float2 bb = *(const float2*)&bias[col];
            #pragma unroll
            for (int half = 0; half < 2; half++) {
                const int r = r0 + half * 8;
                if (r >= M) continue;
                float a0 = acc[mt][nt][half * 2] + bb.x;
                float a1 = acc[mt][nt][half * 2 + 1] + bb.y;
                if (FLAGS & 2) {
                    float2 rr = *(const float2*)&R[(size_t)r * N + col];
                    a0 += rr.x; a1 += rr.y;
                }
                if (FLAGS & 1) { a0 = fmaxf(a0, 0.f); a1 = fmaxf(a1, 0.f); }
                if (FLAGS & 4)
                    *(float2*)&Cf[(size_t)r * N + col] = make_float2(a0, a1);
                if (FLAGS & 8)
                    *(__half2*)&Cx[(size_t)r * N + col] = __floats2half2_rn(a0, a1);
            }
        }
    }
}

// ---------------- deformable attention sampling (fp16 V + fp16 OA, fp16 out) ----------------
__global__ void __launch_bounds__(256) deform_kernel(
    const __half* __restrict__ VX, const __half* __restrict__ OA,
    __half* __restrict__ OX)
{
    int t = blockIdx.x * 256 + threadIdx.x;
    if (t >= NQ * HEADS) return;
    const int n = t >> 3, h = t & 7;
    const float rx = ((float)(n % 200) + 0.5f) * (1.f / 200.f);
    const float ry = ((float)(n / 200) + 0.5f) * (1.f / 200.f);
    const __half* op = OA + (size_t)n * 768 + h * 64;
    const __half* ap = OA + (size_t)n * 768 + 512 + h * 32;

    float e[32];
    {
        const uint4* apv = (const uint4*)ap;
        #pragma unroll
        for (int q = 0; q < 4; q++) {
            uint4 u = apv[q];
            uint32_t wv[4] = {u.x, u.y, u.z, u.w};
            #pragma unroll
            for (int d = 0; d < 4; d++) {
                float2 f2 = __half22float2(*(const __half2*)&wv[d]);
                e[q * 8 + d * 2 + 0] = f2.x;
                e[q * 8 + d * 2 + 1] = f2.y;
            }
        }
        float m = -1e30f;
        #pragma unroll
        for (int k = 0; k < 32; k++) m = fmaxf(m, e[k]);
        float s = 0.f;
        #pragma unroll
        for (int k = 0; k < 32; k++) { e[k] = expf(e[k] - m); s += e[k]; }
        float inv = 1.f / s;
        #pragma unroll
        for (int k = 0; k < 32; k++) e[k] *= inv;
    }

    float acc[16];
    #pragma unroll
    for (int d = 0; d < 16; d++) acc[d] = 0.f;

    const int stc[4] = {0, 32768, 40960, 43008};
    const int Wc[4]  = {256, 128, 64, 32};
    const int Hc[4]  = {128, 64, 32, 16};
    const uint4* opv = (const uint4*)op;

    #pragma unroll
    for (int l = 0; l < 4; l++) {
        const int W = Wc[l], H = Hc[l], st = stc[l];
        const float Wf = (float)W, Hf = (float)H;
        uint4 o0 = opv[l * 2], o1 = opv[l * 2 + 1];
        uint32_t ow[8] = {o0.x, o0.y, o0.z, o0.w, o1.x, o1.y, o1.z, o1.w};
        #pragma unroll
        for (int p = 0; p < 8; p++) {
            float2 off2 = __half22float2(*(const __half2*)&ow[p]);
            float aw = e[l * 8 + p];
            float x = (rx + off2.x / Wf) * Wf - 0.5f;
            float y = (ry + off2.y / Hf) * Hf - 0.5f;
            float xf = floorf(x), yf = floorf(y);
            int x0 = (int)xf, y0 = (int)yf;
            float fx = x - xf, fy = y - yf;
            float wx[2] = {1.f - fx, fx};
            float wy[2] = {1.f - fy, fy};
            #pragma unroll
            for (int c = 0; c < 4; c++) {
                int xi = x0 + (c & 1), yi = y0 + (c >> 1);
                float wgt = wx[c & 1] * wy[c >> 1];
                if (xi >= 0 && xi < W && yi >= 0 && yi < H && wgt != 0.f) {
                    const uint4* gp = (const uint4*)(VX + ((size_t)(st + yi * W + xi)) * 128 + h * 16);
                    uint4 u0 = gp[0];
                    uint4 u1 = gp[1];
                    uint32_t wv[8] = {u0.x, u0.y, u0.z, u0.w, u1.x, u1.y, u1.z, u1.w};
                    float cw = aw * wgt;
                    #pragma unroll
                    for (int d = 0; d < 8; d++) {
                        float2 g2 = __half22float2(*(const __half2*)&wv[d]);
                        acc[d * 2 + 0] += cw * g2.x;
                        acc[d * 2 + 1] += cw * g2.y;
                    }
                }
            }
        }
    }
    uint32_t ov[8];
    #pragma unroll
    for (int d = 0; d < 8; d++) {
        __half2 h2 = __floats2half2_rn(acc[d * 2], acc[d * 2 + 1]);
        ov[d] = *(uint32_t*)&h2;
    }
    uint4* o = (uint4*)(OX + (size_t)n * 128 + h * 16);
    o[0] = make_uint4(ov[0], ov[1], ov[2], ov[3]);
    o[1] = make_uint4(ov[4], ov[5], ov[6], ov[7]);
}

// ---------------- layernorm: warp-per-row, 8 rows per block ----------------
// MODE: 3 fp32 + fp16(y), 4 fp32 + fp16(y + pos), 5 fp16(y) only
template<int MODE>
__global__ void __launch_bounds__(256) ln_kernel(
    const float* __restrict__ X, const float* __restrict__ g,
    const float* __restrict__ b, float* __restrict__ Y,
    __half* __restrict__ Yx, const float* __restrict__ pos)
{
    const int wid = threadIdx.x >> 5, lane = threadIdx.x & 31;
    const int r = blockIdx.x * 8 + wid;
    if (r >= NQ) return;
    const size_t base = (size_t)r * 128 + lane * 4;
    float4 x4 = *(const float4*)&X[base];
    float s = x4.x + x4.y + x4.z + x4.w;
    #pragma unroll
    for (int o = 16; o > 0; o >>= 1) s += __shfl_xor_sync(0xffffffffu, s, o);
    float m = s * (1.f / 128.f);
    float d0 = x4.x - m, d1 = x4.y - m, d2 = x4.z - m, d3 = x4.w - m;
    float q = d0 * d0 + d1 * d1 + d2 * d2 + d3 * d3;
    #pragma unroll
    for (int o = 16; o > 0; o >>= 1) q += __shfl_xor_sync(0xffffffffu, q, o);
    float inv = rsqrtf(q * (1.f / 128.f) + 1e-5f);
    float4 g4 = *(const float4*)&g[lane * 4];
    float4 b4 = *(const float4*)&b[lane * 4];
    float y0 = d0 * inv * g4.x + b4.x;
    float y1 = d1 * inv * g4.y + b4.y;
    float y2 = d2 * inv * g4.z + b4.z;
    float y3 = d3 * inv * g4.w + b4.w;
    if (MODE != 5)
        *(float4*)&Y[base] = make_float4(y0, y1, y2, y3);
    if (MODE == 4) {
        float4 p4 = *(const float4*)&pos[base];
        y0 += p4.x; y1 += p4.y; y2 += p4.z; y3 += p4.w;
    }
    __half2 h01 = __floats2half2_rn(y0, y1);
    __half2 h23 = __floats2half2_rn(y2, y3);
    *(uint2*)&Yx[base] = make_uint2(*(uint32_t*)&h01, *(uint32_t*)&h23);
}

// ---------------- conv1 (7x7, 128->128) via mma.sync fp16, fused BN stats ----------------
constexpr int ROWB = 144;
constexpr int C1TILE = 128 * ROWB;
constexpr int C1BUF  = 2 * C1TILE;
constexpr int CONV1_SMEM = 2 * C1BUF;

__global__ void __launch_bounds__(256, 2) conv1_f16_kernel(
    const __half* __restrict__ q16, const __half* __restrict__ w16,
    float* __restrict__ Out, float* __restrict__ part)
{
    extern __shared__ char smem[];
    __shared__ float red_s[8][128], red_q[8][128];
    const int tid = threadIdx.x;
    const int wid = tid >> 5, lane = tid & 31;
    const int warp_m = wid >> 2, warp_n = wid & 3;
    const uint32_t sb = smem_u32(smem);
    const int bm = blockIdx.x * 128;

    const int lrow = tid >> 1, lhalf = tid & 1;
    const int pm = bm + lrow;
    const int py = pm / 200, px = pm % 200;
    const bool prow_ok = pm < NQ;
    const uint32_t s_arow = sb + (uint32_t)lrow * ROWB + (uint32_t)lhalf * 64;
    const uint32_t s_brow = s_arow + C1TILE;

    const uint32_t a_base = sb + (uint32_t)(warp_m * 64 + (lane & 15)) * ROWB + (uint32_t)(lane >> 4) * 16;
    const uint32_t b_base = sb + C1TILE + (uint32_t)(warp_n * 32 + (lane & 7)) * ROWB
                          + (uint32_t)((lane >> 3) & 1) * 16;

    float acc[4][4][4];
    #pragma unroll
    for (int mt = 0; mt < 4; mt++)
        #pragma unroll
        for (int nt = 0; nt < 4; nt++)
            #pragma unroll
            for (int d = 0; d < 4; d++) acc[mt][nt][d] = 0.f;

    auto load_chunk = [&](int c, int buf) {
        const int e = c >> 1, ch = c & 1;
        const int qy = py + e / 7 - 3;
        const int qx = px + e % 7 - 3;
        const bool val = prow_ok && qy >= 0 && qy < 200 && qx >= 0 && qx < 200;
        const size_t aoff = (size_t)(val ? (qy * 200 + qx) : 0) * 128 + (size_t)ch * 64 + (size_t)lhalf * 32;
        const char* ag = (const char*)(q16 + aoff);
        const size_t boff = ((size_t)c * 128 + lrow) * 64 + (size_t)lhalf * 32;
        const char* bg = (const char*)(w16 + boff);
        const uint32_t sa = s_arow + (uint32_t)buf * C1BUF;
        const uint32_t sbr = s_brow + (uint32_t)buf * C1BUF;
        #pragma unroll
        for (int i = 0; i < 4; i++) {
            cpasync16(sa + i * 16,  ag + i * 16, val);
            cpasync16(sbr + i * 16, bg + i * 16, true);
        }
    };

    load_chunk(0, 0); cp_commit();
    load_chunk(1, 1); cp_commit();

    for (int c = 0; c < W1CHUNKS; c++) {
        const int buf = c & 1;
        cp_wait1();
        __syncthreads();

        const uint32_t ab = a_base + (uint32_t)buf * C1BUF;
        const uint32_t bb = b_base + (uint32_t)buf * C1BUF;
        #pragma unroll
        for (int ks = 0; ks < 4; ks++) {
            const uint32_t kbyte = (uint32_t)ks * 32;
            uint32_t bfr[4][2];
            #pragma unroll
            for (int nt = 0; nt < 4; nt++)
                ldmx2(bfr[nt], bb + (uint32_t)nt * 8 * ROWB + kbyte);
            #pragma unroll
            for (int mt = 0; mt < 4; mt++) {
                uint32_t afr[4];
                ldmx4(afr, ab + (uint32_t)mt * 16 * ROWB + kbyte);
                #pragma unroll
                for (int nt = 0; nt < 4; nt++)
                    mma_f16(acc[mt][nt], afr, bfr[nt]);
            }
        }
        __syncthreads();
        if (c + 2 < W1CHUNKS) load_chunk(c + 2, buf);
        cp_commit();
    }

    const int g = lane >> 2, tg = lane & 3;
    #pragma unroll
    for (int mt = 0; mt < 4; mt++) {
        const int r0 = bm + warp_m * 64 + mt * 16 + g;
        #pragma unroll
        for (int nt = 0; nt < 4; nt++) {
            const int col = warp_n * 32 + nt * 8 + tg * 2;
            if (r0 < NQ)
                *(float2*)&Out[(size_t)r0 * 128 + col] = make_float2(acc[mt][nt][0], acc[mt][nt][1]);
            if (r0 + 8 < NQ)
                *(float2*)&Out[(size_t)(r0 + 8) * 128 + col] = make_float2(acc[mt][nt][2], acc[mt][nt][3]);
        }
    }

    // fused BN stats
    float cs[8], cq[8];
    #pragma unroll
    for (int nt = 0; nt < 4; nt++)
        #pragma unroll
        for (int j = 0; j < 2; j++) {
            float s = 0.f, q = 0.f;
            #pragma unroll
            for (int mt = 0; mt < 4; mt++) {
                float v0 = acc[mt][nt][j], v1 = acc[mt][nt][2 + j];
                s += v0 + v1; q += v0 * v0 + v1 * v1;
            }
            cs[nt * 2 + j] = s; cq[nt * 2 + j] = q;
        }
    #pragma unroll
    for (int k = 0; k < 8; k++) {
        #pragma unroll
        for (int o = 4; o <= 16; o <<= 1) {
            cs[k] += __shfl_xor_sync(0xffffffffu, cs[k], o);
            cq[k] += __shfl_xor_sync(0xffffffffu, cq[k], o);
        }
    }
    if (lane < 4) {
        #pragma unroll
        for (int nt = 0; nt < 4; nt++)
            #pragma unroll
            for (int j = 0; j < 2; j++) {
                int col = warp_n * 32 + nt * 8 + lane * 2 + j;
                red_s[wid][col] = cs[nt * 2 + j];
                red_q[wid][col] = cq[nt * 2 + j];
            }
    }
    __syncthreads();
    if (tid < 128) {
        int wn = tid >> 5;
        float s = red_s[wn][tid] + red_s[4 + wn][tid];
        float q = red_q[wn][tid] + red_q[4 + wn][tid];
        part[(size_t)blockIdx.x * 256 + tid] = s;
        part[(size_t)blockIdx.x * 256 + 128 + tid] = q;
    }
}

// ---------------- convs 2-4 (3x3) via mma.sync bf16x3, fused BN stats ----------------
constexpr int CATILE = 128 * ROWB;
constexpr int CBTILE = 64 * ROWB;
constexpr int CBUF = 2 * CATILE + 2 * CBTILE;
constexpr int CONV_SMEM = 2 * CBUF;

template<int CHUNKS, int CIN_CH, int CST>
__global__ void __launch_bounds__(256, 2) conv_mma_kernel(
    const __nv_bfloat16* __restrict__ inh, const __nv_bfloat16* __restrict__ inl,
    const __nv_bfloat16* __restrict__ wh, const __nv_bfloat16* __restrict__ wl,
    float* __restrict__ Out, int COUT, float* __restrict__ part)
{
    extern __shared__ char smem[];
    __shared__ float red_s[8][64], red_q[8][64];
    const int tid = threadIdx.x;
    const int wid = tid >> 5, lane = tid & 31;
    const int warp_m = wid >> 1, warp_n = wid & 1;
    const uint32_t sb = smem_u32(smem);
    const int bm = blockIdx.x * 128;

    const int lrow = tid >> 1, lhalf = tid & 1;
    const int pm = bm + lrow;
    const int py = pm / 200, px = pm % 200;
    const bool prow_ok = pm < NQ;
    const uint32_t s_arow = sb + (uint32_t)lrow * ROWB + (uint32_t)lhalf * 64;
    const int brow = tid >> 2, bq = tid & 3;
    const uint32_t s_brow = sb + 2 * CATILE + (uint32_t)brow * ROWB + (uint32_t)bq * 32;

    const uint32_t a_base = sb + (uint32_t)(warp_m * 32 + (lane & 15)) * ROWB + (uint32_t)(lane >> 4) * 16;
    const uint32_t b_base = sb + 2 * CATILE + (uint32_t)(warp_n * 32 + (lane & 7)) * ROWB
                          + (uint32_t)((lane >> 3) & 1) * 16;

    float acc[2][4][4];
    #pragma unroll
    for (int mt = 0; mt < 2; mt++)
        #pragma unroll
        for (int nt = 0; nt < 4; nt++)
            #pragma unroll
            for (int d = 0; d < 4; d++) acc[mt][nt][d] = 0.f;

    auto load_chunk = [&](int c, int buf) {
        const int e = c / CIN_CH, cih = c % CIN_CH;
        const int qy = py + e / 3 - 1;
        const int qx = px + e % 3 - 1;
        const bool val = prow_ok && qy >= 0 && qy < 200 && qx >= 0 && qx < 200;
        const size_t aoff = (size_t)(val ? (qy * 200 + qx) : 0) * CST + (size_t)cih * 64 + (size_t)lhalf * 32;
        const char* agh = (const char*)(inh + aoff);
        const char* agl = (const char*)(inl + aoff);
        const size_t boff = ((size_t)c * 64 + brow) * 64 + (size_t)bq * 16;
        const char* bgh = (const char*)(wh + boff);
        const char* bgl = (const char*)(wl + boff);
        const uint32_t sa = s_arow + (uint32_t)buf * CBUF;
        const uint32_t sbr = s_brow + (uint32_t)buf * CBUF;
        #pragma unroll
        for (int i = 0; i < 4; i++) {
            cpasync16(sa + i * 16,           agh + i * 16, val);
            cpasync16(sa + CATILE + i * 16,  agl + i * 16, val);
        }
        #pragma unroll
        for (int i = 0; i < 2; i++) {
            cpasync16(sbr + i * 16,          bgh + i * 16, true);
            cpasync16(sbr + CBTILE + i * 16, bgl + i * 16, true);
        }
    };

    load_chunk(0, 0); cp_commit();
    load_chunk(1, 1); cp_commit();

    for (int c = 0; c < CHUNKS; c++) {
        const int buf = c & 1;
        cp_wait1();
        __syncthreads();

        const uint32_t ab = a_base + (uint32_t)buf * CBUF;
        const uint32_t bb = b_base + (uint32_t)buf * CBUF;
        #pragma unroll
        for (int ks = 0; ks < 4; ks++) {
            const uint32_t kbyte = (uint32_t)ks * 32;
            uint32_t bh[4][2], bl[4][2];
            #pragma unroll
            for (int nt = 0; nt < 4; nt++) {
                ldmx2(bh[nt], bb + (uint32_t)nt * 8 * ROWB + kbyte);
                ldmx2(bl[nt], bb + CBTILE + (uint32_t)nt * 8 * ROWB + kbyte);
            }
            #pragma unroll
            for (int mt = 0; mt < 2; mt++) {
                uint32_t ah[4], al[4];
                ldmx4(ah, ab + (uint32_t)mt * 16 * ROWB + kbyte);
                ldmx4(al, ab + CATILE + (uint32_t)mt * 16 * ROWB + kbyte);
                #pragma unroll
                for (int nt = 0; nt < 4; nt++) {
                    mma_bf16(acc[mt][nt], ah, bh[nt]);
                    mma_bf16(acc[mt][nt], ah, bl[nt]);
                    mma_bf16(acc[mt][nt], al, bh[nt]);
                }
            }
        }
        __syncthreads();
        if (c + 2 < CHUNKS) load_chunk(c + 2, buf);
        cp_commit();
    }

    const int g = lane >> 2, tg = lane & 3;
    #pragma unroll
    for (int mt = 0; mt < 2; mt++) {
        const int r0 = bm + warp_m * 32 + mt * 16 + g;
        #pragma unroll
        for (int nt = 0; nt < 4; nt++) {
            const int col = warp_n * 32 + nt * 8 + tg * 2;
            if (col >= COUT) continue;
            if (r0 < NQ)
                *(float2*)&Out[(size_t)r0 * COUT + col] = make_float2(acc[mt][nt][0], acc[mt][nt][1]);
            if (r0 + 8 < NQ)
                *(float2*)&Out[(size_t)(r0 + 8) * COUT + col] = make_float2(acc[mt][nt][2], acc[mt][nt][3]);
        }
    }

    // fused BN stats
    float cs[8], cq[8];
    #pragma unroll
    for (int nt = 0; nt < 4; nt++)
        #pragma unroll
        for (int j = 0; j < 2; j++) {
            float s = 0.f, q = 0.f;
            #pragma unroll
            for (int mt = 0; mt < 2; mt++) {
                float v0 = acc[mt][nt][j], v1 = acc[mt][nt][2 + j];
                s += v0 + v1; q += v0 * v0 + v1 * v1;
            }
            cs[nt * 2 + j] = s; cq[nt * 2 + j] = q;
        }
    #pragma unroll
    for (int k = 0; k < 8; k++) {
        #pragma unroll
        for (int o = 4; o <= 16; o <<= 1) {
            cs[k] += __shfl_xor_sync(0xffffffffu, cs[k], o);
            cq[k] += __shfl_xor_sync(0xffffffffu, cq[k], o);
        }
    }
    if (lane < 4) {
        #pragma unroll
        for (int nt = 0; nt < 4; nt++)
            #pragma unroll
            for (int j = 0; j < 2; j++) {
                int col = warp_n * 32 + nt * 8 + lane * 2 + j;
                red_s[wid][col] = cs[nt * 2 + j];
                red_q[wid][col] = cq[nt * 2 + j];
            }
    }
    __syncthreads();
    if (tid < COUT) {
        int wn = tid >> 5;
        float s = 0.f, q = 0.f;
        #pragma unroll
        for (int wm = 0; wm < 4; wm++) {
            s += red_s[wm * 2 + wn][tid];
            q += red_q[wm * 2 + wn][tid];
        }
        part[(size_t)blockIdx.x * 2 * COUT + tid] = s;
        part[(size_t)blockIdx.x * 2 * COUT + COUT + tid] = q;
    }
}

// ---------------- batchnorm finalize (sums NBLK per-block partials) ----------------
__global__ void bn_finalize_kernel(const float* __restrict__ part,
                                   const float* __restrict__ gamma, const float* __restrict__ beta,
                                   float* __restrict__ scale, float* __restrict__ shift, int C)
{
    int c = threadIdx.x;
    float s = 0.f, q = 0.f;
    for (int g = 0; g < NBLK; g++) {
        s += part[(size_t)g * 2 * C + c];
        q += part[(size_t)g * 2 * C + C + c];
    }
    const float invP = 1.f / (float)NQ;
    float m = s * invP;
    float v = q * invP - m * m;
    float sc = gamma[c] * rsqrtf(v + 1e-5f);
    scale[c] = sc;
    shift[c] = beta[c] - m * sc;
}

// BN+ReLU -> bf16 split, 4-wide vectorized
__global__ void bn_apply_split_kernel(const float* __restrict__ X, const float* __restrict__ scale,
                                      const float* __restrict__ shift,
                                      __nv_bfloat16* __restrict__ hi, __nv_bfloat16* __restrict__ lo,
                                      int C, int CST, int total4)
{
    int i = blockIdx.x * blockDim.x + threadIdx.x;
    if (i >= total4) return;
    int idx = i * 4;
    int c = idx % CST;
    int p = idx / CST;
    float v[4] = {0.f, 0.f, 0.f, 0.f};
    if (c < C) {
        float4 x4 = *(const float4*)&X[(size_t)p * C + c];
        float4 sc = *(const float4*)&scale[c];
        float4 sh = *(const float4*)&shift[c];
        v[0] = fmaxf(0.f, fmaf(x4.x, sc.x, sh.x));
        v[1] = fmaxf(0.f, fmaf(x4.y, sc.y, sh.y));
        v[2] = fmaxf(0.f, fmaf(x4.z, sc.z, sh.z));
        v[3] = fmaxf(0.f, fmaf(x4.w, sc.w, sh.w));
    }
    __nv_bfloat16 h[4], l[4];
    #pragma unroll
    for (int k = 0; k < 4; k++) split2(v[k], h[k], l[k]);
    __nv_bfloat162 h01(h[0], h[1]), h23(h[2], h[3]);
    __nv_bfloat162 l01(l[0], l[1]), l23(l[2], l[3]);
    *(uint2*)&hi[idx] = make_uint2(*(uint32_t*)&h01, *(uint32_t*)&h23);
    *(uint2*)&lo[idx] = make_uint2(*(uint32_t*)&l01, *(uint32_t*)&l23);
}

// ---------------- head: fused BN4+ReLU + 1x1 conv 48 -> 21, output NCHW ----------------
__global__ void head_conv_kernel(const float* __restrict__ H4raw, const float* __restrict__ scale,
                                 const float* __restrict__ shift,
                                 const float* __restrict__ Wo, const float* __restrict__ bo,
                                 float* __restrict__ out)
{
    int p = blockIdx.x * blockDim.x + threadIdx.x;
    if (p >= NQ) return;
    float x[48];
    const float4* hp = (const float4*)(H4raw + (size_t)p * 48);
    #pragma unroll
    for (int i = 0; i < 12; i++) {
        float4 v = hp[i];
        x[i * 4 + 0] = v.x; x[i * 4 + 1] = v.y; x[i * 4 + 2] = v.z; x[i * 4 + 3] = v.w;
    }
    #pragma unroll
    for (int ci = 0; ci < 48; ci++)
        x[ci] = fmaxf(0.f, fmaf(x[ci], scale[ci], shift[ci]));
    for (int co = 0; co < 21; co++) {
        float s = bo[co];
        const float* w = Wo + co * 48;
        #pragma unroll
        for (int ci = 0; ci < 48; ci++) s = fmaf(x[ci], w[ci], s);
        out[(size_t)co * NQ + p] = s;
    }
}

// ---------------- launch ----------------
extern "C" void kernel_launch(void* const* d_in, const int* in_sizes, int n_in,
                              void* d_out, int out_size)
{
    const float* value = (const float*)d_in[0];
    const float* bq    = (const float*)d_in[1];
    const float* bpos  = (const float*)d_in[2];
    const int*   proj  = (const int*)d_in[3];
    const float* Wv    = (const float*)d_in[4];
    const float* bv    = (const float*)d_in[5];
    const float* Woff  = (const float*)d_in[6];
    const float* boff  = (const float*)d_in[7];
    const float* Wattn = (const float*)d_in[8];
    const float* battn = (const float*)d_in[9];
    const float* Wout  = (const float*)d_in[10];
    const float* bout  = (const float*)d_in[11];
    const float* Wf1   = (const float*)d_in[12];
    const float* bf1   = (const float*)d_in[13];
    const float* Wf2   = (const float*)d_in[14];
    const float* bf2   = (const float*)d_in[15];
    const float* lng   = (const float*)d_in[16];
    const float* lnb   = (const float*)d_in[17];
    const float* cw1   = (const float*)d_in[18];
    const float* g1    = (const float*)d_in[19];
    const float* b1    = (const float*)d_in[20];
    const float* cw2   = (const float*)d_in[21];
    const float* g2    = (const float*)d_in[22];
    const float* b2    = (const float*)d_in[23];
    const float* cw3   = (const float*)d_in[24];
    const float* g3    = (const float*)d_in[25];
    const float* b3    = (const float*)d_in[26];
    const float* cw4   = (const float*)d_in[27];
    const float* g4    = (const float*)d_in[28];
    const float* b4    = (const float*)d_in[29];
    const float* objw  = (const float*)d_in[30];
    const float* objb  = (const float*)d_in[31];
    float* out = (float*)d_out;

    float* S = nullptr;
    cudaGetSymbolAddress((void**)&S, g_scratch);
    int* pmax = nullptr;
    cudaGetSymbolAddress((void**)&pmax, g_pmax);
    __nv_bfloat16 *s1h, *s1l, *s2h, *s2l, *wch, *wcl;
    __half *vx, *vin16, *q16, *qp16, *w16, *wf16, *oa16;
    cudaGetSymbolAddress((void**)&s1h, g_s1h);
    cudaGetSymbolAddress((void**)&s1l, g_s1l);
    cudaGetSymbolAddress((void**)&s2h, g_s2h);
    cudaGetSymbolAddress((void**)&s2l, g_s2l);
    cudaGetSymbolAddress((void**)&vx,  g_vx);
    cudaGetSymbolAddress((void**)&vin16, g_vin16);
    cudaGetSymbolAddress((void**)&q16, g_q16);
    cudaGetSymbolAddress((void**)&qp16, g_qp16);
    cudaGetSymbolAddress((void**)&w16, g_w16);
    cudaGetSymbolAddress((void**)&wf16, g_wf16);
    cudaGetSymbolAddress((void**)&oa16, g_oa16);
    cudaGetSymbolAddress((void**)&wch, g_wch);
    cudaGetSymbolAddress((void**)&wcl, g_wcl);

    float* PQ    = S + OFF_Q;
    float* PT1   = S + OFF_T1;
    float* PT2   = S + OFF_T2;
    float* PH1   = S + OFF_H1;
    float* PH2   = S + OFF_H2;
    float* PH3   = S + OFF_H3;
    float* PH4   = S + OFF_H4;
    float* PPART = S + OFF_PART;
    float* PSCALE= S + OFF_SCALE;
    float* PSHIFT= S + OFF_SHIFT;
    float* PBIAS = S + OFF_BIAS;

    cudaFuncSetAttribute(conv1_f16_kernel, cudaFuncAttributeMaxDynamicSharedMemorySize, CONV1_SMEM);
    cudaFuncSetAttribute(gemm_f16<8>,    cudaFuncAttributeMaxDynamicSharedMemorySize, F16GEMM_SMEM);
    cudaFuncSetAttribute(gemm_f16<9>,    cudaFuncAttributeMaxDynamicSharedMemorySize, F16GEMM_SMEM);
    cudaFuncSetAttribute(gemm_f16<6>,    cudaFuncAttributeMaxDynamicSharedMemorySize, F16GEMM_SMEM);
    cudaFuncSetAttribute((conv_mma_kernel<18, 2, 128>), cudaFuncAttributeMaxDynamicSharedMemorySize, CONV_SMEM);
    cudaFuncSetAttribute((conv_mma_kernel<9, 1, 64>),   cudaFuncAttributeMaxDynamicSharedMemorySize, CONV_SMEM);

    // --- observed_masks (2-launch deterministic) ---
    reduce_max_part_kernel<<<NMAXB, 256>>>(proj, pmax);
    write_mask_kernel<<<(NQ + 255) / 256, 256>>>(proj, pmax, out + 21 * NQ);

    // --- fused weight prep + value fp16 (single launch) ---
    prep_kernel<<<(Q10 + 255) / 256, 256>>>(cw1, cw2, cw3, cw4, Woff, Wattn, Wv, Wf1, Wf2, Wout,
                                            boff, battn, value,
                                            w16, wch, wcl, wf16, PBIAS, vin16);

    // --- q init ---
    cudaMemcpyAsync(PQ, bq, (size_t)NQ * ED * sizeof(float), cudaMemcpyDeviceToDevice);

    // --- 2 encoder layers ---
    add_f16_kernel<<<(NQ * ED / 4 + 255) / 256, 256>>>(PQ, bpos, qp16, NQ * ED / 4);
    for (int i = 0; i < 2; i++) {
        size_t LW = (size_t)i * WFL;
        gemm_f16<8><<<dim3(340, 1), 256, F16GEMM_SMEM>>>(vin16, wf16 + LW + 768 * 128,
                                                         bv + i * 128, nullptr, nullptr, vx, NV, 128);
        gemm_f16<8><<<dim3(313, 6), 256, F16GEMM_SMEM>>>(qp16, wf16 + LW,
                                                         PBIAS + i * 768, nullptr, nullptr, oa16, NQ, 768);
        deform_kernel<<<(NQ * HEADS + 255) / 256, 256>>>(vx, oa16, q16);
        gemm_f16<6><<<dim3(313, 1), 256, F16GEMM_SMEM>>>(q16, wf16 + LW + 1152 * 128,
                                                         bout + i * 128, PQ, PT1, nullptr, NQ, 128);
        ln_kernel<3><<<(NQ + 7) / 8, 256>>>(PT1, lng + (i * 2 + 0) * 128, lnb + (i * 2 + 0) * 128, PQ, q16, nullptr);
        gemm_f16<9><<<dim3(313, 1), 256, F16GEMM_SMEM>>>(q16, wf16 + LW + 896 * 128,
                                                         bf1 + i * 128, nullptr, nullptr, qp16, NQ, 128);
        gemm_f16<6><<<dim3(313, 1), 256, F16GEMM_SMEM>>>(qp16, wf16 + LW + 1024 * 128,
                                                         bf2 + i * 128, PQ, PT2, nullptr, NQ, 128);
        if (i == 0)
            ln_kernel<4><<<(NQ + 7) / 8, 256>>>(PT2, lng + 1 * 128, lnb + 1 * 128, PQ, qp16, bpos);   // fp16(q+pos)
        else
            ln_kernel<5><<<(NQ + 7) / 8, 256>>>(PT2, lng + 3 * 128, lnb + 3 * 128, nullptr, q16, nullptr); // fp16 only
    }

    // --- conv head (BN stats fused into conv epilogues) ---
    conv1_f16_kernel<<<NBLK, 256, CONV1_SMEM>>>(q16, w16, PH1, PPART);
    bn_finalize_kernel<<<1, 128>>>(PPART, g1, b1, PSCALE, PSHIFT, 128);
    bn_apply_split_kernel<<<(NQ * 128 / 4 + 255) / 256, 256>>>(PH1, PSCALE, PSHIFT, s1h, s1l, 128, 128, NQ * 128 / 4);

    conv_mma_kernel<18, 2, 128><<<NBLK, 256, CONV_SMEM>>>(s1h, s1l, wch + WC2_OFF, wcl + WC2_OFF, PH2, 64, PPART);
    bn_finalize_kernel<<<1, 64>>>(PPART, g2, b2, PSCALE, PSHIFT, 64);
    bn_apply_split_kernel<<<(NQ * 64 / 4 + 255) / 256, 256>>>(PH2, PSCALE, PSHIFT, s2h, s2l, 64, 64, NQ * 64 / 4);

    conv_mma_kernel<9, 1, 64><<<NBLK, 256, CONV_SMEM>>>(s2h, s2l, wch + WC3_OFF, wcl + WC3_OFF, PH3, 48, PPART);
    bn_finalize_kernel<<<1, 48>>>(PPART, g3, b3, PSCALE, PSHIFT, 48);
    bn_apply_split_kernel<<<(NQ * 64 / 4 + 255) / 256, 256>>>(PH3, PSCALE, PSHIFT, s1h, s1l, 48, 64, NQ * 64 / 4);

    conv_mma_kernel<9, 1, 64><<<NBLK, 256, CONV_SMEM>>>(s1h, s1l, wch + WC4_OFF, wcl + WC4_OFF, PH4, 48, PPART);
    bn_finalize_kernel<<<1, 48>>>(PPART, g4, b4, PSCALE, PSHIFT, 48);
    head_conv_kernel<<<(NQ + 255) / 256, 256>>>(PH4, PSCALE, PSHIFT, objw, objb, out);
}

// round 17
// speedup vs baseline: 3.5472x; 1.0030x over previous
#include <cuda_runtime.h>
#include <cuda_bf16.h>
#include <cuda_fp16.h>
#include <cstdint>
#include <climits>

// ---------------- problem constants ----------------
constexpr int NQ = 40000;        // 200*200
constexpr int ED = 128;
constexpr int NV = 43520;        // sum of level sizes
constexpr int HEADS = 8;
constexpr int NBLK = 313;        // conv blocks = bn partials
constexpr int NMAXB = 40;        // max-reduction partial blocks

// ---------------- scratch layout (floats) ----------------
constexpr size_t OFF_Q    = 0;
constexpr size_t SZ_Q     = (size_t)NQ * ED;
constexpr size_t OFF_T1   = OFF_Q + SZ_Q;
constexpr size_t OFF_T2   = OFF_T1 + SZ_Q;
constexpr size_t OFF_H1   = OFF_T2 + SZ_Q;
constexpr size_t SZ_H1    = (size_t)NQ * 128;
constexpr size_t OFF_H2   = OFF_H1 + SZ_H1;
constexpr size_t SZ_H2    = (size_t)NQ * 64;
constexpr size_t OFF_H3   = OFF_H2 + SZ_H2;
constexpr size_t SZ_H3    = (size_t)NQ * 48;
constexpr size_t OFF_H4   = OFF_H3 + SZ_H3;
constexpr size_t OFF_PART = OFF_H4 + SZ_H3;
constexpr size_t SZ_PART  = (size_t)NBLK * 2 * 128 + 256;
constexpr size_t OFF_SCALE= OFF_PART + SZ_PART;
constexpr size_t OFF_SHIFT= OFF_SCALE + 128;
constexpr size_t OFF_BIAS = OFF_SHIFT + 128;       // 2 layers x 768 packed bias
constexpr size_t SCRATCH_TOTAL = OFF_BIAS + 2 * 768;

__device__ float g_scratch[SCRATCH_TOTAL];
__device__ int   g_pmax[NMAXB];

// ---------------- bf16 / fp16 buffers ----------------
constexpr int W1CHUNKS = 98;                 // conv1: 49 taps * 2 ci-halves
__device__ __align__(16) __nv_bfloat16 g_s1h[(size_t)NQ * 128];
__device__ __align__(16) __nv_bfloat16 g_s1l[(size_t)NQ * 128];
__device__ __align__(16) __nv_bfloat16 g_s2h[(size_t)NQ * 128];
__device__ __align__(16) __nv_bfloat16 g_s2l[(size_t)NQ * 128];
__device__ __align__(16) __half        g_vx[(size_t)NV * 256];    // fp16 V, both layers [NV][256]
__device__ __align__(16) __half        g_vin16[(size_t)NV * 128]; // fp16 value input
__device__ __align__(16) __half        g_q16[(size_t)NQ * 128];   // fp16 scratch
__device__ __align__(16) __half        g_qp16[(size_t)NQ * 128];  // fp16 scratch
__device__ __align__(16) __half        g_oa16[(size_t)NQ * 768];  // fp16 offsets+logits
// fp16 weights per layer: [OA 768][gap][Wf1 128][Wf2 128][Wout 128] x 128 k
constexpr int WFL = 1280 * 128;              // per-layer stride
__device__ __align__(16) __half g_wf16[(size_t)2 * WFL];
// combined V-projection weights [256][128] = Wv0 | Wv1
__device__ __align__(16) __half g_wv16[256 * 128];
// conv1 weights [chunk][co 128][k 64] fp16
__device__ __align__(16) __half g_w16[(size_t)W1CHUNKS * 128 * 64];
// convs 2-4 bf16 split weights
constexpr int WC2_OFF = 0, WC3_OFF = 73728, WC4_OFF = 110592, WC_TOTAL = 147456;
__device__ __align__(16) __nv_bfloat16 g_wch[WC_TOTAL];
__device__ __align__(16) __nv_bfloat16 g_wcl[WC_TOTAL];

// ---------------- small helpers ----------------
__device__ __forceinline__ uint32_t smem_u32(const void* p) {
    return (uint32_t)__cvta_generic_to_shared(p);
}
__device__ __forceinline__ void cpasync16(uint32_t dst, const void* src, bool valid) {
    asm volatile("cp.async.cg.shared.global [%0], [%1], 16, %2;"
                 :: "r"(dst), "l"(src), "r"(valid ? 16u : 0u));
}
__device__ __forceinline__ void cp_commit() { asm volatile("cp.async.commit_group;"); }
__device__ __forceinline__ void cp_wait1()  { asm volatile("cp.async.wait_group 1;"); }
__device__ __forceinline__ void cp_wait0()  { asm volatile("cp.async.wait_group 0;"); }

__device__ __forceinline__ void ldmx4(uint32_t* r, uint32_t addr) {
    asm volatile("ldmatrix.sync.aligned.m8n8.x4.shared.b16 {%0,%1,%2,%3}, [%4];"
                 : "=r"(r[0]), "=r"(r[1]), "=r"(r[2]), "=r"(r[3]) : "r"(addr));
}
__device__ __forceinline__ void ldmx2(uint32_t* r, uint32_t addr) {
    asm volatile("ldmatrix.sync.aligned.m8n8.x2.shared.b16 {%0,%1}, [%2];"
                 : "=r"(r[0]), "=r"(r[1]) : "r"(addr));
}
__device__ __forceinline__ void mma_bf16(float* c, const uint32_t* a, const uint32_t* b) {
    asm volatile("mma.sync.aligned.m16n8k16.row.col.f32.bf16.bf16.f32 "
                 "{%0,%1,%2,%3}, {%4,%5,%6,%7}, {%8,%9}, {%0,%1,%2,%3};"
                 : "+f"(c[0]), "+f"(c[1]), "+f"(c[2]), "+f"(c[3])
                 : "r"(a[0]), "r"(a[1]), "r"(a[2]), "r"(a[3]), "r"(b[0]), "r"(b[1]));
}
__device__ __forceinline__ void mma_f16(float* c, const uint32_t* a, const uint32_t* b) {
    asm volatile("mma.sync.aligned.m16n8k16.row.col.f32.f16.f16.f32 "
                 "{%0,%1,%2,%3}, {%4,%5,%6,%7}, {%8,%9}, {%0,%1,%2,%3};"
                 : "+f"(c[0]), "+f"(c[1]), "+f"(c[2]), "+f"(c[3])
                 : "r"(a[0]), "r"(a[1]), "r"(a[2]), "r"(a[3]), "r"(b[0]), "r"(b[1]));
}
__device__ __forceinline__ void split2(float v, __nv_bfloat16& h, __nv_bfloat16& l) {
    h = __float2bfloat16(v);
    l = __float2bfloat16(v - __bfloat162float(h));
}

// ---------------- observed_masks: 2-launch deterministic max + mask ----------------
__global__ void reduce_max_part_kernel(const int* __restrict__ p, int* __restrict__ pm) {
    int v = INT_MIN;
    for (int k = blockIdx.x * blockDim.x + threadIdx.x; k < NQ; k += gridDim.x * blockDim.x)
        v = max(v, p[k]);
    #pragma unroll
    for (int o = 16; o > 0; o >>= 1) v = max(v, __shfl_xor_sync(0xffffffffu, v, o));
    __shared__ int sm[8];
    int w = threadIdx.x >> 5;
    if ((threadIdx.x & 31) == 0) sm[w] = v;
    __syncthreads();
    if (threadIdx.x == 0) {
        int bv = sm[0];
        for (int i = 1; i < (int)(blockDim.x >> 5); i++) bv = max(bv, sm[i]);
        pm[blockIdx.x] = bv;
    }
}

__global__ void write_mask_kernel(const int* __restrict__ p, const int* __restrict__ pm,
                                  float* __restrict__ out) {
    __shared__ int sm;
    if (threadIdx.x == 0) {
        int v = INT_MIN;
        #pragma unroll
        for (int g = 0; g < NMAXB; g++) v = max(v, pm[g]);
        sm = v;
    }
    __syncthreads();
    int i = blockIdx.x * blockDim.x + threadIdx.x;
    if (i < NQ) out[i] = (p[i] < sm) ? 1.0f : 0.0f;
}

// q+pos -> fp16, 4-wide
__global__ void add_f16_kernel(const float* __restrict__ A, const float* __restrict__ B,
                               __half* __restrict__ o, int n4)
{
    int i = blockIdx.x * blockDim.x + threadIdx.x;
    if (i >= n4) return;
    int idx = i * 4;
    float4 a = *(const float4*)&A[idx];
    float4 b = *(const float4*)&B[idx];
    __half2 h01 = __floats2half2_rn(a.x + b.x, a.y + b.y);
    __half2 h23 = __floats2half2_rn(a.z + b.z, a.w + b.w);
    *(uint2*)&o[idx] = make_uint2(*(uint32_t*)&h01, *(uint32_t*)&h23);
}

// ---------------- fused weight prep + value fp16: one launch ----------------
constexpr int Q0 = 802816;            // conv1 fp16 [chunk][co][k]
constexpr int Q1 = Q0 + 73728;        // conv2 bf16 split
constexpr int Q2 = Q1 + 36864;        // conv3 bf16 split
constexpr int Q3 = Q2 + 36864;        // conv4 bf16 split
constexpr int Q4 = Q3 + 2 * 98304;    // OA fp16 (Woff|Wattn), both layers
constexpr int Q5 = Q4 + 2 * 16384;    // Wv fp16 combined [256][128]
constexpr int Q6 = Q5 + 2 * 16384;    // Wf1 fp16
constexpr int Q7 = Q6 + 2 * 16384;    // Wf2 fp16
constexpr int Q8 = Q7 + 2 * 16384;    // Wout fp16
constexpr int Q9 = Q8 + 2 * 768;      // bias pack
constexpr int Q10 = Q9 + NV * 128;    // value -> fp16

__global__ void prep_kernel(
    const float* __restrict__ cw1, const float* __restrict__ cw2,
    const float* __restrict__ cw3, const float* __restrict__ cw4,
    const float* __restrict__ Woff, const float* __restrict__ Wattn,
    const float* __restrict__ Wv, const float* __restrict__ Wf1,
    const float* __restrict__ Wf2, const float* __restrict__ Wout,
    const float* __restrict__ boff, const float* __restrict__ battn,
    const float* __restrict__ value,
    __half* __restrict__ w16, __nv_bfloat16* __restrict__ wch, __nv_bfloat16* __restrict__ wcl,
    __half* __restrict__ wf16, __half* __restrict__ wv16,
    float* __restrict__ bias_out, __half* __restrict__ vin16)
{
    int i = blockIdx.x * blockDim.x + threadIdx.x;
    if (i >= Q10) return;
    if (i < Q0) {
        int k = i & 63, co = (i >> 6) & 127, c = i >> 13;
        int e = c >> 1, ci = ((c & 1) << 6) + k;
        w16[i] = __float2half_rn(cw1[(((size_t)co * 128 + ci) * 7 + e / 7) * 7 + e % 7]);
    } else if (i < Q3) {
        const float* W; int CO, CI, CIN_CH, base, j;
        if (i < Q1)      { j = i - Q0; W = cw2; CO = 64; CI = 128; CIN_CH = 2; base = WC2_OFF; }
        else if (i < Q2) { j = i - Q1; W = cw3; CO = 48; CI = 64;  CIN_CH = 1; base = WC3_OFF; }
        else             { j = i - Q2; W = cw4; CO = 48; CI = 48;  CIN_CH = 1; base = WC4_OFF; }
        int k = j & 63, co = (j >> 6) & 63, c = j >> 12;
        int e = c / CIN_CH, ci = (c % CIN_CH) * 64 + k;
        float v = (co < CO && ci < CI) ? W[(((size_t)co * CI + ci) * 3 + e / 3) * 3 + e % 3] : 0.f;
        split2(v, wch[base + j], wcl[base + j]);
    } else if (i < Q4) {
        int j = i - Q3, l = j / 98304, r = j % 98304;
        int n = r >> 7, k = r & 127;
        float v = (n < 512) ? Woff[((size_t)l * 128 + k) * 512 + n]
                            : Wattn[((size_t)l * 128 + k) * 256 + (n - 512)];
        wf16[(size_t)l * WFL + r] = __float2half_rn(v);
    } else if (i < Q5) {
        int j = i - Q4;                       // [l*128+n][k] combined, l*16384+n*128+k == j
        int l = j >> 14, r = j & 16383;
        int n = r >> 7, k = r & 127;
        wv16[j] = __float2half_rn(Wv[((size_t)l * 128 + k) * 128 + n]);
    } else if (i < Q8) {
        const float* W; int off, j;
        if (i < Q6)      { j = i - Q5; W = Wf1;  off = 896 * 128; }
        else if (i < Q7) { j = i - Q6; W = Wf2;  off = 1024 * 128; }
        else             { j = i - Q7; W = Wout; off = 1152 * 128; }
        int l = j >> 14, r = j & 16383;
        int n = r >> 7, k = r & 127;
        wf16[(size_t)l * WFL + off + r] = __float2half_rn(W[((size_t)l * 128 + k) * 128 + n]);
    } else if (i < Q9) {
        int j = i - Q8, l = j / 768, n = j % 768;
        bias_out[(size_t)l * 768 + n] = (n < 512) ? boff[(size_t)l * 512 + n] : battn[(size_t)l * 256 + n - 512];
    } else {
        int j = i - Q9;
        vin16[j] = __float2half_rn(value[j]);
    }
}

// ---------------- fp16 single GEMM ----------------
// FLAGS: 1 relu, 2 residual (fp32 R), 4 fp32 out, 8 fp16 out
constexpr int GROWB = 272;
constexpr int GTILE = 128 * GROWB;
constexpr int F16GEMM_SMEM = 2 * GTILE;

template<int FLAGS>
__global__ void __launch_bounds__(256, 2) gemm_f16(
    const __half* __restrict__ A, const __half* __restrict__ B,
    const float* __restrict__ bias, const float* __restrict__ R,
    float* __restrict__ Cf, __half* __restrict__ Cx, int M, int N)
{
    extern __shared__ char smem[];
    const int tid = threadIdx.x;
    const int wid = tid >> 5, lane = tid & 31;
    const int warp_m = wid >> 2, warp_n = wid & 3;
    const uint32_t sb = smem_u32(smem);
    const int bm = blockIdx.x * 128, bn = blockIdx.y * 128;

    {
        const int lrow = tid >> 1, lhalf = tid & 1;
        const bool aval = (bm + lrow) < M;
        const uint32_t sa = sb + (uint32_t)lrow * GROWB + (uint32_t)lhalf * 128;
        const char* ag = (const char*)(A + (size_t)(aval ? (bm + lrow) : 0) * 128 + lhalf * 64);
        const char* bg = (const char*)(B + (size_t)(bn + lrow) * 128 + lhalf * 64);
        #pragma unroll
        for (int i = 0; i < 8; i++) {
            cpasync16(sa + i * 16,         ag + i * 16, aval);
            cpasync16(sa + GTILE + i * 16, bg + i * 16, true);
        }
        cp_commit();
        cp_wait0();
        __syncthreads();
    }

    float acc[4][4][4];
    #pragma unroll
    for (int mt = 0; mt < 4; mt++)
        #pragma unroll
        for (int nt = 0; nt < 4; nt++)
            #pragma unroll
            for (int d = 0; d < 4; d++) acc[mt][nt][d] = 0.f;

    const uint32_t a_base = sb + (uint32_t)(warp_m * 64 + (lane & 15)) * GROWB + (uint32_t)(lane >> 4) * 16;
    const uint32_t b_base = sb + GTILE + (uint32_t)(warp_n * 32 + (lane & 7)) * GROWB
                          + (uint32_t)((lane >> 3) & 1) * 16;

    #pragma unroll
    for (int ks = 0; ks < 8; ks++) {
        const uint32_t kbyte = (uint32_t)ks * 32;
        uint32_t bfr[4][2];
        #pragma unroll
        for (int nt = 0; nt < 4; nt++)
            ldmx2(bfr[nt], b_base + (uint32_t)nt * 8 * GROWB + kbyte);
        #pragma unroll
        for (int mt = 0; mt < 4; mt++) {
            uint32_t afr[4];
            ldmx4(afr, a_base + (uint32_t)mt * 16 * GROWB + kbyte);
            #pragma unroll
            for (int nt = 0; nt < 4; nt++)
                mma_f16(acc[mt][nt], afr, bfr[nt]);
        }
    }

    const int g = lane >> 2, tg = lane & 3;
    #pragma unroll
    for (int mt = 0; mt < 4; mt++) {
        const int r0 = bm + warp_m * 64 + mt * 16 + g;
        #pragma unroll
        for (int nt = 0; nt < 4; nt++) {
            const int col = bn + warp_n * 32 + nt * 8 + tg * 2;
            float2 bb = *(const float2*)&bias[col];
            #pragma unroll
            for (int half = 0; half < 2; half++) {
                const int r = r0 + half * 8;
                if (r >= M) continue;
                float a0 = acc[mt][nt][half * 2] + bb.x;
                float a1 = acc[mt][nt][half * 2 + 1] + bb.y;
                if (FLAGS & 2) {
                    float2 rr = *(const float2*)&R[(size_t)r * N + col];
                    a0 += rr.x; a1 += rr.y;
                }
                if (FLAGS & 1) { a0 = fmaxf(a0, 0.f); a1 = fmaxf(a1, 0.f); }
                if (FLAGS & 4)
                    *(float2*)&Cf[(size_t)r * N + col] = make_float2(a0, a1);
                if (FLAGS & 8)
                    *(__half2*)&Cx[(size_t)r * N + col] = __floats2half2_rn(a0, a1);
            }
        }
    }
}

// ---------------- deformable attention sampling (fp16 V stride 256, fp16 OA, fp16 out) ----------------
__global__ void __launch_bounds__(256) deform_kernel(
    const __half* __restrict__ VX, const __half* __restrict__ OA,
    __half* __restrict__ OX)
{
    int t = blockIdx.x * 256 + threadIdx.x;
    if (t >= NQ * HEADS) return;
    const int n = t >> 3, h = t & 7;
    const float rx = ((float)(n % 200) + 0.5f) * (1.f / 200.f);
    const float ry = ((float)(n / 200) + 0.5f) * (1.f / 200.f);
    const __half* op = OA + (size_t)n * 768 + h * 64;
    const __half* ap = OA + (size_t)n * 768 + 512 + h * 32;

    float e[32];
    {
        const uint4* apv = (const uint4*)ap;
        #pragma unroll
        for (int q = 0; q < 4; q++) {
            uint4 u = apv[q];
            uint32_t wv[4] = {u.x, u.y, u.z, u.w};
            #pragma unroll
            for (int d = 0; d < 4; d++) {
                float2 f2 = __half22float2(*(const __half2*)&wv[d]);
                e[q * 8 + d * 2 + 0] = f2.x;
                e[q * 8 + d * 2 + 1] = f2.y;
            }
        }
        float m = -1e30f;
        #pragma unroll
        for (int k = 0; k < 32; k++) m = fmaxf(m, e[k]);
        float s = 0.f;
        #pragma unroll
        for (int k = 0; k < 32; k++) { e[k] = expf(e[k] - m); s += e[k]; }
        float inv = 1.f / s;
        #pragma unroll
        for (int k = 0; k < 32; k++) e[k] *= inv;
    }

    float acc[16];
    #pragma unroll
    for (int d = 0; d < 16; d++) acc[d] = 0.f;

    const int stc[4] = {0, 32768, 40960, 43008};
    const int Wc[4]  = {256, 128, 64, 32};
    const int Hc[4]  = {128, 64, 32, 16};
    const uint4* opv = (const uint4*)op;

    #pragma unroll
    for (int l = 0; l < 4; l++) {
        const int W = Wc[l], H = Hc[l], st = stc[l];
        const float Wf = (float)W, Hf = (float)H;
        uint4 o0 = opv[l * 2], o1 = opv[l * 2 + 1];
        uint32_t ow[8] = {o0.x, o0.y, o0.z, o0.w, o1.x, o1.y, o1.z, o1.w};
        #pragma unroll
        for (int p = 0; p < 8; p++) {
            float2 off2 = __half22float2(*(const __half2*)&ow[p]);
            float aw = e[l * 8 + p];
            float x = (rx + off2.x / Wf) * Wf - 0.5f;
            float y = (ry + off2.y / Hf) * Hf - 0.5f;
            float xf = floorf(x), yf = floorf(y);
            int x0 = (int)xf, y0 = (int)yf;
            float fx = x - xf, fy = y - yf;
            float wx[2] = {1.f - fx, fx};
            float wy[2] = {1.f - fy, fy};
            #pragma unroll
            for (int c = 0; c < 4; c++) {
                int xi = x0 + (c & 1), yi = y0 + (c >> 1);
                float wgt = wx[c & 1] * wy[c >> 1];
                if (xi >= 0 && xi < W && yi >= 0 && yi < H && wgt != 0.f) {
                    const uint4* gp = (const uint4*)(VX + ((size_t)(st + yi * W + xi)) * 256 + h * 16);
                    uint4 u0 = gp[0];
                    uint4 u1 = gp[1];
                    uint32_t wv[8] = {u0.x, u0.y, u0.z, u0.w, u1.x, u1.y, u1.z, u1.w};
                    float cw = aw * wgt;
                    #pragma unroll
                    for (int d = 0; d < 8; d++) {
                        float2 g2 = __half22float2(*(const __half2*)&wv[d]);
                        acc[d * 2 + 0] += cw * g2.x;
                        acc[d * 2 + 1] += cw * g2.y;
                    }
                }
            }
        }
    }
    uint32_t ov[8];
    #pragma unroll
    for (int d = 0; d < 8; d++) {
        __half2 h2 = __floats2half2_rn(acc[d * 2], acc[d * 2 + 1]);
        ov[d] = *(uint32_t*)&h2;
    }
    uint4* o = (uint4*)(OX + (size_t)n * 128 + h * 16);
    o[0] = make_uint4(ov[0], ov[1], ov[2], ov[3]);
    o[1] = make_uint4(ov[4], ov[5], ov[6], ov[7]);
}

// ---------------- layernorm: warp-per-row, 8 rows per block ----------------
// MODE: 3 fp32 + fp16(y), 4 fp32 + fp16(y + pos), 5 fp16(y) only
template<int MODE>
__global__ void __launch_bounds__(256) ln_kernel(
    const float* __restrict__ X, const float* __restrict__ g,
    const float* __restrict__ b, float* __restrict__ Y,
    __half* __restrict__ Yx, const float* __restrict__ pos)
{
    const int wid = threadIdx.x >> 5, lane = threadIdx.x & 31;
    const int r = blockIdx.x * 8 + wid;
    if (r >= NQ) return;
    const size_t base = (size_t)r * 128 + lane * 4;
    float4 x4 = *(const float4*)&X[base];
    float s = x4.x + x4.y + x4.z + x4.w;
    #pragma unroll
    for (int o = 16; o > 0; o >>= 1) s += __shfl_xor_sync(0xffffffffu, s, o);
    float m = s * (1.f / 128.f);
    float d0 = x4.x - m, d1 = x4.y - m, d2 = x4.z - m, d3 = x4.w - m;
    float q = d0 * d0 + d1 * d1 + d2 * d2 + d3 * d3;
    #pragma unroll
    for (int o = 16; o > 0; o >>= 1) q += __shfl_xor_sync(0xffffffffu, q, o);
    float inv = rsqrtf(q * (1.f / 128.f) + 1e-5f);
    float4 g4 = *(const float4*)&g[lane * 4];
    float4 b4 = *(const float4*)&b[lane * 4];
    float y0 = d0 * inv * g4.x + b4.x;
    float y1 = d1 * inv * g4.y + b4.y;
    float y2 = d2 * inv * g4.z + b4.z;
    float y3 = d3 * inv * g4.w + b4.w;
    if (MODE != 5)
        *(float4*)&Y[base] = make_float4(y0, y1, y2, y3);
    if (MODE == 4) {
        float4 p4 = *(const float4*)&pos[base];
        y0 += p4.x; y1 += p4.y; y2 += p4.z; y3 += p4.w;
    }
    __half2 h01 = __floats2half2_rn(y0, y1);
    __half2 h23 = __floats2half2_rn(y2, y3);
    *(uint2*)&Yx[base] = make_uint2(*(uint32_t*)&h01, *(uint32_t*)&h23);
}

// ---------------- conv1 (7x7, 128->128) via mma.sync fp16, fused BN stats ----------------
constexpr int ROWB = 144;
constexpr int C1TILE = 128 * ROWB;
constexpr int C1BUF  = 2 * C1TILE;
constexpr int CONV1_SMEM = 2 * C1BUF;

__global__ void __launch_bounds__(256, 2) conv1_f16_kernel(
    const __half* __restrict__ q16, const __half* __restrict__ w16,
    float* __restrict__ Out, float* __restrict__ part)
{
    extern __shared__ char smem[];
    __shared__ float red_s[8][128], red_q[8][128];
    const int tid = threadIdx.x;
    const int wid = tid >> 5, lane = tid & 31;
    const int warp_m = wid >> 2, warp_n = wid & 3;
    const uint32_t sb = smem_u32(smem);
    const int bm = blockIdx.x * 128;

    const int lrow = tid >> 1, lhalf = tid & 1;
    const int pm = bm + lrow;
    const int py = pm / 200, px = pm % 200;
    const bool prow_ok = pm < NQ;
    const uint32_t s_arow = sb + (uint32_t)lrow * ROWB + (uint32_t)lhalf * 64;
    const uint32_t s_brow = s_arow + C1TILE;

    const uint32_t a_base = sb + (uint32_t)(warp_m * 64 + (lane & 15)) * ROWB + (uint32_t)(lane >> 4) * 16;
    const uint32_t b_base = sb + C1TILE + (uint32_t)(warp_n * 32 + (lane & 7)) * ROWB
                          + (uint32_t)((lane >> 3) & 1) * 16;

    float acc[4][4][4];
    #pragma unroll
    for (int mt = 0; mt < 4; mt++)
        #pragma unroll
        for (int nt = 0; nt < 4; nt++)
            #pragma unroll
            for (int d = 0; d < 4; d++) acc[mt][nt][d] = 0.f;

    auto load_chunk = [&](int c, int buf) {
        const int e = c >> 1, ch = c & 1;
        const int qy = py + e / 7 - 3;
        const int qx = px + e % 7 - 3;
        const bool val = prow_ok && qy >= 0 && qy < 200 && qx >= 0 && qx < 200;
        const size_t aoff = (size_t)(val ? (qy * 200 + qx) : 0) * 128 + (size_t)ch * 64 + (size_t)lhalf * 32;
        const char* ag = (const char*)(q16 + aoff);
        const size_t boff = ((size_t)c * 128 + lrow) * 64 + (size_t)lhalf * 32;
        const char* bg = (const char*)(w16 + boff);
        const uint32_t sa = s_arow + (uint32_t)buf * C1BUF;
        const uint32_t sbr = s_brow + (uint32_t)buf * C1BUF;
        #pragma unroll
        for (int i = 0; i < 4; i++) {
            cpasync16(sa + i * 16,  ag + i * 16, val);
            cpasync16(sbr + i * 16, bg + i * 16, true);
        }
    };

    load_chunk(0, 0); cp_commit();
    load_chunk(1, 1); cp_commit();

    for (int c = 0; c < W1CHUNKS; c++) {
        const int buf = c & 1;
        cp_wait1();
        __syncthreads();

        const uint32_t ab = a_base + (uint32_t)buf * C1BUF;
        const uint32_t bb = b_base + (uint32_t)buf * C1BUF;
        #pragma unroll
        for (int ks = 0; ks < 4; ks++) {
            const uint32_t kbyte = (uint32_t)ks * 32;
            uint32_t bfr[4][2];
            #pragma unroll
            for (int nt = 0; nt < 4; nt++)
                ldmx2(bfr[nt], bb + (uint32_t)nt * 8 * ROWB + kbyte);
            #pragma unroll
            for (int mt = 0; mt < 4; mt++) {
                uint32_t afr[4];
                ldmx4(afr, ab + (uint32_t)mt * 16 * ROWB + kbyte);
                #pragma unroll
                for (int nt = 0; nt < 4; nt++)
                    mma_f16(acc[mt][nt], afr, bfr[nt]);
            }
        }
        __syncthreads();
        if (c + 2 < W1CHUNKS) load_chunk(c + 2, buf);
        cp_commit();
    }

    const int g = lane >> 2, tg = lane & 3;
    #pragma unroll
    for (int mt = 0; mt < 4; mt++) {
        const int r0 = bm + warp_m * 64 + mt * 16 + g;
        #pragma unroll
        for (int nt = 0; nt < 4; nt++) {
            const int col = warp_n * 32 + nt * 8 + tg * 2;
            if (r0 < NQ)
                *(float2*)&Out[(size_t)r0 * 128 + col] = make_float2(acc[mt][nt][0], acc[mt][nt][1]);
            if (r0 + 8 < NQ)
                *(float2*)&Out[(size_t)(r0 + 8) * 128 + col] = make_float2(acc[mt][nt][2], acc[mt][nt][3]);
        }
    }

    // fused BN stats
    float cs[8], cq[8];
    #pragma unroll
    for (int nt = 0; nt < 4; nt++)
        #pragma unroll
        for (int j = 0; j < 2; j++) {
            float s = 0.f, q = 0.f;
            #pragma unroll
            for (int mt = 0; mt < 4; mt++) {
                float v0 = acc[mt][nt][j], v1 = acc[mt][nt][2 + j];
                s += v0 + v1; q += v0 * v0 + v1 * v1;
            }
            cs[nt * 2 + j] = s; cq[nt * 2 + j] = q;
        }
    #pragma unroll
    for (int k = 0; k < 8; k++) {
        #pragma unroll
        for (int o = 4; o <= 16; o <<= 1) {
            cs[k] += __shfl_xor_sync(0xffffffffu, cs[k], o);
            cq[k] += __shfl_xor_sync(0xffffffffu, cq[k], o);
        }
    }
    if (lane < 4) {
        #pragma unroll
        for (int nt = 0; nt < 4; nt++)
            #pragma unroll
            for (int j = 0; j < 2; j++) {
                int col = warp_n * 32 + nt * 8 + lane * 2 + j;
                red_s[wid][col] = cs[nt * 2 + j];
                red_q[wid][col] = cq[nt * 2 + j];
            }
    }
    __syncthreads();
    if (tid < 128) {
        int wn = tid >> 5;
        float s = red_s[wn][tid] + red_s[4 + wn][tid];
        float q = red_q[wn][tid] + red_q[4 + wn][tid];
        part[(size_t)blockIdx.x * 256 + tid] = s;
        part[(size_t)blockIdx.x * 256 + 128 + tid] = q;
    }
}

// ---------------- convs 2-4 (3x3) via mma.sync bf16x3, fused BN stats ----------------
constexpr int CATILE = 128 * ROWB;
constexpr int CBTILE = 64 * ROWB;
constexpr int CBUF = 2 * CATILE + 2 * CBTILE;
constexpr int CONV_SMEM = 2 * CBUF;

template<int CHUNKS, int CIN_CH, int CST>
__global__ void __launch_bounds__(256, 2) conv_mma_kernel(
    const __nv_bfloat16* __restrict__ inh, const __nv_bfloat16* __restrict__ inl,
    const __nv_bfloat16* __restrict__ wh, const __nv_bfloat16* __restrict__ wl,
    float* __restrict__ Out, int COUT, float* __restrict__ part)
{
    extern __shared__ char smem[];
    __shared__ float red_s[8][64], red_q[8][64];
    const int tid = threadIdx.x;
    const int wid = tid >> 5, lane = tid & 31;
    const int warp_m = wid >> 1, warp_n = wid & 1;
    const uint32_t sb = smem_u32(smem);
    const int bm = blockIdx.x * 128;

    const int lrow = tid >> 1, lhalf = tid & 1;
    const int pm = bm + lrow;
    const int py = pm / 200, px = pm % 200;
    const bool prow_ok = pm < NQ;
    const uint32_t s_arow = sb + (uint32_t)lrow * ROWB + (uint32_t)lhalf * 64;
    const int brow = tid >> 2, bq = tid & 3;
    const uint32_t s_brow = sb + 2 * CATILE + (uint32_t)brow * ROWB + (uint32_t)bq * 32;

    const uint32_t a_base = sb + (uint32_t)(warp_m * 32 + (lane & 15)) * ROWB + (uint32_t)(lane >> 4) * 16;
    const uint32_t b_base = sb + 2 * CATILE + (uint32_t)(warp_n * 32 + (lane & 7)) * ROWB
                          + (uint32_t)((lane >> 3) & 1) * 16;

    float acc[2][4][4];
    #pragma unroll
    for (int mt = 0; mt < 2; mt++)
        #pragma unroll
        for (int nt = 0; nt < 4; nt++)
            #pragma unroll
            for (int d = 0; d < 4; d++) acc[mt][nt][d] = 0.f;

    auto load_chunk = [&](int c, int buf) {
        const int e = c / CIN_CH, cih = c % CIN_CH;
        const int qy = py + e / 3 - 1;
        const int qx = px + e % 3 - 1;
        const bool val = prow_ok && qy >= 0 && qy < 200 && qx >= 0 && qx < 200;
        const size_t aoff = (size_t)(val ? (qy * 200 + qx) : 0) * CST + (size_t)cih * 64 + (size_t)lhalf * 32;
        const char* agh = (const char*)(inh + aoff);
        const char* agl = (const char*)(inl + aoff);
        const size_t boff = ((size_t)c * 64 + brow) * 64 + (size_t)bq * 16;
        const char* bgh = (const char*)(wh + boff);
        const char* bgl = (const char*)(wl + boff);
        const uint32_t sa = s_arow + (uint32_t)buf * CBUF;
        const uint32_t sbr = s_brow + (uint32_t)buf * CBUF;
        #pragma unroll
        for (int i = 0; i < 4; i++) {
            cpasync16(sa + i * 16,           agh + i * 16, val);
            cpasync16(sa + CATILE + i * 16,  agl + i * 16, val);
        }
        #pragma unroll
        for (int i = 0; i < 2; i++) {
            cpasync16(sbr + i * 16,          bgh + i * 16, true);
            cpasync16(sbr + CBTILE + i * 16, bgl + i * 16, true);
        }
    };

    load_chunk(0, 0); cp_commit();
    load_chunk(1, 1); cp_commit();

    for (int c = 0; c < CHUNKS; c++) {
        const int buf = c & 1;
        cp_wait1();
        __syncthreads();

        const uint32_t ab = a_base + (uint32_t)buf * CBUF;
        const uint32_t bb = b_base + (uint32_t)buf * CBUF;
        #pragma unroll
        for (int ks = 0; ks < 4; ks++) {
            const uint32_t kbyte = (uint32_t)ks * 32;
            uint32_t bh[4][2], bl[4][2];
            #pragma unroll
            for (int nt = 0; nt < 4; nt++) {
                ldmx2(bh[nt], bb + (uint32_t)nt * 8 * ROWB + kbyte);
                ldmx2(bl[nt], bb + CBTILE + (uint32_t)nt * 8 * ROWB + kbyte);
            }
            #pragma unroll
            for (int mt = 0; mt < 2; mt++) {
                uint32_t ah[4], al[4];
                ldmx4(ah, ab + (uint32_t)mt * 16 * ROWB + kbyte);
                ldmx4(al, ab + CATILE + (uint32_t)mt * 16 * ROWB + kbyte);
                #pragma unroll
                for (int nt = 0; nt < 4; nt++) {
                    mma_bf16(acc[mt][nt], ah, bh[nt]);
                    mma_bf16(acc[mt][nt], ah, bl[nt]);
                    mma_bf16(acc[mt][nt], al, bh[nt]);
                }
            }
        }
        __syncthreads();
        if (c + 2 < CHUNKS) load_chunk(c + 2, buf);
        cp_commit();
    }

    const int g = lane >> 2, tg = lane & 3;
    #pragma unroll
    for (int mt = 0; mt < 2; mt++) {
        const int r0 = bm + warp_m * 32 + mt * 16 + g;
        #pragma unroll
        for (int nt = 0; nt < 4; nt++) {
            const int col = warp_n * 32 + nt * 8 + tg * 2;
            if (col >= COUT) continue;
            if (r0 < NQ)
                *(float2*)&Out[(size_t)r0 * COUT + col] = make_float2(acc[mt][nt][0], acc[mt][nt][1]);
            if (r0 + 8 < NQ)
                *(float2*)&Out[(size_t)(r0 + 8) * COUT + col] = make_float2(acc[mt][nt][2], acc[mt][nt][3]);
        }
    }

    // fused BN stats
    float cs[8], cq[8];
    #pragma unroll
    for (int nt = 0; nt < 4; nt++)
        #pragma unroll
        for (int j = 0; j < 2; j++) {
            float s = 0.f, q = 0.f;
            #pragma unroll
            for (int mt = 0; mt < 2; mt++) {
                float v0 = acc[mt][nt][j], v1 = acc[mt][nt][2 + j];
                s += v0 + v1; q += v0 * v0 + v1 * v1;
            }
            cs[nt * 2 + j] = s; cq[nt * 2 + j] = q;
        }
    #pragma unroll
    for (int k = 0; k < 8; k++) {
        #pragma unroll
        for (int o = 4; o <= 16; o <<= 1) {
            cs[k] += __shfl_xor_sync(0xffffffffu, cs[k], o);
            cq[k] += __shfl_xor_sync(0xffffffffu, cq[k], o);
        }
    }
    if (lane < 4) {
        #pragma unroll
        for (int nt = 0; nt < 4; nt++)
            #pragma unroll
            for (int j = 0; j < 2; j++) {
                int col = warp_n * 32 + nt * 8 + lane * 2 + j;
                red_s[wid][col] = cs[nt * 2 + j];
                red_q[wid][col] = cq[nt * 2 + j];
            }
    }
    __syncthreads();
    if (tid < COUT) {
        int wn = tid >> 5;
        float s = 0.f, q = 0.f;
        #pragma unroll
        for (int wm = 0; wm < 4; wm++) {
            s += red_s[wm * 2 + wn][tid];
            q += red_q[wm * 2 + wn][tid];
        }
        part[(size_t)blockIdx.x * 2 * COUT + tid] = s;
        part[(size_t)blockIdx.x * 2 * COUT + COUT + tid] = q;
    }
}

// ---------------- batchnorm finalize (sums NBLK per-block partials) ----------------
__global__ void bn_finalize_kernel(const float* __restrict__ part,
                                   const float* __restrict__ gamma, const float* __restrict__ beta,
                                   float* __restrict__ scale, float* __restrict__ shift, int C)
{
    int c = threadIdx.x;
    float s = 0.f, q = 0.f;
    for (int g = 0; g < NBLK; g++) {
        s += part[(size_t)g * 2 * C + c];
        q += part[(size_t)g * 2 * C + C + c];
    }
    const float invP = 1.f / (float)NQ;
    float m = s * invP;
    float v = q * invP - m * m;
    float sc = gamma[c] * rsqrtf(v + 1e-5f);
    scale[c] = sc;
    shift[c] = beta[c] - m * sc;
}

// BN+ReLU -> bf16 split, 4-wide vectorized
__global__ void bn_apply_split_kernel(const float* __restrict__ X, const float* __restrict__ scale,
                                      const float* __restrict__ shift,
                                      __nv_bfloat16* __restrict__ hi, __nv_bfloat16* __restrict__ lo,
                                      int C, int CST, int total4)
{
    int i = blockIdx.x * blockDim.x + threadIdx.x;
    if (i >= total4) return;
    int idx = i * 4;
    int c = idx % CST;
    int p = idx / CST;
    float v[4] = {0.f, 0.f, 0.f, 0.f};
    if (c < C) {
        float4 x4 = *(const float4*)&X[(size_t)p * C + c];
        float4 sc = *(const float4*)&scale[c];
        float4 sh = *(const float4*)&shift[c];
        v[0] = fmaxf(0.f, fmaf(x4.x, sc.x, sh.x));
        v[1] = fmaxf(0.f, fmaf(x4.y, sc.y, sh.y));
        v[2] = fmaxf(0.f, fmaf(x4.z, sc.z, sh.z));
        v[3] = fmaxf(0.f, fmaf(x4.w, sc.w, sh.w));
    }
    __nv_bfloat16 h[4], l[4];
    #pragma unroll
    for (int k = 0; k < 4; k++) split2(v[k], h[k], l[k]);
    __nv_bfloat162 h01(h[0], h[1]), h23(h[2], h[3]);
    __nv_bfloat162 l01(l[0], l[1]), l23(l[2], l[3]);
    *(uint2*)&hi[idx] = make_uint2(*(uint32_t*)&h01, *(uint32_t*)&h23);
    *(uint2*)&lo[idx] = make_uint2(*(uint32_t*)&l01, *(uint32_t*)&l23);
}

// ---------------- head: fused BN4+ReLU + 1x1 conv 48 -> 21, output NCHW ----------------
__global__ void head_conv_kernel(const float* __restrict__ H4raw, const float* __restrict__ scale,
                                 const float* __restrict__ shift,
                                 const float* __restrict__ Wo, const float* __restrict__ bo,
                                 float* __restrict__ out)
{
    int p = blockIdx.x * blockDim.x + threadIdx.x;
    if (p >= NQ) return;
    float x[48];
    const float4* hp = (const float4*)(H4raw + (size_t)p * 48);
    #pragma unroll
    for (int i = 0; i < 12; i++) {
        float4 v = hp[i];
        x[i * 4 + 0] = v.x; x[i * 4 + 1] = v.y; x[i * 4 + 2] = v.z; x[i * 4 + 3] = v.w;
    }
    #pragma unroll
    for (int ci = 0; ci < 48; ci++)
        x[ci] = fmaxf(0.f, fmaf(x[ci], scale[ci], shift[ci]));
    for (int co = 0; co < 21; co++) {
        float s = bo[co];
        const float* w = Wo + co * 48;
        #pragma unroll
        for (int ci = 0; ci < 48; ci++) s = fmaf(x[ci], w[ci], s);
        out[(size_t)co * NQ + p] = s;
    }
}

// ---------------- launch ----------------
extern "C" void kernel_launch(void* const* d_in, const int* in_sizes, int n_in,
                              void* d_out, int out_size)
{
    const float* value = (const float*)d_in[0];
    const float* bq    = (const float*)d_in[1];
    const float* bpos  = (const float*)d_in[2];
    const int*   proj  = (const int*)d_in[3];
    const float* Wv    = (const float*)d_in[4];
    const float* bv    = (const float*)d_in[5];
    const float* Woff  = (const float*)d_in[6];
    const float* boff  = (const float*)d_in[7];
    const float* Wattn = (const float*)d_in[8];
    const float* battn = (const float*)d_in[9];
    const float* Wout  = (const float*)d_in[10];
    const float* bout  = (const float*)d_in[11];
    const float* Wf1   = (const float*)d_in[12];
    const float* bf1   = (const float*)d_in[13];
    const float* Wf2   = (const float*)d_in[14];
    const float* bf2   = (const float*)d_in[15];
    const float* lng   = (const float*)d_in[16];
    const float* lnb   = (const float*)d_in[17];
    const float* cw1   = (const float*)d_in[18];
    const float* g1    = (const float*)d_in[19];
    const float* b1    = (const float*)d_in[20];
    const float* cw2   = (const float*)d_in[21];
    const float* g2    = (const float*)d_in[22];
    const float* b2    = (const float*)d_in[23];
    const float* cw3   = (const float*)d_in[24];
    const float* g3    = (const float*)d_in[25];
    const float* b3    = (const float*)d_in[26];
    const float* cw4   = (const float*)d_in[27];
    const float* g4    = (const float*)d_in[28];
    const float* b4    = (const float*)d_in[29];
    const float* objw  = (const float*)d_in[30];
    const float* objb  = (const float*)d_in[31];
    float* out = (float*)d_out;

    float* S = nullptr;
    cudaGetSymbolAddress((void**)&S, g_scratch);
    int* pmax = nullptr;
    cudaGetSymbolAddress((void**)&pmax, g_pmax);
    __nv_bfloat16 *s1h, *s1l, *s2h, *s2l, *wch, *wcl;
    __half *vx, *vin16, *q16, *qp16, *w16, *wf16, *wv16, *oa16;
    cudaGetSymbolAddress((void**)&s1h, g_s1h);
    cudaGetSymbolAddress((void**)&s1l, g_s1l);
    cudaGetSymbolAddress((void**)&s2h, g_s2h);
    cudaGetSymbolAddress((void**)&s2l, g_s2l);
    cudaGetSymbolAddress((void**)&vx,  g_vx);
    cudaGetSymbolAddress((void**)&vin16, g_vin16);
    cudaGetSymbolAddress((void**)&q16, g_q16);
    cudaGetSymbolAddress((void**)&qp16, g_qp16);
    cudaGetSymbolAddress((void**)&w16, g_w16);
    cudaGetSymbolAddress((void**)&wf16, g_wf16);
    cudaGetSymbolAddress((void**)&wv16, g_wv16);
    cudaGetSymbolAddress((void**)&oa16, g_oa16);
    cudaGetSymbolAddress((void**)&wch, g_wch);
    cudaGetSymbolAddress((void**)&wcl, g_wcl);

    float* PQ    = S + OFF_Q;
    float* PT1   = S + OFF_T1;
    float* PT2   = S + OFF_T2;
    float* PH1   = S + OFF_H1;
    float* PH2   = S + OFF_H2;
    float* PH3   = S + OFF_H3;
    float* PH4   = S + OFF_H4;
    float* PPART = S + OFF_PART;
    float* PSCALE= S + OFF_SCALE;
    float* PSHIFT= S + OFF_SHIFT;
    float* PBIAS = S + OFF_BIAS;

    cudaFuncSetAttribute(conv1_f16_kernel, cudaFuncAttributeMaxDynamicSharedMemorySize, CONV1_SMEM);
    cudaFuncSetAttribute(gemm_f16<8>,    cudaFuncAttributeMaxDynamicSharedMemorySize, F16GEMM_SMEM);
    cudaFuncSetAttribute(gemm_f16<9>,    cudaFuncAttributeMaxDynamicSharedMemorySize, F16GEMM_SMEM);
    cudaFuncSetAttribute(gemm_f16<6>,    cudaFuncAttributeMaxDynamicSharedMemorySize, F16GEMM_SMEM);
    cudaFuncSetAttribute((conv_mma_kernel<18, 2, 128>), cudaFuncAttributeMaxDynamicSharedMemorySize, CONV_SMEM);
    cudaFuncSetAttribute((conv_mma_kernel<9, 1, 64>),   cudaFuncAttributeMaxDynamicSharedMemorySize, CONV_SMEM);

    // --- observed_masks (2-launch deterministic) ---
    reduce_max_part_kernel<<<NMAXB, 256>>>(proj, pmax);
    write_mask_kernel<<<(NQ + 255) / 256, 256>>>(proj, pmax, out + 21 * NQ);

    // --- fused weight prep + value fp16 (single launch) ---
    prep_kernel<<<(Q10 + 255) / 256, 256>>>(cw1, cw2, cw3, cw4, Woff, Wattn, Wv, Wf1, Wf2, Wout,
                                            boff, battn, value,
                                            w16, wch, wcl, wf16, wv16, PBIAS, vin16);

    // --- both layers' V projections in one N=256 GEMM (bv is contiguous [2][128]) ---
    gemm_f16<8><<<dim3(340, 2), 256, F16GEMM_SMEM>>>(vin16, wv16, bv, nullptr, nullptr, vx, NV, 256);

    // --- 2 encoder layers (PQ starts as bq; no memcpy needed) ---
    add_f16_kernel<<<(NQ * ED / 4 + 255) / 256, 256>>>(bq, bpos, qp16, NQ * ED / 4);
    for (int i = 0; i < 2; i++) {
        size_t LW = (size_t)i * WFL;
        gemm_f16<8><<<dim3(313, 6), 256, F16GEMM_SMEM>>>(qp16, wf16 + LW,
                                                         PBIAS + i * 768, nullptr, nullptr, oa16, NQ, 768);
        deform_kernel<<<(NQ * HEADS + 255) / 256, 256>>>(vx + (size_t)i * 128, oa16, q16);
        gemm_f16<6><<<dim3(313, 1), 256, F16GEMM_SMEM>>>(q16, wf16 + LW + 1152 * 128,
                                                         bout + i * 128, (i == 0) ? bq : PQ, PT1, nullptr, NQ, 128);
        ln_kernel<3><<<(NQ + 7) / 8, 256>>>(PT1, lng + (i * 2 + 0) * 128, lnb + (i * 2 + 0) * 128, PQ, q16, nullptr);
        gemm_f16<9><<<dim3(313, 1), 256, F16GEMM_SMEM>>>(q16, wf16 + LW + 896 * 128,
                                                         bf1 + i * 128, nullptr, nullptr, qp16, NQ, 128);
        gemm_f16<6><<<dim3(313, 1), 256, F16GEMM_SMEM>>>(qp16, wf16 + LW + 1024 * 128,
                                                         bf2 + i * 128, PQ, PT2, nullptr, NQ, 128);
        if (i == 0)
            ln_kernel<4><<<(NQ + 7) / 8, 256>>>(PT2, lng + 1 * 128, lnb + 1 * 128, PQ, qp16, bpos);   // fp16(q+pos)
        else
            ln_kernel<5><<<(NQ + 7) / 8, 256>>>(PT2, lng + 3 * 128, lnb + 3 * 128, nullptr, q16, nullptr); // fp16 only
    }

    // --- conv head (BN stats fused into conv epilogues) ---
    conv1_f16_kernel<<<NBLK, 256, CONV1_SMEM>>>(q16, w16, PH1, PPART);
    bn_finalize_kernel<<<1, 128>>>(PPART, g1, b1, PSCALE, PSHIFT, 128);
    bn_apply_split_kernel<<<(NQ * 128 / 4 + 255) / 256, 256>>>(PH1, PSCALE, PSHIFT, s1h, s1l, 128, 128, NQ * 128 / 4);

    conv_mma_kernel<18, 2, 128><<<NBLK, 256, CONV_SMEM>>>(s1h, s1l, wch + WC2_OFF, wcl + WC2_OFF, PH2, 64, PPART);
    bn_finalize_kernel<<<1, 64>>>(PPART, g2, b2, PSCALE, PSHIFT, 64);
    bn_apply_split_kernel<<<(NQ * 64 / 4 + 255) / 256, 256>>>(PH2, PSCALE, PSHIFT, s2h, s2l, 64, 64, NQ * 64 / 4);

    conv_mma_kernel<9, 1, 64><<<NBLK, 256, CONV_SMEM>>>(s2h, s2l, wch + WC3_OFF, wcl + WC3_OFF, PH3, 48, PPART);
    bn_finalize_kernel<<<1, 48>>>(PPART, g3, b3, PSCALE, PSHIFT, 48);
    bn_apply_split_kernel<<<(NQ * 64 / 4 + 255) / 256, 256>>>(PH3, PSCALE, PSHIFT, s1h, s1l, 48, 64, NQ * 64 / 4);

    conv_mma_kernel<9, 1, 64><<<NBLK, 256, CONV_SMEM>>>(s1h, s1l, wch + WC4_OFF, wcl + WC4_OFF, PH4, 48, PPART);
    bn_finalize_kernel<<<1, 48>>>(PPART, g4, b4, PSCALE, PSHIFT, 48);
    head_conv_kernel<<<(NQ + 255) / 256, 256>>>(PH4, PSCALE, PSHIFT, objw, objb, out);
}